// round 9
// baseline (speedup 1.0000x reference)
#include <cuda_runtime.h>
#include <cuda_bf16.h>
#include <cstdint>

#define KL 4096
#define KB 4
#define KD 512
#define KV 1000
#define KVP 1024   // padded vocab

// ---------------------------------------------------------------------------
// PTX helpers (sm_80-compatible only: ldmatrix / mma.sync / cp.async)
// ---------------------------------------------------------------------------
__device__ __forceinline__ uint32_t smem_to_u32(const void* p) {
    uint32_t a;
    asm("{ .reg .u64 t; cvta.to.shared.u64 t, %1; cvt.u32.u64 %0, t; }" : "=r"(a) : "l"(p));
    return a;
}
__device__ __forceinline__ void cpasync16(uint32_t s, const void* g) {
    asm volatile("cp.async.cg.shared.global [%0], [%1], 16;" :: "r"(s), "l"(g));
}
__device__ __forceinline__ void cp_commit() {
    asm volatile("cp.async.commit_group;" ::: "memory");
}
template <int N>
__device__ __forceinline__ void cp_wait() {
    asm volatile("cp.async.wait_group %0;" :: "n"(N) : "memory");
}
__device__ __forceinline__ void ldmx4(uint32_t* r, uint32_t a) {
    asm volatile("ldmatrix.sync.aligned.m8n8.x4.shared.b16 {%0,%1,%2,%3}, [%4];"
                 : "=r"(r[0]), "=r"(r[1]), "=r"(r[2]), "=r"(r[3]) : "r"(a));
}
__device__ __forceinline__ void mma16816(float* d, const uint32_t* a, const uint32_t* b) {
    asm volatile(
        "mma.sync.aligned.m16n8k16.row.col.f32.bf16.bf16.f32 "
        "{%0,%1,%2,%3}, {%4,%5,%6,%7}, {%8,%9}, {%0,%1,%2,%3};"
        : "+f"(d[0]), "+f"(d[1]), "+f"(d[2]), "+f"(d[3])
        : "r"(a[0]), "r"(a[1]), "r"(a[2]), "r"(a[3]), "r"(b[0]), "r"(b[1]));
}
#define SMEM_SWIZZLE_128B(o) ((o) ^ (((o) >> 3) & 0x70))

// symmetric-G tile pair tables (upper triangle of 4x4)
__constant__ int c_pi[10] = {0, 0, 0, 0, 1, 1, 1, 2, 2, 3};
__constant__ int c_pj[10] = {0, 1, 2, 3, 1, 2, 3, 2, 3, 3};
__constant__ int c_PT[16] = {0, 1, 2, 3,  0, 4, 5, 6,  0, 0, 7, 8,  0, 0, 0, 9};

// ---------------------------------------------------------------------------
// scratch (static device globals; no allocations)
// ---------------------------------------------------------------------------
#define G_NSPLIT 3   // 10 pairs * KB * 3 = 120 CTAs -> single wave on 148 SMs
#define M_NSPLIT 2
__device__ __align__(128) float g_part2[KB * KD * 64];   // colsum partials
__device__ __align__(128) float g_s[KB * KD];
__device__ __align__(128) __nv_bfloat16 g_Xb_hi[(size_t)KB * KL * KD], g_Xb_lo[(size_t)KB * KL * KD];
__device__ __align__(128) __nv_bfloat16 g_Xt_hi[(size_t)KB * KD * KL], g_Xt_lo[(size_t)KB * KD * KL];
__device__ __align__(128) __nv_bfloat16 g_Ww_hi[KD * KD], g_Ww_lo[KD * KD];
__device__ __align__(128) __nv_bfloat16 g_Lw_hi[KVP * KD], g_Lw_lo[KVP * KD];
__device__ __align__(128) float g_Lbp[KVP];
__device__ __align__(128) float g_Gp[(size_t)KB * G_NSPLIT * 10 * 128 * 128]; // 7.9 MB
__device__ __align__(128) float g_Mp[(size_t)M_NSPLIT * KB * KD * KD];        // 8 MB
__device__ __align__(128) __nv_bfloat16 g_G_hi[KB * KD * KD], g_G_lo[KB * KD * KD];
__device__ __align__(128) __nv_bfloat16 g_M_hi[KB * KD * KD], g_M_lo[KB * KD * KD];
__device__ __align__(128) __nv_bfloat16 g_P_hi[(size_t)KB * KVP * KD], g_P_lo[(size_t)KB * KVP * KD];
__device__ __align__(128) float g_logits[(size_t)KB * KL * KVP];

__device__ __forceinline__ void split_f32(float v, __nv_bfloat16& h, __nv_bfloat16& l) {
    h = __float2bfloat16(v);
    l = __float2bfloat16(v - __bfloat162float(h));
}

// ---------------------------------------------------------------------------
// prep_x: x (L,B,D) fp32 -> Xb[b][l][d] hi/lo, Xt[b][d][l] hi/lo, colsum partials
// ---------------------------------------------------------------------------
__global__ __launch_bounds__(256) void prep_x_k(const float* __restrict__ x) {
    __shared__ __nv_bfloat16 shi[64][65], slo[64][65];
    __shared__ float ssum[4][64];
    int b = blockIdx.z;
    int lblk = blockIdx.x;
    int l0 = lblk * 64, d0 = blockIdx.y * 64;
    int t = threadIdx.x;
    int c = t & 63, r4 = t >> 6;
    float ps = 0.f;
#pragma unroll 4
    for (int rr = 0; rr < 16; rr++) {
        int r = r4 * 16 + rr;
        float v = x[(size_t)(l0 + r) * (KB * KD) + b * KD + d0 + c];
        ps += v;
        __nv_bfloat16 h, l;
        split_f32(v, h, l);
        size_t o = ((size_t)b * KL + (l0 + r)) * KD + d0 + c;
        g_Xb_hi[o] = h; g_Xb_lo[o] = l;
        shi[r][c] = h; slo[r][c] = l;
    }
    ssum[r4][c] = ps;
    __syncthreads();
#pragma unroll 4
    for (int rr = 0; rr < 16; rr++) {
        int r = r4 * 16 + rr;   // d index
        size_t o = ((size_t)b * KD + (d0 + r)) * KL + l0 + c;
        g_Xt_hi[o] = shi[c][r];
        g_Xt_lo[o] = slo[c][r];
    }
    if (t < 64) {
        float s = ssum[0][t] + ssum[1][t] + ssum[2][t] + ssum[3][t];
        g_part2[((size_t)b * KD + d0 + t) * 64 + lblk] = s;
    }
}

__global__ void colsum_final_k() {
    int idx = blockIdx.x * 256 + threadIdx.x;  // KB*KD
    float s = 0.f;
    const float* p = &g_part2[(size_t)idx * 64];
#pragma unroll
    for (int k = 0; k < 64; k++) s += p[k];
    g_s[idx] = s;
}

// ---------------------------------------------------------------------------
// prep_w (flat): split Ww; split Lw padded to 1024 rows; pad Lb
// ---------------------------------------------------------------------------
__global__ void prep_w_k(const float* __restrict__ Ww, const float* __restrict__ Lw,
                         const float* __restrict__ Lb) {
    int idx = blockIdx.x * 256 + threadIdx.x;   // over KVP*KD
    int row = idx / KD;
    float v2 = (row < KV) ? Lw[idx] : 0.f;
    __nv_bfloat16 h2, l2;
    split_f32(v2, h2, l2);
    g_Lw_hi[idx] = h2; g_Lw_lo[idx] = l2;
    if (idx < KD * KD) {
        __nv_bfloat16 h, l;
        split_f32(Ww[idx], h, l);
        g_Ww_hi[idx] = h; g_Ww_lo[idx] = l;
    }
    if (idx < KVP) g_Lbp[idx] = (idx < KV) ? Lb[idx] : 0.f;
}

// ---------------------------------------------------------------------------
// mma.sync bf16 split GEMM: C[m][n] = sum_k A[m][k]*B[n][k], hi/lo 3-product
//   K handled in 64-wide chunks. NCtot chunks split over nsplit slots.
//   mode 0: write Chi/Clo bf16 (batch b)
//   mode 2: write Cf fp32 + bias[col] (batch b)
//   mode 3: write Cf fp32 K-split partial (slot blockIdx.z)
//   mode 4: symmetric pairs — i0/j0 from c_pi/c_pj[blockIdx.x]; local tile out
// CTA tile 128x128, K-chunk 64, 3-stage cp.async, one barrier per chunk.
// Next-chunk cp.async interleaved per-kk; MMA products pass-outermost.
// Fragment smem addressing: inline swizzle of the FULL offset (the hoisted
// variant mis-composed XOR with carry and walked out of smem — R8 crash).
// ---------------------------------------------------------------------------
#define TILE_BYTES 16384               // 128 rows x 128B (64 bf16)
#define STAGE_BYTES (4 * TILE_BYTES)   // Ah, Al, Bh, Bl
#define NSTAGE 3
#define DYN_SMEM (NSTAGE * STAGE_BYTES)  // 192 KB

__global__ __launch_bounds__(256, 1) void mma_gemm_k(
    const __nv_bfloat16* __restrict__ Ahi, const __nv_bfloat16* __restrict__ Alo, size_t sA,
    const __nv_bfloat16* __restrict__ Bhi, const __nv_bfloat16* __restrict__ Blo, size_t sB,
    int ldk, int NCtot, int nsplit,
    __nv_bfloat16* __restrict__ Chi, __nv_bfloat16* __restrict__ Clo,
    float* __restrict__ Cf, size_t sC, int ldc,
    const float* __restrict__ bias, int mode) {
    extern __shared__ __align__(1024) char smem[];
    uint32_t smb = smem_to_u32(smem);
    int tid = threadIdx.x;
    int wid = tid >> 5, lane = tid & 31;
    int b = blockIdx.z / nsplit, sp = blockIdx.z % nsplit;
    int basec = NCtot / nsplit, remc = NCtot % nsplit;
    int NC = basec + (sp < remc ? 1 : 0);
    int startc = sp * basec + (sp < remc ? sp : remc);
    int koff0 = startc << 6;
    int i0, j0;
    if (mode == 4) {
        i0 = c_pi[blockIdx.x] * 128;
        j0 = c_pj[blockIdx.x] * 128;
    } else {
        i0 = blockIdx.x * 128;
        j0 = blockIdx.y * 128;
    }
    int wm = (wid >> 2) * 64, wn = (wid & 3) * 32;

    const __nv_bfloat16* tiles[4] = {Ahi + sA * b, Alo + sA * b, Bhi + sB * b, Blo + sB * b};
    const int row0[4] = {i0, i0, j0, j0};

    // ---- loader constants (per thread): 4 iters covering one tile ----
    uint32_t sw_st[4];
    int goe[4];
    int lrr[4];
#pragma unroll
    for (int it = 0; it < 4; it++) {
        int q = tid + it * 256;
        int lr = q >> 3, lu = q & 7;
        uint32_t boff = (uint32_t)(lr * 128 + lu * 16);
        sw_st[it] = SMEM_SWIZZLE_128B(boff);   // full-offset swizzle: safe
        goe[it] = lu * 8;
        lrr[it] = lr;
    }

    float acc[4][4][4];
#pragma unroll
    for (int a = 0; a < 4; a++)
#pragma unroll
        for (int bb = 0; bb < 4; bb++)
#pragma unroll
            for (int c = 0; c < 4; c++) acc[a][bb][c] = 0.f;

    int arow = wm + (lane & 15);
    int akh16 = ((lane >> 4) & 1) * 16;
    int brow = wn + ((lane >> 4) & 1) * 8 + (lane & 7);
    int bkh16 = ((lane >> 3) & 1) * 16;

    // full-chunk loader (prologue only)
    auto load_chunk = [&](int chunk) {
        uint32_t sbase = smb + (chunk % NSTAGE) * STAGE_BYTES;
        int koff = koff0 + (chunk << 6);
#pragma unroll
        for (int tile = 0; tile < 4; tile++) {
            const __nv_bfloat16* src = tiles[tile] + (size_t)(row0[tile]) * ldk + koff;
#pragma unroll
            for (int it = 0; it < 4; it++)
                cpasync16(sbase + tile * TILE_BYTES + sw_st[it],
                          src + (size_t)lrr[it] * ldk + goe[it]);
        }
        cp_commit();
    };

    load_chunk(0);
    if (NC > 1) load_chunk(1);

    for (int kc = 0; kc < NC; kc++) {
        if (kc < NC - 1) cp_wait<1>();
        else cp_wait<0>();
        __syncthreads();

        uint32_t sAh = smb + (kc % NSTAGE) * STAGE_BYTES;
        bool do_load = (kc + 2 < NC);
        uint32_t dstb = smb + ((kc + 2) % NSTAGE) * STAGE_BYTES;
        int koff_n = koff0 + ((kc + 2) << 6);

#pragma unroll
        for (int kk = 0; kk < 4; kk++) {
            // ---- fragment loads: swizzle the FULL byte offset (correct) ----
            uint32_t ah[4][4], al[4][4], bh[2][4], bl[2][4];
#pragma unroll
            for (int np = 0; np < 2; np++) {
                uint32_t o = (uint32_t)((brow + np * 16) * 128 + kk * 32 + bkh16);
                uint32_t sw = SMEM_SWIZZLE_128B(o);
                ldmx4(bh[np], sAh + 2 * TILE_BYTES + sw);
                ldmx4(bl[np], sAh + 3 * TILE_BYTES + sw);
            }
#pragma unroll
            for (int mt = 0; mt < 4; mt++) {
                uint32_t o = (uint32_t)((arow + mt * 16) * 128 + kk * 32 + akh16);
                uint32_t sw = SMEM_SWIZZLE_128B(o);
                ldmx4(ah[mt], sAh + sw);
                ldmx4(al[mt], sAh + TILE_BYTES + sw);
            }
            // ---- interleave one tile of next-chunk cp.async ----
            if (do_load) {
                const __nv_bfloat16* src = tiles[kk] + (size_t)(row0[kk]) * ldk + koff_n;
#pragma unroll
                for (int it = 0; it < 4; it++)
                    cpasync16(dstb + kk * TILE_BYTES + sw_st[it],
                              src + (size_t)lrr[it] * ldk + goe[it]);
            }
            // ---- MMAs: product-pass outermost (16 independent chains/pass) ----
#pragma unroll
            for (int p = 0; p < 3; p++)
#pragma unroll
                for (int mt = 0; mt < 4; mt++)
#pragma unroll
                    for (int nt = 0; nt < 4; nt++) {
                        const uint32_t* af = (p == 2) ? al[mt] : ah[mt];
                        const uint32_t* bf = (p == 1) ? &bl[nt >> 1][(nt & 1) * 2]
                                                      : &bh[nt >> 1][(nt & 1) * 2];
                        mma16816(acc[mt][nt], af, bf);
                    }
        }
        if (do_load) cp_commit();
    }

    // ---- epilogue ----
    float* loc = (mode == 4)
        ? Cf + ((size_t)blockIdx.z * gridDim.x + blockIdx.x) * (128 * 128)
        : nullptr;
#pragma unroll
    for (int mt = 0; mt < 4; mt++) {
#pragma unroll
        for (int half = 0; half < 2; half++) {
            int lrow = wm + mt * 16 + (lane >> 2) + half * 8;
            int grow = i0 + lrow;
#pragma unroll
            for (int nt = 0; nt < 4; nt++) {
                int lcol = wn + nt * 8 + (lane & 3) * 2;
                int gcol = j0 + lcol;
                float v0 = acc[mt][nt][half * 2 + 0];
                float v1 = acc[mt][nt][half * 2 + 1];
                if (mode == 4) {
                    *(float2*)&loc[lrow * 128 + lcol] = make_float2(v0, v1);
                } else if (mode == 3) {
                    *(float2*)&Cf[sC * blockIdx.z + (size_t)grow * ldc + gcol] = make_float2(v0, v1);
                } else if (mode == 2) {
                    float2 f2 = make_float2(v0 + bias[gcol], v1 + bias[gcol + 1]);
                    *(float2*)&Cf[sC * b + (size_t)grow * ldc + gcol] = f2;
                } else {
                    __nv_bfloat162 h2, l2;
                    split_f32(v0, h2.x, l2.x);
                    split_f32(v1, h2.y, l2.y);
                    *(__nv_bfloat162*)&Chi[sC * b + (size_t)grow * ldc + gcol] = h2;
                    *(__nv_bfloat162*)&Clo[sC * b + (size_t)grow * ldc + gcol] = l2;
                }
            }
        }
    }
}

// ---------------------------------------------------------------------------
// reduce symmetric-G partials (10 tile-pairs x G_NSPLIT) -> full G hi/lo bf16
// ---------------------------------------------------------------------------
__global__ void reduce_G_k() {
    size_t idx = ((size_t)blockIdx.x * 256 + threadIdx.x) * 2;  // KB*KD*KD elems
    const size_t per = (size_t)KD * KD;
    int b = (int)(idx / per);
    size_t rem = idx % per;
    int i = (int)(rem / KD), j = (int)(rem % KD);
    int ti = i >> 7, tj = j >> 7;
    float s0 = 0.f, s1 = 0.f;
    if (ti <= tj) {
        int p = c_PT[ti * 4 + tj];
        size_t off = (size_t)((i & 127) * 128 + (j & 127));
        for (int sp = 0; sp < G_NSPLIT; sp++) {
            const float* base = g_Gp + ((size_t)(b * G_NSPLIT + sp) * 10 + p) * (128 * 128);
            s0 += base[off];
            s1 += base[off + 1];
        }
    } else {
        int p = c_PT[tj * 4 + ti];
        size_t off = (size_t)((j & 127) * 128 + (i & 127));
        for (int sp = 0; sp < G_NSPLIT; sp++) {
            const float* base = g_Gp + ((size_t)(b * G_NSPLIT + sp) * 10 + p) * (128 * 128);
            s0 += base[off];
            s1 += base[off + 128];   // G[i][j+1] = mirrored tile, next row
        }
    }
    __nv_bfloat162 h2, l2;
    split_f32(s0, h2.x, l2.x);
    split_f32(s1, h2.y, l2.y);
    *(__nv_bfloat162*)&g_G_hi[idx] = h2;
    *(__nv_bfloat162*)&g_G_lo[idx] = l2;
}

// ---------------------------------------------------------------------------
// reduce M K-split partials + rank-1 Wb[i]*s[b][j] -> hi/lo bf16
// ---------------------------------------------------------------------------
__global__ void reduce_M_k(const float* __restrict__ Wb) {
    size_t idx = ((size_t)blockIdx.x * 256 + threadIdx.x) * 2;
    const size_t per = (size_t)KD * KD;
    int b = (int)(idx / per);
    size_t rem = idx % per;
    int i = (int)(rem / KD), j = (int)(rem % KD);
    float s0 = 0.f, s1 = 0.f;
    for (int sp = 0; sp < M_NSPLIT; sp++) {
        const float* p = g_Mp + ((size_t)(b * M_NSPLIT + sp)) * per + rem;
        s0 += p[0];
        s1 += p[1];
    }
    float u = Wb[i];
    s0 += u * g_s[b * KD + j];
    s1 += u * g_s[b * KD + j + 1];
    __nv_bfloat162 h2, l2;
    split_f32(s0, h2.x, l2.x);
    split_f32(s1, h2.y, l2.y);
    *(__nv_bfloat162*)&g_M_hi[idx] = h2;
    *(__nv_bfloat162*)&g_M_lo[idx] = l2;
}

// ---------------------------------------------------------------------------
// log_softmax over V + permute (B,L,V)->(L,B,V)
// ---------------------------------------------------------------------------
__global__ void logsoftmax_k(float* __restrict__ out) {
    int l = blockIdx.x, b = blockIdx.y;
    const float* row = g_logits + (size_t)(b * KL + l) * KVP;
    float* orow = out + (size_t)(l * KB + b) * KV;
    __shared__ float sred[8];
    int t = threadIdx.x;
    int wid = t >> 5, lane = t & 31;
    bool act = t < (KV / 4);
    float4 v = act ? *(const float4*)&row[t * 4]
                   : make_float4(-3.4e38f, -3.4e38f, -3.4e38f, -3.4e38f);
    float m = fmaxf(fmaxf(v.x, v.y), fmaxf(v.z, v.w));
#pragma unroll
    for (int s = 16; s >= 1; s >>= 1) m = fmaxf(m, __shfl_xor_sync(0xffffffffu, m, s));
    if (lane == 0) sred[wid] = m;
    __syncthreads();
    float m8 = (lane < 8) ? sred[lane] : -3.4e38f;
#pragma unroll
    for (int s = 4; s >= 1; s >>= 1) m8 = fmaxf(m8, __shfl_xor_sync(0xffffffffu, m8, s));
    float vmax = __shfl_sync(0xffffffffu, m8, 0);

    float e = act ? (__expf(v.x - vmax) + __expf(v.y - vmax) +
                     __expf(v.z - vmax) + __expf(v.w - vmax))
                  : 0.f;
#pragma unroll
    for (int s = 16; s >= 1; s >>= 1) e += __shfl_xor_sync(0xffffffffu, e, s);
    __syncthreads();
    if (lane == 0) sred[wid] = e;
    __syncthreads();
    float e8 = (lane < 8) ? sred[lane] : 0.f;
#pragma unroll
    for (int s = 4; s >= 1; s >>= 1) e8 += __shfl_xor_sync(0xffffffffu, e8, s);
    float denom = vmax + logf(__shfl_sync(0xffffffffu, e8, 0));

    if (act) {
        float4 o;
        o.x = v.x - denom; o.y = v.y - denom;
        o.z = v.z - denom; o.w = v.w - denom;
        *(float4*)&orow[t * 4] = o;
    }
}

// ---------------------------------------------------------------------------
extern "C" void kernel_launch(void* const* d_in, const int* in_sizes, int n_in,
                              void* d_out, int out_size) {
    (void)in_sizes; (void)n_in; (void)out_size;
    const float* x  = (const float*)d_in[0];
    const float* Ww = (const float*)d_in[1];
    const float* Wb = (const float*)d_in[2];
    const float* Lw = (const float*)d_in[3];
    const float* Lb = (const float*)d_in[4];
    float* out = (float*)d_out;

    static bool attr_set = false;
    if (!attr_set) {
        cudaFuncSetAttribute(mma_gemm_k, cudaFuncAttributeMaxDynamicSharedMemorySize, DYN_SMEM);
        attr_set = true;
    }

    __nv_bfloat16 *Xb_hi, *Xb_lo, *Xt_hi, *Xt_lo, *Wwh, *Wwl, *Lwh, *Lwl;
    __nv_bfloat16 *Gh, *Gl, *Mh, *Ml, *Ph, *Pl;
    float *Lbp, *logits, *Gp, *Mp;
    cudaGetSymbolAddress((void**)&Xb_hi, g_Xb_hi);
    cudaGetSymbolAddress((void**)&Xb_lo, g_Xb_lo);
    cudaGetSymbolAddress((void**)&Xt_hi, g_Xt_hi);
    cudaGetSymbolAddress((void**)&Xt_lo, g_Xt_lo);
    cudaGetSymbolAddress((void**)&Wwh, g_Ww_hi);
    cudaGetSymbolAddress((void**)&Wwl, g_Ww_lo);
    cudaGetSymbolAddress((void**)&Lwh, g_Lw_hi);
    cudaGetSymbolAddress((void**)&Lwl, g_Lw_lo);
    cudaGetSymbolAddress((void**)&Gh, g_G_hi);
    cudaGetSymbolAddress((void**)&Gl, g_G_lo);
    cudaGetSymbolAddress((void**)&Mh, g_M_hi);
    cudaGetSymbolAddress((void**)&Ml, g_M_lo);
    cudaGetSymbolAddress((void**)&Ph, g_P_hi);
    cudaGetSymbolAddress((void**)&Pl, g_P_lo);
    cudaGetSymbolAddress((void**)&Lbp, g_Lbp);
    cudaGetSymbolAddress((void**)&logits, g_logits);
    cudaGetSymbolAddress((void**)&Gp, g_Gp);
    cudaGetSymbolAddress((void**)&Mp, g_Mp);

    prep_x_k<<<dim3(KL / 64, KD / 64, KB), 256>>>(x);
    colsum_final_k<<<(KB * KD) / 256, 256>>>();
    prep_w_k<<<(KVP * KD) / 256, 256>>>(Ww, Lw, Lb);

    // G[b] = Xt*Xt^T (symmetric): 10 upper tile-pairs, K-split x3 -> 120 CTAs
    mma_gemm_k<<<dim3(10, 1, KB * G_NSPLIT), 256, DYN_SMEM>>>(
        Xt_hi, Xt_lo, (size_t)KD * KL, Xt_hi, Xt_lo, (size_t)KD * KL,
        KL, KL / 64, G_NSPLIT, nullptr, nullptr, Gp, 0, 128, nullptr, 4);
    reduce_G_k<<<(KB * KD * KD / 2) / 256, 256>>>();

    // M[b] = Ww*G[b]^T (512x512, K=512); K-split x2; rank-1 in reduce
    mma_gemm_k<<<dim3(4, 4, KB * M_NSPLIT), 256, DYN_SMEM>>>(
        Wwh, Wwl, 0, Gh, Gl, (size_t)KD * KD,
        KD, KD / 64, M_NSPLIT, nullptr, nullptr, Mp, (size_t)KD * KD, KD, nullptr, 3);
    reduce_M_k<<<(KB * KD * KD / 2) / 256, 256>>>(Wb);

    // P[b][v][k] = sum_n Lw[v][n] * M[b][k][n]  -> bf16 split
    mma_gemm_k<<<dim3(KVP / 128, KD / 128, KB), 256, DYN_SMEM>>>(
        Lwh, Lwl, 0, Mh, Ml, (size_t)KD * KD,
        KD, KD / 64, 1, Ph, Pl, nullptr, (size_t)KVP * KD, KD, nullptr, 0);

    // logits[b] = Xb * P^T + Lb  (4096x1024, K=512)
    mma_gemm_k<<<dim3(KL / 128, KVP / 128, KB), 256, DYN_SMEM>>>(
        Xb_hi, Xb_lo, (size_t)KL * KD, Ph, Pl, (size_t)KVP * KD,
        KD, KD / 64, 1, nullptr, nullptr, logits, (size_t)KL * KVP, KVP, Lbp, 2);

    logsoftmax_k<<<dim3(KL, KB), 256>>>(out);
}

// round 10
// speedup vs baseline: 1.0103x; 1.0103x over previous
#include <cuda_runtime.h>
#include <cuda_bf16.h>
#include <cstdint>

#define KL 4096
#define KB 4
#define KD 512
#define KV 1000
#define KVP 1024   // padded vocab

// ---------------------------------------------------------------------------
// PTX helpers (sm_80-compatible only: ldmatrix / mma.sync / cp.async)
// ---------------------------------------------------------------------------
__device__ __forceinline__ uint32_t smem_to_u32(const void* p) {
    uint32_t a;
    asm("{ .reg .u64 t; cvta.to.shared.u64 t, %1; cvt.u32.u64 %0, t; }" : "=r"(a) : "l"(p));
    return a;
}
__device__ __forceinline__ void cpasync16(uint32_t s, const void* g) {
    asm volatile("cp.async.cg.shared.global [%0], [%1], 16;" :: "r"(s), "l"(g));
}
__device__ __forceinline__ void cp_commit() {
    asm volatile("cp.async.commit_group;" ::: "memory");
}
template <int N>
__device__ __forceinline__ void cp_wait() {
    asm volatile("cp.async.wait_group %0;" :: "n"(N) : "memory");
}
__device__ __forceinline__ void ldmx4(uint32_t* r, uint32_t a) {
    asm volatile("ldmatrix.sync.aligned.m8n8.x4.shared.b16 {%0,%1,%2,%3}, [%4];"
                 : "=r"(r[0]), "=r"(r[1]), "=r"(r[2]), "=r"(r[3]) : "r"(a));
}
__device__ __forceinline__ void mma16816(float* d, const uint32_t* a, const uint32_t* b) {
    asm volatile(
        "mma.sync.aligned.m16n8k16.row.col.f32.bf16.bf16.f32 "
        "{%0,%1,%2,%3}, {%4,%5,%6,%7}, {%8,%9}, {%0,%1,%2,%3};"
        : "+f"(d[0]), "+f"(d[1]), "+f"(d[2]), "+f"(d[3])
        : "r"(a[0]), "r"(a[1]), "r"(a[2]), "r"(a[3]), "r"(b[0]), "r"(b[1]));
}
#define SMEM_SWIZZLE_128B(o) ((o) ^ (((o) >> 3) & 0x70))

// symmetric-G tile pair tables (upper triangle of 4x4)
__constant__ int c_pi[10] = {0, 0, 0, 0, 1, 1, 1, 2, 2, 3};
__constant__ int c_pj[10] = {0, 1, 2, 3, 1, 2, 3, 2, 3, 3};
__constant__ int c_PT[16] = {0, 1, 2, 3,  0, 4, 5, 6,  0, 0, 7, 8,  0, 0, 0, 9};

// ---------------------------------------------------------------------------
// scratch (static device globals; no allocations)
// ---------------------------------------------------------------------------
#define G_NSPLIT 3   // 10 pairs * KB * 3 = 120 CTAs -> single wave on 148 SMs
#define M_NSPLIT 2
__device__ __align__(128) float g_part2[KB * KD * 64];   // colsum partials
__device__ __align__(128) float g_s[KB * KD];
__device__ __align__(128) __nv_bfloat16 g_Xb_hi[(size_t)KB * KL * KD], g_Xb_lo[(size_t)KB * KL * KD];
__device__ __align__(128) __nv_bfloat16 g_Xt_hi[(size_t)KB * KD * KL], g_Xt_lo[(size_t)KB * KD * KL];
__device__ __align__(128) __nv_bfloat16 g_Ww_hi[KD * KD], g_Ww_lo[KD * KD];
__device__ __align__(128) __nv_bfloat16 g_Lw_hi[KVP * KD], g_Lw_lo[KVP * KD];
__device__ __align__(128) float g_Lbp[KVP];
__device__ __align__(128) float g_Gp[(size_t)KB * G_NSPLIT * 10 * 128 * 128]; // 7.9 MB
__device__ __align__(128) float g_Mp[(size_t)M_NSPLIT * KB * KD * KD];        // 8 MB
__device__ __align__(128) __nv_bfloat16 g_G_hi[KB * KD * KD], g_G_lo[KB * KD * KD];
__device__ __align__(128) __nv_bfloat16 g_M_hi[KB * KD * KD], g_M_lo[KB * KD * KD];
__device__ __align__(128) __nv_bfloat16 g_P_hi[(size_t)KB * KVP * KD], g_P_lo[(size_t)KB * KVP * KD];
__device__ __align__(128) float g_logits[(size_t)KB * KL * KVP];

__device__ __forceinline__ void split_f32(float v, __nv_bfloat16& h, __nv_bfloat16& l) {
    h = __float2bfloat16(v);
    l = __float2bfloat16(v - __bfloat162float(h));
}

// ---------------------------------------------------------------------------
// prep_x: x (L,B,D) fp32 -> Xb[b][l][d] hi/lo, Xt[b][d][l] hi/lo, colsum partials
// ---------------------------------------------------------------------------
__global__ __launch_bounds__(256) void prep_x_k(const float* __restrict__ x) {
    __shared__ __nv_bfloat16 shi[64][65], slo[64][65];
    __shared__ float ssum[4][64];
    int b = blockIdx.z;
    int lblk = blockIdx.x;
    int l0 = lblk * 64, d0 = blockIdx.y * 64;
    int t = threadIdx.x;
    int c = t & 63, r4 = t >> 6;
    float ps = 0.f;
#pragma unroll 4
    for (int rr = 0; rr < 16; rr++) {
        int r = r4 * 16 + rr;
        float v = x[(size_t)(l0 + r) * (KB * KD) + b * KD + d0 + c];
        ps += v;
        __nv_bfloat16 h, l;
        split_f32(v, h, l);
        size_t o = ((size_t)b * KL + (l0 + r)) * KD + d0 + c;
        g_Xb_hi[o] = h; g_Xb_lo[o] = l;
        shi[r][c] = h; slo[r][c] = l;
    }
    ssum[r4][c] = ps;
    __syncthreads();
#pragma unroll 4
    for (int rr = 0; rr < 16; rr++) {
        int r = r4 * 16 + rr;   // d index
        size_t o = ((size_t)b * KD + (d0 + r)) * KL + l0 + c;
        g_Xt_hi[o] = shi[c][r];
        g_Xt_lo[o] = slo[c][r];
    }
    if (t < 64) {
        float s = ssum[0][t] + ssum[1][t] + ssum[2][t] + ssum[3][t];
        g_part2[((size_t)b * KD + d0 + t) * 64 + lblk] = s;
    }
}

__global__ void colsum_final_k() {
    int idx = blockIdx.x * 256 + threadIdx.x;  // KB*KD
    float s = 0.f;
    const float* p = &g_part2[(size_t)idx * 64];
#pragma unroll
    for (int k = 0; k < 64; k++) s += p[k];
    g_s[idx] = s;
}

// ---------------------------------------------------------------------------
// prep_w (flat): split Ww; split Lw padded to 1024 rows; pad Lb
// ---------------------------------------------------------------------------
__global__ void prep_w_k(const float* __restrict__ Ww, const float* __restrict__ Lw,
                         const float* __restrict__ Lb) {
    int idx = blockIdx.x * 256 + threadIdx.x;   // over KVP*KD
    int row = idx / KD;
    float v2 = (row < KV) ? Lw[idx] : 0.f;
    __nv_bfloat16 h2, l2;
    split_f32(v2, h2, l2);
    g_Lw_hi[idx] = h2; g_Lw_lo[idx] = l2;
    if (idx < KD * KD) {
        __nv_bfloat16 h, l;
        split_f32(Ww[idx], h, l);
        g_Ww_hi[idx] = h; g_Ww_lo[idx] = l;
    }
    if (idx < KVP) g_Lbp[idx] = (idx < KV) ? Lb[idx] : 0.f;
}

// ---------------------------------------------------------------------------
// mma.sync bf16 split GEMM (R7-proven): C[m][n] = sum_k A[m][k]*B[n][k]
//   modes 0/2/3/4 as before. CTA tile 128x128, K-chunk 64, 3-stage cp.async.
// ---------------------------------------------------------------------------
#define TILE_BYTES 16384               // 128 rows x 128B (64 bf16)
#define STAGE_BYTES (4 * TILE_BYTES)   // Ah, Al, Bh, Bl
#define NSTAGE 3
#define DYN_SMEM (NSTAGE * STAGE_BYTES)  // 192 KB

__global__ __launch_bounds__(256, 1) void mma_gemm_k(
    const __nv_bfloat16* __restrict__ Ahi, const __nv_bfloat16* __restrict__ Alo, size_t sA,
    const __nv_bfloat16* __restrict__ Bhi, const __nv_bfloat16* __restrict__ Blo, size_t sB,
    int ldk, int NCtot, int nsplit,
    __nv_bfloat16* __restrict__ Chi, __nv_bfloat16* __restrict__ Clo,
    float* __restrict__ Cf, size_t sC, int ldc,
    const float* __restrict__ bias, int mode) {
    extern __shared__ __align__(1024) char smem[];
    uint32_t smb = smem_to_u32(smem);
    int tid = threadIdx.x;
    int wid = tid >> 5, lane = tid & 31;
    int b = blockIdx.z / nsplit, sp = blockIdx.z % nsplit;
    int basec = NCtot / nsplit, remc = NCtot % nsplit;
    int NC = basec + (sp < remc ? 1 : 0);
    int startc = sp * basec + (sp < remc ? sp : remc);
    int koff0 = startc << 6;
    int i0, j0;
    if (mode == 4) {
        i0 = c_pi[blockIdx.x] * 128;
        j0 = c_pj[blockIdx.x] * 128;
    } else {
        i0 = blockIdx.x * 128;
        j0 = blockIdx.y * 128;
    }
    int wm = (wid >> 2) * 64, wn = (wid & 3) * 32;

    const __nv_bfloat16* tiles[4] = {Ahi + sA * b, Alo + sA * b, Bhi + sB * b, Blo + sB * b};
    const int row0[4] = {i0, i0, j0, j0};

    int lr[4], lu[4];
#pragma unroll
    for (int it = 0; it < 4; it++) {
        int q = tid + it * 256;
        lr[it] = q >> 3;
        lu[it] = q & 7;
    }

    auto load_chunk = [&](int chunk) {
        uint32_t sbase = smb + (chunk % NSTAGE) * STAGE_BYTES;
        int koff = koff0 + (chunk << 6);
#pragma unroll
        for (int tile = 0; tile < 4; tile++) {
            const __nv_bfloat16* src = tiles[tile];
#pragma unroll
            for (int it = 0; it < 4; it++) {
                uint32_t boff = (uint32_t)(lr[it] * 128 + lu[it] * 16);
                uint32_t sw = SMEM_SWIZZLE_128B(boff);
                const void* g = src + (size_t)(row0[tile] + lr[it]) * ldk + koff + lu[it] * 8;
                cpasync16(sbase + tile * TILE_BYTES + sw, g);
            }
        }
        cp_commit();
    };

    float acc[4][4][4];
#pragma unroll
    for (int a = 0; a < 4; a++)
#pragma unroll
        for (int bb = 0; bb < 4; bb++)
#pragma unroll
            for (int c = 0; c < 4; c++) acc[a][bb][c] = 0.f;

    int arow = wm + (lane & 15);
    int akh16 = ((lane >> 4) & 1) * 16;
    int brow = wn + ((lane >> 4) & 1) * 8 + (lane & 7);
    int bkh16 = ((lane >> 3) & 1) * 16;

    load_chunk(0);
    if (NC > 1) load_chunk(1);

    for (int kc = 0; kc < NC; kc++) {
        if (kc < NC - 1) cp_wait<1>();
        else cp_wait<0>();
        __syncthreads();

        uint32_t sAh = smb + (kc % NSTAGE) * STAGE_BYTES;
        uint32_t sAl = sAh + TILE_BYTES;
        uint32_t sBh = sAh + 2 * TILE_BYTES;
        uint32_t sBl = sAh + 3 * TILE_BYTES;

#pragma unroll
        for (int kk = 0; kk < 4; kk++) {
            uint32_t ah[4][4], al[4][4], bh[2][4], bl[2][4];
#pragma unroll
            for (int mt = 0; mt < 4; mt++) {
                uint32_t o = (uint32_t)((arow + mt * 16) * 128 + kk * 32 + akh16);
                uint32_t sw = SMEM_SWIZZLE_128B(o);
                ldmx4(ah[mt], sAh + sw);
                ldmx4(al[mt], sAl + sw);
            }
#pragma unroll
            for (int np = 0; np < 2; np++) {
                uint32_t o = (uint32_t)((brow + np * 16) * 128 + kk * 32 + bkh16);
                uint32_t sw = SMEM_SWIZZLE_128B(o);
                ldmx4(bh[np], sBh + sw);
                ldmx4(bl[np], sBl + sw);
            }
#pragma unroll
            for (int mt = 0; mt < 4; mt++)
#pragma unroll
                for (int nt = 0; nt < 4; nt++) {
                    uint32_t* bfh = &bh[nt >> 1][(nt & 1) * 2];
                    uint32_t* bfl = &bl[nt >> 1][(nt & 1) * 2];
                    mma16816(acc[mt][nt], ah[mt], bfh);  // hi*hi
                    mma16816(acc[mt][nt], ah[mt], bfl);  // hi*lo
                    mma16816(acc[mt][nt], al[mt], bfh);  // lo*hi
                }
        }
        if (kc + 2 < NC) load_chunk(kc + 2);
    }

    // ---- epilogue ----
    float* loc = (mode == 4)
        ? Cf + ((size_t)blockIdx.z * gridDim.x + blockIdx.x) * (128 * 128)
        : nullptr;
#pragma unroll
    for (int mt = 0; mt < 4; mt++) {
#pragma unroll
        for (int half = 0; half < 2; half++) {
            int lrow = wm + mt * 16 + (lane >> 2) + half * 8;
            int grow = i0 + lrow;
#pragma unroll
            for (int nt = 0; nt < 4; nt++) {
                int lcol = wn + nt * 8 + (lane & 3) * 2;
                int gcol = j0 + lcol;
                float v0 = acc[mt][nt][half * 2 + 0];
                float v1 = acc[mt][nt][half * 2 + 1];
                if (mode == 4) {
                    *(float2*)&loc[lrow * 128 + lcol] = make_float2(v0, v1);
                } else if (mode == 3) {
                    *(float2*)&Cf[sC * blockIdx.z + (size_t)grow * ldc + gcol] = make_float2(v0, v1);
                } else if (mode == 2) {
                    float2 f2 = make_float2(v0 + bias[gcol], v1 + bias[gcol + 1]);
                    *(float2*)&Cf[sC * b + (size_t)grow * ldc + gcol] = f2;
                } else {
                    __nv_bfloat162 h2, l2;
                    split_f32(v0, h2.x, l2.x);
                    split_f32(v1, h2.y, l2.y);
                    *(__nv_bfloat162*)&Chi[sC * b + (size_t)grow * ldc + gcol] = h2;
                    *(__nv_bfloat162*)&Clo[sC * b + (size_t)grow * ldc + gcol] = l2;
                }
            }
        }
    }
}

// ---------------------------------------------------------------------------
// logits GEMM: 512 threads, tile 128x256, persistent over 4 j-tiles.
//   logits[b][i][j] = sum_k Xb[b][i][k] * P[b][j][k] + Lb[j]
//   Grid (KL/128, 1, KB) = 128 CTAs (single wave). 2-stage pipeline, 96KB/stage.
//   16 warps: 2x8 layout of 64x32 warp tiles. Frag loads streamed per-mt to
//   stay under the 128-reg cap.
// ---------------------------------------------------------------------------
#define L_AT 16384                 // A tile bytes (128 rows x 128B)
#define L_BT 32768                 // B tile bytes (256 rows x 128B)
#define L_STAGE (2 * L_AT + 2 * L_BT)   // 98304
#define L_DYN (2 * L_STAGE)             // 196608

__global__ __launch_bounds__(512, 1) void logits_gemm_k(
    const __nv_bfloat16* __restrict__ Ahi, const __nv_bfloat16* __restrict__ Alo,
    const __nv_bfloat16* __restrict__ Bhi, const __nv_bfloat16* __restrict__ Blo,
    const float* __restrict__ bias, float* __restrict__ Cf) {
    extern __shared__ __align__(1024) char smem[];
    uint32_t smb = smem_to_u32(smem);
    int tid = threadIdx.x;
    int wid = tid >> 5, lane = tid & 31;
    int b = blockIdx.z;
    int i0 = blockIdx.x * 128;
    int wm = (wid >> 3) * 64, wn = (wid & 7) * 32;

    const __nv_bfloat16* A0h = Ahi + (size_t)b * KL * KD;
    const __nv_bfloat16* A0l = Alo + (size_t)b * KL * KD;
    const __nv_bfloat16* B0h = Bhi + (size_t)b * KVP * KD;
    const __nv_bfloat16* B0l = Blo + (size_t)b * KVP * KD;
    float* C0 = Cf + (size_t)b * KL * KVP;

    // loader: chunk c (0..31): jt=c>>3, koff=(c&7)*64, j0=jt*256
    auto load_chunk = [&](int c) {
        uint32_t sbase = smb + (c & 1) * L_STAGE;
        int koff = (c & 7) << 6;
        int j0c = (c >> 3) << 8;
        // A hi/lo: 1024 16B-units each -> 2 per thread
#pragma unroll
        for (int it = 0; it < 2; it++) {
            int q = tid + it * 512;
            int r = q >> 3, u = q & 7;
            uint32_t sw = SMEM_SWIZZLE_128B((uint32_t)(r * 128 + u * 16));
            size_t go = (size_t)(i0 + r) * KD + koff + u * 8;
            cpasync16(sbase + sw, A0h + go);
            cpasync16(sbase + L_AT + sw, A0l + go);
        }
        // B hi/lo: 2048 units each -> 4 per thread
#pragma unroll
        for (int it = 0; it < 4; it++) {
            int q = tid + it * 512;
            int r = q >> 3, u = q & 7;
            uint32_t sw = SMEM_SWIZZLE_128B((uint32_t)(r * 128 + u * 16));
            size_t go = (size_t)(j0c + r) * KD + koff + u * 8;
            cpasync16(sbase + 2 * L_AT + sw, B0h + go);
            cpasync16(sbase + 2 * L_AT + L_BT + sw, B0l + go);
        }
        cp_commit();
    };

    float acc[4][4][4];
#pragma unroll
    for (int a = 0; a < 4; a++)
#pragma unroll
        for (int bb = 0; bb < 4; bb++)
#pragma unroll
            for (int cc = 0; cc < 4; cc++) acc[a][bb][cc] = 0.f;

    int arow = wm + (lane & 15);
    int akh16 = ((lane >> 4) & 1) * 16;
    int brow = wn + ((lane >> 4) & 1) * 8 + (lane & 7);
    int bkh16 = ((lane >> 3) & 1) * 16;

    load_chunk(0);

    const int NCall = 32;   // 4 j-tiles x 8 chunks
    for (int c = 0; c < NCall; c++) {
        cp_wait<0>();
        __syncthreads();
        if (c + 1 < NCall) load_chunk(c + 1);

        uint32_t sb = smb + (c & 1) * L_STAGE;
#pragma unroll
        for (int kk = 0; kk < 4; kk++) {
            uint32_t bh[2][4], bl[2][4];
#pragma unroll
            for (int np = 0; np < 2; np++) {
                uint32_t o = (uint32_t)((brow + np * 16) * 128 + kk * 32 + bkh16);
                uint32_t sw = SMEM_SWIZZLE_128B(o);
                ldmx4(bh[np], sb + 2 * L_AT + sw);
                ldmx4(bl[np], sb + 2 * L_AT + L_BT + sw);
            }
#pragma unroll
            for (int mt = 0; mt < 4; mt++) {
                uint32_t ah[4], al[4];
                uint32_t o = (uint32_t)((arow + mt * 16) * 128 + kk * 32 + akh16);
                uint32_t sw = SMEM_SWIZZLE_128B(o);
                ldmx4(ah, sb + sw);
                ldmx4(al, sb + L_AT + sw);
#pragma unroll
                for (int p = 0; p < 3; p++)
#pragma unroll
                    for (int nt = 0; nt < 4; nt++) {
                        const uint32_t* af = (p == 2) ? al : ah;
                        const uint32_t* bf = (p == 1) ? &bl[nt >> 1][(nt & 1) * 2]
                                                      : &bh[nt >> 1][(nt & 1) * 2];
                        mma16816(acc[mt][nt], af, bf);
                    }
            }
        }

        if ((c & 7) == 7) {
            // epilogue for j-tile (c>>3)
            int j0c = (c >> 3) << 8;
#pragma unroll
            for (int mt = 0; mt < 4; mt++) {
#pragma unroll
                for (int half = 0; half < 2; half++) {
                    int grow = i0 + wm + mt * 16 + (lane >> 2) + half * 8;
#pragma unroll
                    for (int nt = 0; nt < 4; nt++) {
                        int gcol = j0c + wn + nt * 8 + (lane & 3) * 2;
                        float v0 = acc[mt][nt][half * 2 + 0] + bias[gcol];
                        float v1 = acc[mt][nt][half * 2 + 1] + bias[gcol + 1];
                        *(float2*)&C0[(size_t)grow * KVP + gcol] = make_float2(v0, v1);
                        acc[mt][nt][half * 2 + 0] = 0.f;
                        acc[mt][nt][half * 2 + 1] = 0.f;
                    }
                }
            }
        }
    }
}

// ---------------------------------------------------------------------------
// reduce symmetric-G partials (10 tile-pairs x G_NSPLIT) -> full G hi/lo bf16
// ---------------------------------------------------------------------------
__global__ void reduce_G_k() {
    size_t idx = ((size_t)blockIdx.x * 256 + threadIdx.x) * 2;  // KB*KD*KD elems
    const size_t per = (size_t)KD * KD;
    int b = (int)(idx / per);
    size_t rem = idx % per;
    int i = (int)(rem / KD), j = (int)(rem % KD);
    int ti = i >> 7, tj = j >> 7;
    float s0 = 0.f, s1 = 0.f;
    if (ti <= tj) {
        int p = c_PT[ti * 4 + tj];
        size_t off = (size_t)((i & 127) * 128 + (j & 127));
        for (int sp = 0; sp < G_NSPLIT; sp++) {
            const float* base = g_Gp + ((size_t)(b * G_NSPLIT + sp) * 10 + p) * (128 * 128);
            s0 += base[off];
            s1 += base[off + 1];
        }
    } else {
        int p = c_PT[tj * 4 + ti];
        size_t off = (size_t)((j & 127) * 128 + (i & 127));
        for (int sp = 0; sp < G_NSPLIT; sp++) {
            const float* base = g_Gp + ((size_t)(b * G_NSPLIT + sp) * 10 + p) * (128 * 128);
            s0 += base[off];
            s1 += base[off + 128];   // G[i][j+1] = mirrored tile, next row
        }
    }
    __nv_bfloat162 h2, l2;
    split_f32(s0, h2.x, l2.x);
    split_f32(s1, h2.y, l2.y);
    *(__nv_bfloat162*)&g_G_hi[idx] = h2;
    *(__nv_bfloat162*)&g_G_lo[idx] = l2;
}

// ---------------------------------------------------------------------------
// reduce M K-split partials + rank-1 Wb[i]*s[b][j] -> hi/lo bf16
// ---------------------------------------------------------------------------
__global__ void reduce_M_k(const float* __restrict__ Wb) {
    size_t idx = ((size_t)blockIdx.x * 256 + threadIdx.x) * 2;
    const size_t per = (size_t)KD * KD;
    int b = (int)(idx / per);
    size_t rem = idx % per;
    int i = (int)(rem / KD), j = (int)(rem % KD);
    float s0 = 0.f, s1 = 0.f;
    for (int sp = 0; sp < M_NSPLIT; sp++) {
        const float* p = g_Mp + ((size_t)(b * M_NSPLIT + sp)) * per + rem;
        s0 += p[0];
        s1 += p[1];
    }
    float u = Wb[i];
    s0 += u * g_s[b * KD + j];
    s1 += u * g_s[b * KD + j + 1];
    __nv_bfloat162 h2, l2;
    split_f32(s0, h2.x, l2.x);
    split_f32(s1, h2.y, l2.y);
    *(__nv_bfloat162*)&g_M_hi[idx] = h2;
    *(__nv_bfloat162*)&g_M_lo[idx] = l2;
}

// ---------------------------------------------------------------------------
// log_softmax over V + permute (B,L,V)->(L,B,V)
// ---------------------------------------------------------------------------
__global__ void logsoftmax_k(float* __restrict__ out) {
    int l = blockIdx.x, b = blockIdx.y;
    const float* row = g_logits + (size_t)(b * KL + l) * KVP;
    float* orow = out + (size_t)(l * KB + b) * KV;
    __shared__ float sred[8];
    int t = threadIdx.x;
    int wid = t >> 5, lane = t & 31;
    bool act = t < (KV / 4);
    float4 v = act ? *(const float4*)&row[t * 4]
                   : make_float4(-3.4e38f, -3.4e38f, -3.4e38f, -3.4e38f);
    float m = fmaxf(fmaxf(v.x, v.y), fmaxf(v.z, v.w));
#pragma unroll
    for (int s = 16; s >= 1; s >>= 1) m = fmaxf(m, __shfl_xor_sync(0xffffffffu, m, s));
    if (lane == 0) sred[wid] = m;
    __syncthreads();
    float m8 = (lane < 8) ? sred[lane] : -3.4e38f;
#pragma unroll
    for (int s = 4; s >= 1; s >>= 1) m8 = fmaxf(m8, __shfl_xor_sync(0xffffffffu, m8, s));
    float vmax = __shfl_sync(0xffffffffu, m8, 0);

    float e = act ? (__expf(v.x - vmax) + __expf(v.y - vmax) +
                     __expf(v.z - vmax) + __expf(v.w - vmax))
                  : 0.f;
#pragma unroll
    for (int s = 16; s >= 1; s >>= 1) e += __shfl_xor_sync(0xffffffffu, e, s);
    __syncthreads();
    if (lane == 0) sred[wid] = e;
    __syncthreads();
    float e8 = (lane < 8) ? sred[lane] : 0.f;
#pragma unroll
    for (int s = 4; s >= 1; s >>= 1) e8 += __shfl_xor_sync(0xffffffffu, e8, s);
    float denom = vmax + logf(__shfl_sync(0xffffffffu, e8, 0));

    if (act) {
        float4 o;
        o.x = v.x - denom; o.y = v.y - denom;
        o.z = v.z - denom; o.w = v.w - denom;
        *(float4*)&orow[t * 4] = o;
    }
}

// ---------------------------------------------------------------------------
extern "C" void kernel_launch(void* const* d_in, const int* in_sizes, int n_in,
                              void* d_out, int out_size) {
    (void)in_sizes; (void)n_in; (void)out_size;
    const float* x  = (const float*)d_in[0];
    const float* Ww = (const float*)d_in[1];
    const float* Wb = (const float*)d_in[2];
    const float* Lw = (const float*)d_in[3];
    const float* Lb = (const float*)d_in[4];
    float* out = (float*)d_out;

    static bool attr_set = false;
    if (!attr_set) {
        cudaFuncSetAttribute(mma_gemm_k, cudaFuncAttributeMaxDynamicSharedMemorySize, DYN_SMEM);
        cudaFuncSetAttribute(logits_gemm_k, cudaFuncAttributeMaxDynamicSharedMemorySize, L_DYN);
        attr_set = true;
    }

    __nv_bfloat16 *Xb_hi, *Xb_lo, *Xt_hi, *Xt_lo, *Wwh, *Wwl, *Lwh, *Lwl;
    __nv_bfloat16 *Gh, *Gl, *Mh, *Ml, *Ph, *Pl;
    float *Lbp, *logits, *Gp, *Mp;
    cudaGetSymbolAddress((void**)&Xb_hi, g_Xb_hi);
    cudaGetSymbolAddress((void**)&Xb_lo, g_Xb_lo);
    cudaGetSymbolAddress((void**)&Xt_hi, g_Xt_hi);
    cudaGetSymbolAddress((void**)&Xt_lo, g_Xt_lo);
    cudaGetSymbolAddress((void**)&Wwh, g_Ww_hi);
    cudaGetSymbolAddress((void**)&Wwl, g_Ww_lo);
    cudaGetSymbolAddress((void**)&Lwh, g_Lw_hi);
    cudaGetSymbolAddress((void**)&Lwl, g_Lw_lo);
    cudaGetSymbolAddress((void**)&Gh, g_G_hi);
    cudaGetSymbolAddress((void**)&Gl, g_G_lo);
    cudaGetSymbolAddress((void**)&Mh, g_M_hi);
    cudaGetSymbolAddress((void**)&Ml, g_M_lo);
    cudaGetSymbolAddress((void**)&Ph, g_P_hi);
    cudaGetSymbolAddress((void**)&Pl, g_P_lo);
    cudaGetSymbolAddress((void**)&Lbp, g_Lbp);
    cudaGetSymbolAddress((void**)&logits, g_logits);
    cudaGetSymbolAddress((void**)&Gp, g_Gp);
    cudaGetSymbolAddress((void**)&Mp, g_Mp);

    prep_x_k<<<dim3(KL / 64, KD / 64, KB), 256>>>(x);
    colsum_final_k<<<(KB * KD) / 256, 256>>>();
    prep_w_k<<<(KVP * KD) / 256, 256>>>(Ww, Lw, Lb);

    // G[b] = Xt*Xt^T (symmetric): 10 upper tile-pairs, K-split x3 -> 120 CTAs
    mma_gemm_k<<<dim3(10, 1, KB * G_NSPLIT), 256, DYN_SMEM>>>(
        Xt_hi, Xt_lo, (size_t)KD * KL, Xt_hi, Xt_lo, (size_t)KD * KL,
        KL, KL / 64, G_NSPLIT, nullptr, nullptr, Gp, 0, 128, nullptr, 4);
    reduce_G_k<<<(KB * KD * KD / 2) / 256, 256>>>();

    // M[b] = Ww*G[b]^T (512x512, K=512); K-split x2; rank-1 in reduce
    mma_gemm_k<<<dim3(4, 4, KB * M_NSPLIT), 256, DYN_SMEM>>>(
        Wwh, Wwl, 0, Gh, Gl, (size_t)KD * KD,
        KD, KD / 64, M_NSPLIT, nullptr, nullptr, Mp, (size_t)KD * KD, KD, nullptr, 3);
    reduce_M_k<<<(KB * KD * KD / 2) / 256, 256>>>(Wb);

    // P[b][v][k] = sum_n Lw[v][n] * M[b][k][n]  -> bf16 split
    mma_gemm_k<<<dim3(KVP / 128, KD / 128, KB), 256, DYN_SMEM>>>(
        Lwh, Lwl, 0, Mh, Ml, (size_t)KD * KD,
        KD, KD / 64, 1, Ph, Pl, nullptr, (size_t)KVP * KD, KD, nullptr, 0);

    // logits[b] = Xb * P^T + Lb : persistent 512-thread kernel, 128 CTAs
    logits_gemm_k<<<dim3(KL / 128, 1, KB), 512, L_DYN>>>(
        Xb_hi, Xb_lo, Ph, Pl, Lbp, logits);

    logsoftmax_k<<<dim3(KL, KB), 256>>>(out);
}

// round 11
// speedup vs baseline: 1.0143x; 1.0040x over previous
#include <cuda_runtime.h>
#include <cuda_bf16.h>
#include <cstdint>

#define KL 4096
#define KB 4
#define KD 512
#define KV 1000
#define KVP 1024   // padded vocab

// ---------------------------------------------------------------------------
// PTX helpers (sm_80-compatible only: ldmatrix / mma.sync / cp.async)
// ---------------------------------------------------------------------------
__device__ __forceinline__ uint32_t smem_to_u32(const void* p) {
    uint32_t a;
    asm("{ .reg .u64 t; cvta.to.shared.u64 t, %1; cvt.u32.u64 %0, t; }" : "=r"(a) : "l"(p));
    return a;
}
__device__ __forceinline__ void cpasync16(uint32_t s, const void* g) {
    asm volatile("cp.async.cg.shared.global [%0], [%1], 16;" :: "r"(s), "l"(g));
}
__device__ __forceinline__ void cp_commit() {
    asm volatile("cp.async.commit_group;" ::: "memory");
}
template <int N>
__device__ __forceinline__ void cp_wait() {
    asm volatile("cp.async.wait_group %0;" :: "n"(N) : "memory");
}
__device__ __forceinline__ void ldmx4(uint32_t* r, uint32_t a) {
    asm volatile("ldmatrix.sync.aligned.m8n8.x4.shared.b16 {%0,%1,%2,%3}, [%4];"
                 : "=r"(r[0]), "=r"(r[1]), "=r"(r[2]), "=r"(r[3]) : "r"(a));
}
__device__ __forceinline__ void mma16816(float* d, const uint32_t* a, const uint32_t* b) {
    asm volatile(
        "mma.sync.aligned.m16n8k16.row.col.f32.bf16.bf16.f32 "
        "{%0,%1,%2,%3}, {%4,%5,%6,%7}, {%8,%9}, {%0,%1,%2,%3};"
        : "+f"(d[0]), "+f"(d[1]), "+f"(d[2]), "+f"(d[3])
        : "r"(a[0]), "r"(a[1]), "r"(a[2]), "r"(a[3]), "r"(b[0]), "r"(b[1]));
}
#define SMEM_SWIZZLE_128B(o) ((o) ^ (((o) >> 3) & 0x70))

// symmetric-G tile pair tables (upper triangle of 4x4)
__constant__ int c_pi[10] = {0, 0, 0, 0, 1, 1, 1, 2, 2, 3};
__constant__ int c_pj[10] = {0, 1, 2, 3, 1, 2, 3, 2, 3, 3};
__constant__ int c_PT[16] = {0, 1, 2, 3,  0, 4, 5, 6,  0, 0, 7, 8,  0, 0, 0, 9};

// ---------------------------------------------------------------------------
// scratch (static device globals; no allocations)
// ---------------------------------------------------------------------------
#define G_NSPLIT 3   // 10 pairs * KB * 3 = 120 CTAs -> single wave on 148 SMs
#define M_NSPLIT 2
__device__ __align__(128) float g_part2[KB * KD * 64];   // colsum partials
__device__ __align__(128) float g_s[KB * KD];
__device__ __align__(128) __nv_bfloat16 g_Xb_hi[(size_t)KB * KL * KD], g_Xb_lo[(size_t)KB * KL * KD];
__device__ __align__(128) __nv_bfloat16 g_Xt_hi[(size_t)KB * KD * KL], g_Xt_lo[(size_t)KB * KD * KL];
__device__ __align__(128) __nv_bfloat16 g_Ww_hi[KD * KD], g_Ww_lo[KD * KD];
__device__ __align__(128) __nv_bfloat16 g_Lw_hi[KVP * KD], g_Lw_lo[KVP * KD];
__device__ __align__(128) float g_Lbp[KVP];
__device__ __align__(128) float g_Gp[(size_t)KB * G_NSPLIT * 10 * 128 * 128]; // 7.9 MB
__device__ __align__(128) float g_Mp[(size_t)M_NSPLIT * KB * KD * KD];        // 8 MB
__device__ __align__(128) __nv_bfloat16 g_G_hi[KB * KD * KD], g_G_lo[KB * KD * KD];
__device__ __align__(128) __nv_bfloat16 g_M_hi[KB * KD * KD], g_M_lo[KB * KD * KD];
__device__ __align__(128) __nv_bfloat16 g_P_hi[(size_t)KB * KVP * KD], g_P_lo[(size_t)KB * KVP * KD];
__device__ __align__(128) float g_logits[(size_t)KB * KL * KVP];

__device__ __forceinline__ void split_f32(float v, __nv_bfloat16& h, __nv_bfloat16& l) {
    h = __float2bfloat16(v);
    l = __float2bfloat16(v - __bfloat162float(h));
}

// ---------------------------------------------------------------------------
// prep_x: x (L,B,D) fp32 -> Xb[b][l][d] hi/lo, Xt[b][d][l] hi/lo, colsum partials
// ---------------------------------------------------------------------------
__global__ __launch_bounds__(256) void prep_x_k(const float* __restrict__ x) {
    __shared__ __nv_bfloat16 shi[64][65], slo[64][65];
    __shared__ float ssum[4][64];
    int b = blockIdx.z;
    int lblk = blockIdx.x;
    int l0 = lblk * 64, d0 = blockIdx.y * 64;
    int t = threadIdx.x;
    int c = t & 63, r4 = t >> 6;
    float ps = 0.f;
#pragma unroll 4
    for (int rr = 0; rr < 16; rr++) {
        int r = r4 * 16 + rr;
        float v = x[(size_t)(l0 + r) * (KB * KD) + b * KD + d0 + c];
        ps += v;
        __nv_bfloat16 h, l;
        split_f32(v, h, l);
        size_t o = ((size_t)b * KL + (l0 + r)) * KD + d0 + c;
        g_Xb_hi[o] = h; g_Xb_lo[o] = l;
        shi[r][c] = h; slo[r][c] = l;
    }
    ssum[r4][c] = ps;
    __syncthreads();
#pragma unroll 4
    for (int rr = 0; rr < 16; rr++) {
        int r = r4 * 16 + rr;   // d index
        size_t o = ((size_t)b * KD + (d0 + r)) * KL + l0 + c;
        g_Xt_hi[o] = shi[c][r];
        g_Xt_lo[o] = slo[c][r];
    }
    if (t < 64) {
        float s = ssum[0][t] + ssum[1][t] + ssum[2][t] + ssum[3][t];
        g_part2[((size_t)b * KD + d0 + t) * 64 + lblk] = s;
    }
}

__global__ void colsum_final_k() {
    int idx = blockIdx.x * 256 + threadIdx.x;  // KB*KD
    float s = 0.f;
    const float* p = &g_part2[(size_t)idx * 64];
#pragma unroll
    for (int k = 0; k < 64; k++) s += p[k];
    g_s[idx] = s;
}

// ---------------------------------------------------------------------------
// prep_w (flat): split Ww; split Lw padded to 1024 rows; pad Lb
// ---------------------------------------------------------------------------
__global__ void prep_w_k(const float* __restrict__ Ww, const float* __restrict__ Lw,
                         const float* __restrict__ Lb) {
    int idx = blockIdx.x * 256 + threadIdx.x;   // over KVP*KD
    int row = idx / KD;
    float v2 = (row < KV) ? Lw[idx] : 0.f;
    __nv_bfloat16 h2, l2;
    split_f32(v2, h2, l2);
    g_Lw_hi[idx] = h2; g_Lw_lo[idx] = l2;
    if (idx < KD * KD) {
        __nv_bfloat16 h, l;
        split_f32(Ww[idx], h, l);
        g_Ww_hi[idx] = h; g_Ww_lo[idx] = l;
    }
    if (idx < KVP) g_Lbp[idx] = (idx < KV) ? Lb[idx] : 0.f;
}

// ---------------------------------------------------------------------------
// mma.sync bf16 split GEMM: C[m][n] = sum_k A[m][k]*B[n][k], hi/lo 3-product
//   K handled in 64-wide chunks. NCtot chunks split over nsplit slots.
//   mode 0: write Chi/Clo bf16 (batch b)
//   mode 2: write Cf fp32 + bias[col] (batch b)
//   mode 3: write Cf fp32 K-split partial (slot blockIdx.z)
//   mode 4: symmetric pairs — i0/j0 from c_pi/c_pj[blockIdx.x]; local tile out
//           diagonal pairs (i0==j0) alias B smem to A (skip half the loads)
// CTA tile 128x128, K-chunk 64, 3-stage cp.async, one barrier per chunk.
// Next-chunk burst issued right AFTER the barrier (max prefetch slack).
// ---------------------------------------------------------------------------
#define TILE_BYTES 16384               // 128 rows x 128B (64 bf16)
#define STAGE_BYTES (4 * TILE_BYTES)   // Ah, Al, Bh, Bl
#define NSTAGE 3
#define DYN_SMEM (NSTAGE * STAGE_BYTES)  // 192 KB

__global__ __launch_bounds__(256, 1) void mma_gemm_k(
    const __nv_bfloat16* __restrict__ Ahi, const __nv_bfloat16* __restrict__ Alo, size_t sA,
    const __nv_bfloat16* __restrict__ Bhi, const __nv_bfloat16* __restrict__ Blo, size_t sB,
    int ldk, int NCtot, int nsplit,
    __nv_bfloat16* __restrict__ Chi, __nv_bfloat16* __restrict__ Clo,
    float* __restrict__ Cf, size_t sC, int ldc,
    const float* __restrict__ bias, int mode) {
    extern __shared__ __align__(1024) char smem[];
    uint32_t smb = smem_to_u32(smem);
    int tid = threadIdx.x;
    int wid = tid >> 5, lane = tid & 31;
    int b = blockIdx.z / nsplit, sp = blockIdx.z % nsplit;
    int basec = NCtot / nsplit, remc = NCtot % nsplit;
    int NC = basec + (sp < remc ? 1 : 0);
    int startc = sp * basec + (sp < remc ? sp : remc);
    int koff0 = startc << 6;
    int i0, j0;
    if (mode == 4) {
        i0 = c_pi[blockIdx.x] * 128;
        j0 = c_pj[blockIdx.x] * 128;
    } else {
        i0 = blockIdx.x * 128;
        j0 = blockIdx.y * 128;
    }
    bool diag = (mode == 4) && (i0 == j0);   // A and B tiles identical
    int wm = (wid >> 2) * 64, wn = (wid & 3) * 32;

    const __nv_bfloat16* tiles[4] = {Ahi + sA * b, Alo + sA * b, Bhi + sB * b, Blo + sB * b};
    const int row0[4] = {i0, i0, j0, j0};
    const int ntiles = diag ? 2 : 4;

    int lr[4], lu[4];
#pragma unroll
    for (int it = 0; it < 4; it++) {
        int q = tid + it * 256;
        lr[it] = q >> 3;
        lu[it] = q & 7;
    }

    auto load_chunk = [&](int chunk) {
        uint32_t sbase = smb + (chunk % NSTAGE) * STAGE_BYTES;
        int koff = koff0 + (chunk << 6);
        for (int tile = 0; tile < ntiles; tile++) {
            const __nv_bfloat16* src = tiles[tile];
#pragma unroll
            for (int it = 0; it < 4; it++) {
                uint32_t boff = (uint32_t)(lr[it] * 128 + lu[it] * 16);
                uint32_t sw = SMEM_SWIZZLE_128B(boff);
                const void* g = src + (size_t)(row0[tile] + lr[it]) * ldk + koff + lu[it] * 8;
                cpasync16(sbase + tile * TILE_BYTES + sw, g);
            }
        }
        cp_commit();
    };

    float acc[4][4][4];
#pragma unroll
    for (int a = 0; a < 4; a++)
#pragma unroll
        for (int bb = 0; bb < 4; bb++)
#pragma unroll
            for (int c = 0; c < 4; c++) acc[a][bb][c] = 0.f;

    int arow = wm + (lane & 15);
    int akh16 = ((lane >> 4) & 1) * 16;
    int brow = wn + ((lane >> 4) & 1) * 8 + (lane & 7);
    int bkh16 = ((lane >> 3) & 1) * 16;
    uint32_t bh_tile_off = diag ? 0u : 2u * TILE_BYTES;   // B aliases A on diag
    uint32_t bl_tile_off = diag ? TILE_BYTES : 3u * TILE_BYTES;

    load_chunk(0);
    if (NC > 1) load_chunk(1);

    for (int kc = 0; kc < NC; kc++) {
        if (kc < NC - 1) cp_wait<1>();
        else cp_wait<0>();
        __syncthreads();
        // prefetch chunk kc+2 NOW: its stage was freed by the barrier, and
        // issuing before compute gives the burst ~2 chunk-computes of slack.
        if (kc + 2 < NC) load_chunk(kc + 2);

        uint32_t sAh = smb + (kc % NSTAGE) * STAGE_BYTES;
        uint32_t sAl = sAh + TILE_BYTES;
        uint32_t sBh = sAh + bh_tile_off;
        uint32_t sBl = sAh + bl_tile_off;

#pragma unroll
        for (int kk = 0; kk < 4; kk++) {
            uint32_t ah[4][4], al[4][4], bh[2][4], bl[2][4];
#pragma unroll
            for (int mt = 0; mt < 4; mt++) {
                uint32_t o = (uint32_t)((arow + mt * 16) * 128 + kk * 32 + akh16);
                uint32_t sw = SMEM_SWIZZLE_128B(o);
                ldmx4(ah[mt], sAh + sw);
                ldmx4(al[mt], sAl + sw);
            }
#pragma unroll
            for (int np = 0; np < 2; np++) {
                uint32_t o = (uint32_t)((brow + np * 16) * 128 + kk * 32 + bkh16);
                uint32_t sw = SMEM_SWIZZLE_128B(o);
                ldmx4(bh[np], sBh + sw);
                ldmx4(bl[np], sBl + sw);
            }
#pragma unroll
            for (int mt = 0; mt < 4; mt++)
#pragma unroll
                for (int nt = 0; nt < 4; nt++) {
                    uint32_t* bfh = &bh[nt >> 1][(nt & 1) * 2];
                    uint32_t* bfl = &bl[nt >> 1][(nt & 1) * 2];
                    mma16816(acc[mt][nt], ah[mt], bfh);  // hi*hi
                    mma16816(acc[mt][nt], ah[mt], bfl);  // hi*lo
                    mma16816(acc[mt][nt], al[mt], bfh);  // lo*hi
                }
        }
    }

    // ---- epilogue ----
    float* loc = (mode == 4)
        ? Cf + ((size_t)blockIdx.z * gridDim.x + blockIdx.x) * (128 * 128)
        : nullptr;
#pragma unroll
    for (int mt = 0; mt < 4; mt++) {
#pragma unroll
        for (int half = 0; half < 2; half++) {
            int lrow = wm + mt * 16 + (lane >> 2) + half * 8;
            int grow = i0 + lrow;
#pragma unroll
            for (int nt = 0; nt < 4; nt++) {
                int lcol = wn + nt * 8 + (lane & 3) * 2;
                int gcol = j0 + lcol;
                float v0 = acc[mt][nt][half * 2 + 0];
                float v1 = acc[mt][nt][half * 2 + 1];
                if (mode == 4) {
                    *(float2*)&loc[lrow * 128 + lcol] = make_float2(v0, v1);
                } else if (mode == 3) {
                    *(float2*)&Cf[sC * blockIdx.z + (size_t)grow * ldc + gcol] = make_float2(v0, v1);
                } else if (mode == 2) {
                    float2 f2 = make_float2(v0 + bias[gcol], v1 + bias[gcol + 1]);
                    *(float2*)&Cf[sC * b + (size_t)grow * ldc + gcol] = f2;
                } else {
                    __nv_bfloat162 h2, l2;
                    split_f32(v0, h2.x, l2.x);
                    split_f32(v1, h2.y, l2.y);
                    *(__nv_bfloat162*)&Chi[sC * b + (size_t)grow * ldc + gcol] = h2;
                    *(__nv_bfloat162*)&Clo[sC * b + (size_t)grow * ldc + gcol] = l2;
                }
            }
        }
    }
}

// ---------------------------------------------------------------------------
// reduce symmetric-G partials (10 tile-pairs x G_NSPLIT) -> full G hi/lo bf16
// ---------------------------------------------------------------------------
__global__ void reduce_G_k() {
    size_t idx = ((size_t)blockIdx.x * 256 + threadIdx.x) * 2;  // KB*KD*KD elems
    const size_t per = (size_t)KD * KD;
    int b = (int)(idx / per);
    size_t rem = idx % per;
    int i = (int)(rem / KD), j = (int)(rem % KD);
    int ti = i >> 7, tj = j >> 7;
    float s0 = 0.f, s1 = 0.f;
    if (ti <= tj) {
        int p = c_PT[ti * 4 + tj];
        size_t off = (size_t)((i & 127) * 128 + (j & 127));
        for (int sp = 0; sp < G_NSPLIT; sp++) {
            const float* base = g_Gp + ((size_t)(b * G_NSPLIT + sp) * 10 + p) * (128 * 128);
            s0 += base[off];
            s1 += base[off + 1];
        }
    } else {
        int p = c_PT[tj * 4 + ti];
        size_t off = (size_t)((j & 127) * 128 + (i & 127));
        for (int sp = 0; sp < G_NSPLIT; sp++) {
            const float* base = g_Gp + ((size_t)(b * G_NSPLIT + sp) * 10 + p) * (128 * 128);
            s0 += base[off];
            s1 += base[off + 128];   // G[i][j+1] = mirrored tile, next row
        }
    }
    __nv_bfloat162 h2, l2;
    split_f32(s0, h2.x, l2.x);
    split_f32(s1, h2.y, l2.y);
    *(__nv_bfloat162*)&g_G_hi[idx] = h2;
    *(__nv_bfloat162*)&g_G_lo[idx] = l2;
}

// ---------------------------------------------------------------------------
// reduce M K-split partials + rank-1 Wb[i]*s[b][j] -> hi/lo bf16
// ---------------------------------------------------------------------------
__global__ void reduce_M_k(const float* __restrict__ Wb) {
    size_t idx = ((size_t)blockIdx.x * 256 + threadIdx.x) * 2;
    const size_t per = (size_t)KD * KD;
    int b = (int)(idx / per);
    size_t rem = idx % per;
    int i = (int)(rem / KD), j = (int)(rem % KD);
    float s0 = 0.f, s1 = 0.f;
    for (int sp = 0; sp < M_NSPLIT; sp++) {
        const float* p = g_Mp + ((size_t)(b * M_NSPLIT + sp)) * per + rem;
        s0 += p[0];
        s1 += p[1];
    }
    float u = Wb[i];
    s0 += u * g_s[b * KD + j];
    s1 += u * g_s[b * KD + j + 1];
    __nv_bfloat162 h2, l2;
    split_f32(s0, h2.x, l2.x);
    split_f32(s1, h2.y, l2.y);
    *(__nv_bfloat162*)&g_M_hi[idx] = h2;
    *(__nv_bfloat162*)&g_M_lo[idx] = l2;
}

// ---------------------------------------------------------------------------
// log_softmax over V + permute (B,L,V)->(L,B,V)
// ---------------------------------------------------------------------------
__global__ void logsoftmax_k(float* __restrict__ out) {
    int l = blockIdx.x, b = blockIdx.y;
    const float* row = g_logits + (size_t)(b * KL + l) * KVP;
    float* orow = out + (size_t)(l * KB + b) * KV;
    __shared__ float sred[8];
    int t = threadIdx.x;
    int wid = t >> 5, lane = t & 31;
    bool act = t < (KV / 4);
    float4 v = act ? *(const float4*)&row[t * 4]
                   : make_float4(-3.4e38f, -3.4e38f, -3.4e38f, -3.4e38f);
    float m = fmaxf(fmaxf(v.x, v.y), fmaxf(v.z, v.w));
#pragma unroll
    for (int s = 16; s >= 1; s >>= 1) m = fmaxf(m, __shfl_xor_sync(0xffffffffu, m, s));
    if (lane == 0) sred[wid] = m;
    __syncthreads();
    float m8 = (lane < 8) ? sred[lane] : -3.4e38f;
#pragma unroll
    for (int s = 4; s >= 1; s >>= 1) m8 = fmaxf(m8, __shfl_xor_sync(0xffffffffu, m8, s));
    float vmax = __shfl_sync(0xffffffffu, m8, 0);

    float e = act ? (__expf(v.x - vmax) + __expf(v.y - vmax) +
                     __expf(v.z - vmax) + __expf(v.w - vmax))
                  : 0.f;
#pragma unroll
    for (int s = 16; s >= 1; s >>= 1) e += __shfl_xor_sync(0xffffffffu, e, s);
    __syncthreads();
    if (lane == 0) sred[wid] = e;
    __syncthreads();
    float e8 = (lane < 8) ? sred[lane] : 0.f;
#pragma unroll
    for (int s = 4; s >= 1; s >>= 1) e8 += __shfl_xor_sync(0xffffffffu, e8, s);
    float denom = vmax + logf(__shfl_sync(0xffffffffu, e8, 0));

    if (act) {
        float4 o;
        o.x = v.x - denom; o.y = v.y - denom;
        o.z = v.z - denom; o.w = v.w - denom;
        *(float4*)&orow[t * 4] = o;
    }
}

// ---------------------------------------------------------------------------
extern "C" void kernel_launch(void* const* d_in, const int* in_sizes, int n_in,
                              void* d_out, int out_size) {
    (void)in_sizes; (void)n_in; (void)out_size;
    const float* x  = (const float*)d_in[0];
    const float* Ww = (const float*)d_in[1];
    const float* Wb = (const float*)d_in[2];
    const float* Lw = (const float*)d_in[3];
    const float* Lb = (const float*)d_in[4];
    float* out = (float*)d_out;

    static bool attr_set = false;
    if (!attr_set) {
        cudaFuncSetAttribute(mma_gemm_k, cudaFuncAttributeMaxDynamicSharedMemorySize, DYN_SMEM);
        attr_set = true;
    }

    __nv_bfloat16 *Xb_hi, *Xb_lo, *Xt_hi, *Xt_lo, *Wwh, *Wwl, *Lwh, *Lwl;
    __nv_bfloat16 *Gh, *Gl, *Mh, *Ml, *Ph, *Pl;
    float *Lbp, *logits, *Gp, *Mp;
    cudaGetSymbolAddress((void**)&Xb_hi, g_Xb_hi);
    cudaGetSymbolAddress((void**)&Xb_lo, g_Xb_lo);
    cudaGetSymbolAddress((void**)&Xt_hi, g_Xt_hi);
    cudaGetSymbolAddress((void**)&Xt_lo, g_Xt_lo);
    cudaGetSymbolAddress((void**)&Wwh, g_Ww_hi);
    cudaGetSymbolAddress((void**)&Wwl, g_Ww_lo);
    cudaGetSymbolAddress((void**)&Lwh, g_Lw_hi);
    cudaGetSymbolAddress((void**)&Lwl, g_Lw_lo);
    cudaGetSymbolAddress((void**)&Gh, g_G_hi);
    cudaGetSymbolAddress((void**)&Gl, g_G_lo);
    cudaGetSymbolAddress((void**)&Mh, g_M_hi);
    cudaGetSymbolAddress((void**)&Ml, g_M_lo);
    cudaGetSymbolAddress((void**)&Ph, g_P_hi);
    cudaGetSymbolAddress((void**)&Pl, g_P_lo);
    cudaGetSymbolAddress((void**)&Lbp, g_Lbp);
    cudaGetSymbolAddress((void**)&logits, g_logits);
    cudaGetSymbolAddress((void**)&Gp, g_Gp);
    cudaGetSymbolAddress((void**)&Mp, g_Mp);

    prep_x_k<<<dim3(KL / 64, KD / 64, KB), 256>>>(x);
    colsum_final_k<<<(KB * KD) / 256, 256>>>();
    prep_w_k<<<(KVP * KD) / 256, 256>>>(Ww, Lw, Lb);

    // G[b] = Xt*Xt^T (symmetric): 10 upper tile-pairs, K-split x3 -> 120 CTAs
    mma_gemm_k<<<dim3(10, 1, KB * G_NSPLIT), 256, DYN_SMEM>>>(
        Xt_hi, Xt_lo, (size_t)KD * KL, Xt_hi, Xt_lo, (size_t)KD * KL,
        KL, KL / 64, G_NSPLIT, nullptr, nullptr, Gp, 0, 128, nullptr, 4);
    reduce_G_k<<<(KB * KD * KD / 2) / 256, 256>>>();

    // M[b] = Ww*G[b]^T (512x512, K=512); K-split x2; rank-1 in reduce
    mma_gemm_k<<<dim3(4, 4, KB * M_NSPLIT), 256, DYN_SMEM>>>(
        Wwh, Wwl, 0, Gh, Gl, (size_t)KD * KD,
        KD, KD / 64, M_NSPLIT, nullptr, nullptr, Mp, (size_t)KD * KD, KD, nullptr, 3);
    reduce_M_k<<<(KB * KD * KD / 2) / 256, 256>>>(Wb);

    // P[b][v][k] = sum_n Lw[v][n] * M[b][k][n]  -> bf16 split
    mma_gemm_k<<<dim3(KVP / 128, KD / 128, KB), 256, DYN_SMEM>>>(
        Lwh, Lwl, 0, Mh, Ml, (size_t)KD * KD,
        KD, KD / 64, 1, Ph, Pl, nullptr, (size_t)KVP * KD, KD, nullptr, 0);

    // logits[b] = Xb * P^T + Lb  (4096x1024, K=512)
    mma_gemm_k<<<dim3(KL / 128, KVP / 128, KB), 256, DYN_SMEM>>>(
        Xb_hi, Xb_lo, (size_t)KL * KD, Ph, Pl, (size_t)KVP * KD,
        KD, KD / 64, 1, nullptr, nullptr, logits, (size_t)KL * KVP, KVP, Lbp, 2);

    logsoftmax_k<<<dim3(KL, KB), 256>>>(out);
}

// round 12
// speedup vs baseline: 1.2136x; 1.1965x over previous
#include <cuda_runtime.h>
#include <cuda_bf16.h>
#include <cuda_fp16.h>
#include <cstdint>

#define KL 4096
#define KB 4
#define KD 512
#define KV 1000
#define KVP 1024   // padded vocab

// ---------------------------------------------------------------------------
// PTX helpers (sm_80-compatible only: ldmatrix / mma.sync / cp.async)
// ---------------------------------------------------------------------------
__device__ __forceinline__ uint32_t smem_to_u32(const void* p) {
    uint32_t a;
    asm("{ .reg .u64 t; cvta.to.shared.u64 t, %1; cvt.u32.u64 %0, t; }" : "=r"(a) : "l"(p));
    return a;
}
__device__ __forceinline__ void cpasync16(uint32_t s, const void* g) {
    asm volatile("cp.async.cg.shared.global [%0], [%1], 16;" :: "r"(s), "l"(g));
}
__device__ __forceinline__ void cp_commit() {
    asm volatile("cp.async.commit_group;" ::: "memory");
}
template <int N>
__device__ __forceinline__ void cp_wait() {
    asm volatile("cp.async.wait_group %0;" :: "n"(N) : "memory");
}
__device__ __forceinline__ void ldmx4(uint32_t* r, uint32_t a) {
    asm volatile("ldmatrix.sync.aligned.m8n8.x4.shared.b16 {%0,%1,%2,%3}, [%4];"
                 : "=r"(r[0]), "=r"(r[1]), "=r"(r[2]), "=r"(r[3]) : "r"(a));
}
__device__ __forceinline__ void mma16816(float* d, const uint32_t* a, const uint32_t* b) {
    asm volatile(
        "mma.sync.aligned.m16n8k16.row.col.f32.bf16.bf16.f32 "
        "{%0,%1,%2,%3}, {%4,%5,%6,%7}, {%8,%9}, {%0,%1,%2,%3};"
        : "+f"(d[0]), "+f"(d[1]), "+f"(d[2]), "+f"(d[3])
        : "r"(a[0]), "r"(a[1]), "r"(a[2]), "r"(a[3]), "r"(b[0]), "r"(b[1]));
}
__device__ __forceinline__ void mma16816h(float* d, const uint32_t* a, const uint32_t* b) {
    asm volatile(
        "mma.sync.aligned.m16n8k16.row.col.f32.f16.f16.f32 "
        "{%0,%1,%2,%3}, {%4,%5,%6,%7}, {%8,%9}, {%0,%1,%2,%3};"
        : "+f"(d[0]), "+f"(d[1]), "+f"(d[2]), "+f"(d[3])
        : "r"(a[0]), "r"(a[1]), "r"(a[2]), "r"(a[3]), "r"(b[0]), "r"(b[1]));
}
#define SMEM_SWIZZLE_128B(o) ((o) ^ (((o) >> 3) & 0x70))

// symmetric-G tile pair tables (upper triangle of 4x4)
__constant__ int c_pi[10] = {0, 0, 0, 0, 1, 1, 1, 2, 2, 3};
__constant__ int c_pj[10] = {0, 1, 2, 3, 1, 2, 3, 2, 3, 3};
__constant__ int c_PT[16] = {0, 1, 2, 3,  0, 4, 5, 6,  0, 0, 7, 8,  0, 0, 0, 9};

// ---------------------------------------------------------------------------
// scratch (static device globals; no allocations)
// ---------------------------------------------------------------------------
#define G_NSPLIT 3   // 10 pairs * KB * 3 = 120 CTAs -> single wave on 148 SMs
#define M_NSPLIT 2
__device__ __align__(128) float g_part2[KB * KD * 64];   // colsum partials
__device__ __align__(128) float g_s[KB * KD];
__device__ __align__(128) __half g_Xb_hi[(size_t)KB * KL * KD], g_Xb_lo[(size_t)KB * KL * KD]; // fp16!
__device__ __align__(128) __nv_bfloat16 g_Xt_hi[(size_t)KB * KD * KL], g_Xt_lo[(size_t)KB * KD * KL];
__device__ __align__(128) __nv_bfloat16 g_Ww_hi[KD * KD], g_Ww_lo[KD * KD];
__device__ __align__(128) __nv_bfloat16 g_Lw_hi[KVP * KD], g_Lw_lo[KVP * KD];
__device__ __align__(128) float g_Lbp[KVP];
__device__ __align__(128) float g_Gp[(size_t)KB * G_NSPLIT * 10 * 128 * 128]; // 7.9 MB
__device__ __align__(128) float g_Mp[(size_t)M_NSPLIT * KB * KD * KD];        // 8 MB
__device__ __align__(128) __nv_bfloat16 g_G_hi[KB * KD * KD], g_G_lo[KB * KD * KD];
__device__ __align__(128) __nv_bfloat16 g_M_hi[KB * KD * KD], g_M_lo[KB * KD * KD];
__device__ __align__(128) __half g_P16[(size_t)KB * KVP * KD];                // fp16 single
__device__ __align__(128) float g_logits[(size_t)KB * KL * KVP];

__device__ __forceinline__ void split_f32(float v, __nv_bfloat16& h, __nv_bfloat16& l) {
    h = __float2bfloat16(v);
    l = __float2bfloat16(v - __bfloat162float(h));
}
__device__ __forceinline__ void split_f16(float v, __half& h, __half& l) {
    h = __float2half(v);
    l = __float2half(v - __half2float(h));
}

// ---------------------------------------------------------------------------
// prep_x: x -> Xb fp16 hi/lo (for logits GEMM), Xt bf16 hi/lo (for G), colsums
// ---------------------------------------------------------------------------
__global__ __launch_bounds__(256) void prep_x_k(const float* __restrict__ x) {
    __shared__ __nv_bfloat16 shi[64][65], slo[64][65];
    __shared__ float ssum[4][64];
    int b = blockIdx.z;
    int lblk = blockIdx.x;
    int l0 = lblk * 64, d0 = blockIdx.y * 64;
    int t = threadIdx.x;
    int c = t & 63, r4 = t >> 6;
    float ps = 0.f;
#pragma unroll 4
    for (int rr = 0; rr < 16; rr++) {
        int r = r4 * 16 + rr;
        float v = x[(size_t)(l0 + r) * (KB * KD) + b * KD + d0 + c];
        ps += v;
        size_t o = ((size_t)b * KL + (l0 + r)) * KD + d0 + c;
        __half fh, fl;
        split_f16(v, fh, fl);
        g_Xb_hi[o] = fh; g_Xb_lo[o] = fl;
        __nv_bfloat16 h, l;
        split_f32(v, h, l);
        shi[r][c] = h; slo[r][c] = l;
    }
    ssum[r4][c] = ps;
    __syncthreads();
#pragma unroll 4
    for (int rr = 0; rr < 16; rr++) {
        int r = r4 * 16 + rr;   // d index
        size_t o = ((size_t)b * KD + (d0 + r)) * KL + l0 + c;
        g_Xt_hi[o] = shi[c][r];
        g_Xt_lo[o] = slo[c][r];
    }
    if (t < 64) {
        float s = ssum[0][t] + ssum[1][t] + ssum[2][t] + ssum[3][t];
        g_part2[((size_t)b * KD + d0 + t) * 64 + lblk] = s;
    }
}

__global__ void colsum_final_k() {
    int idx = blockIdx.x * 256 + threadIdx.x;  // KB*KD
    float s = 0.f;
    const float* p = &g_part2[(size_t)idx * 64];
#pragma unroll
    for (int k = 0; k < 64; k++) s += p[k];
    g_s[idx] = s;
}

// ---------------------------------------------------------------------------
// prep_w (flat): split Ww; split Lw padded to 1024 rows; pad Lb
// ---------------------------------------------------------------------------
__global__ void prep_w_k(const float* __restrict__ Ww, const float* __restrict__ Lw,
                         const float* __restrict__ Lb) {
    int idx = blockIdx.x * 256 + threadIdx.x;   // over KVP*KD
    int row = idx / KD;
    float v2 = (row < KV) ? Lw[idx] : 0.f;
    __nv_bfloat16 h2, l2;
    split_f32(v2, h2, l2);
    g_Lw_hi[idx] = h2; g_Lw_lo[idx] = l2;
    if (idx < KD * KD) {
        __nv_bfloat16 h, l;
        split_f32(Ww[idx], h, l);
        g_Ww_hi[idx] = h; g_Ww_lo[idx] = l;
    }
    if (idx < KVP) g_Lbp[idx] = (idx < KV) ? Lb[idx] : 0.f;
}

// ---------------------------------------------------------------------------
// mma.sync bf16 split GEMM (R7-proven): C[m][n] = sum_k A[m][k]*B[n][k]
//   mode 0: write Chi/Clo bf16    mode 3: fp32 K-split partial
//   mode 4: symmetric-pair local tile    mode 5: write single fp16 (Chi cast)
// ---------------------------------------------------------------------------
#define TILE_BYTES 16384               // 128 rows x 128B (64 bf16)
#define STAGE_BYTES (4 * TILE_BYTES)   // Ah, Al, Bh, Bl
#define NSTAGE 3
#define DYN_SMEM (NSTAGE * STAGE_BYTES)  // 192 KB

__global__ __launch_bounds__(256, 1) void mma_gemm_k(
    const __nv_bfloat16* __restrict__ Ahi, const __nv_bfloat16* __restrict__ Alo, size_t sA,
    const __nv_bfloat16* __restrict__ Bhi, const __nv_bfloat16* __restrict__ Blo, size_t sB,
    int ldk, int NCtot, int nsplit,
    __nv_bfloat16* __restrict__ Chi, __nv_bfloat16* __restrict__ Clo,
    float* __restrict__ Cf, size_t sC, int ldc,
    const float* __restrict__ bias, int mode) {
    extern __shared__ __align__(1024) char smem[];
    uint32_t smb = smem_to_u32(smem);
    int tid = threadIdx.x;
    int wid = tid >> 5, lane = tid & 31;
    int b = blockIdx.z / nsplit, sp = blockIdx.z % nsplit;
    int basec = NCtot / nsplit, remc = NCtot % nsplit;
    int NC = basec + (sp < remc ? 1 : 0);
    int startc = sp * basec + (sp < remc ? sp : remc);
    int koff0 = startc << 6;
    int i0, j0;
    if (mode == 4) {
        i0 = c_pi[blockIdx.x] * 128;
        j0 = c_pj[blockIdx.x] * 128;
    } else {
        i0 = blockIdx.x * 128;
        j0 = blockIdx.y * 128;
    }
    int wm = (wid >> 2) * 64, wn = (wid & 3) * 32;

    const __nv_bfloat16* tiles[4] = {Ahi + sA * b, Alo + sA * b, Bhi + sB * b, Blo + sB * b};
    const int row0[4] = {i0, i0, j0, j0};

    int lr[4], lu[4];
#pragma unroll
    for (int it = 0; it < 4; it++) {
        int q = tid + it * 256;
        lr[it] = q >> 3;
        lu[it] = q & 7;
    }

    auto load_chunk = [&](int chunk) {
        uint32_t sbase = smb + (chunk % NSTAGE) * STAGE_BYTES;
        int koff = koff0 + (chunk << 6);
#pragma unroll
        for (int tile = 0; tile < 4; tile++) {
            const __nv_bfloat16* src = tiles[tile];
#pragma unroll
            for (int it = 0; it < 4; it++) {
                uint32_t boff = (uint32_t)(lr[it] * 128 + lu[it] * 16);
                uint32_t sw = SMEM_SWIZZLE_128B(boff);
                const void* g = src + (size_t)(row0[tile] + lr[it]) * ldk + koff + lu[it] * 8;
                cpasync16(sbase + tile * TILE_BYTES + sw, g);
            }
        }
        cp_commit();
    };

    float acc[4][4][4];
#pragma unroll
    for (int a = 0; a < 4; a++)
#pragma unroll
        for (int bb = 0; bb < 4; bb++)
#pragma unroll
            for (int c = 0; c < 4; c++) acc[a][bb][c] = 0.f;

    int arow = wm + (lane & 15);
    int akh16 = ((lane >> 4) & 1) * 16;
    int brow = wn + ((lane >> 4) & 1) * 8 + (lane & 7);
    int bkh16 = ((lane >> 3) & 1) * 16;

    load_chunk(0);
    if (NC > 1) load_chunk(1);

    for (int kc = 0; kc < NC; kc++) {
        if (kc < NC - 1) cp_wait<1>();
        else cp_wait<0>();
        __syncthreads();

        uint32_t sAh = smb + (kc % NSTAGE) * STAGE_BYTES;
        uint32_t sAl = sAh + TILE_BYTES;
        uint32_t sBh = sAh + 2 * TILE_BYTES;
        uint32_t sBl = sAh + 3 * TILE_BYTES;

#pragma unroll
        for (int kk = 0; kk < 4; kk++) {
            uint32_t ah[4][4], al[4][4], bh[2][4], bl[2][4];
#pragma unroll
            for (int mt = 0; mt < 4; mt++) {
                uint32_t o = (uint32_t)((arow + mt * 16) * 128 + kk * 32 + akh16);
                uint32_t sw = SMEM_SWIZZLE_128B(o);
                ldmx4(ah[mt], sAh + sw);
                ldmx4(al[mt], sAl + sw);
            }
#pragma unroll
            for (int np = 0; np < 2; np++) {
                uint32_t o = (uint32_t)((brow + np * 16) * 128 + kk * 32 + bkh16);
                uint32_t sw = SMEM_SWIZZLE_128B(o);
                ldmx4(bh[np], sBh + sw);
                ldmx4(bl[np], sBl + sw);
            }
#pragma unroll
            for (int mt = 0; mt < 4; mt++)
#pragma unroll
                for (int nt = 0; nt < 4; nt++) {
                    uint32_t* bfh = &bh[nt >> 1][(nt & 1) * 2];
                    uint32_t* bfl = &bl[nt >> 1][(nt & 1) * 2];
                    mma16816(acc[mt][nt], ah[mt], bfh);  // hi*hi
                    mma16816(acc[mt][nt], ah[mt], bfl);  // hi*lo
                    mma16816(acc[mt][nt], al[mt], bfh);  // lo*hi
                }
        }
        if (kc + 2 < NC) load_chunk(kc + 2);
    }

    // ---- epilogue ----
    float* loc = (mode == 4)
        ? Cf + ((size_t)blockIdx.z * gridDim.x + blockIdx.x) * (128 * 128)
        : nullptr;
#pragma unroll
    for (int mt = 0; mt < 4; mt++) {
#pragma unroll
        for (int half = 0; half < 2; half++) {
            int lrow = wm + mt * 16 + (lane >> 2) + half * 8;
            int grow = i0 + lrow;
#pragma unroll
            for (int nt = 0; nt < 4; nt++) {
                int lcol = wn + nt * 8 + (lane & 3) * 2;
                int gcol = j0 + lcol;
                float v0 = acc[mt][nt][half * 2 + 0];
                float v1 = acc[mt][nt][half * 2 + 1];
                if (mode == 4) {
                    *(float2*)&loc[lrow * 128 + lcol] = make_float2(v0, v1);
                } else if (mode == 3) {
                    *(float2*)&Cf[sC * blockIdx.z + (size_t)grow * ldc + gcol] = make_float2(v0, v1);
                } else if (mode == 5) {
                    __half2 hh;
                    hh.x = __float2half(v0);
                    hh.y = __float2half(v1);
                    *(__half2*)&((__half*)Chi)[sC * b + (size_t)grow * ldc + gcol] = hh;
                } else {
                    __nv_bfloat162 h2, l2;
                    split_f32(v0, h2.x, l2.x);
                    split_f32(v1, h2.y, l2.y);
                    *(__nv_bfloat162*)&Chi[sC * b + (size_t)grow * ldc + gcol] = h2;
                    *(__nv_bfloat162*)&Clo[sC * b + (size_t)grow * ldc + gcol] = l2;
                }
            }
        }
    }
}

// ---------------------------------------------------------------------------
// logits GEMM, fp16 2-product: logits[b][i][j] = sum_k Xb[i][k]*P[j][k] + Lb[j]
//   A = Xb fp16 hi+lo (exact split), B = P fp16 single.
//   3 tiles/chunk (48 KB), 3-stage, same R7 pipeline skeleton.
// ---------------------------------------------------------------------------
#define LTILE 16384
#define LSTAGE (3 * LTILE)
#define LNSTAGE 3
#define LDYN (LNSTAGE * LSTAGE)   // 147456

__global__ __launch_bounds__(256, 1) void logits_f16_k(
    const __half* __restrict__ Ahi, const __half* __restrict__ Alo,
    const __half* __restrict__ B16,
    const float* __restrict__ bias, float* __restrict__ Cf) {
    extern __shared__ __align__(1024) char smem[];
    uint32_t smb = smem_to_u32(smem);
    int tid = threadIdx.x;
    int wid = tid >> 5, lane = tid & 31;
    int b = blockIdx.z;
    int i0 = blockIdx.x * 128, j0 = blockIdx.y * 128;
    int wm = (wid >> 2) * 64, wn = (wid & 3) * 32;

    const __half* tiles[3] = {Ahi + (size_t)b * KL * KD, Alo + (size_t)b * KL * KD,
                              B16 + (size_t)b * KVP * KD};
    const int row0[3] = {i0, i0, j0};
    float* C0 = Cf + (size_t)b * KL * KVP;

    int lr[4], lu[4];
#pragma unroll
    for (int it = 0; it < 4; it++) {
        int q = tid + it * 256;
        lr[it] = q >> 3;
        lu[it] = q & 7;
    }

    auto load_chunk = [&](int chunk) {
        uint32_t sbase = smb + (chunk % LNSTAGE) * LSTAGE;
        int koff = chunk << 6;
#pragma unroll
        for (int tile = 0; tile < 3; tile++) {
            const __half* src = tiles[tile];
#pragma unroll
            for (int it = 0; it < 4; it++) {
                uint32_t boff = (uint32_t)(lr[it] * 128 + lu[it] * 16);
                uint32_t sw = SMEM_SWIZZLE_128B(boff);
                cpasync16(sbase + tile * LTILE + sw,
                          src + (size_t)(row0[tile] + lr[it]) * KD + koff + lu[it] * 8);
            }
        }
        cp_commit();
    };

    float acc[4][4][4];
#pragma unroll
    for (int a = 0; a < 4; a++)
#pragma unroll
        for (int bb = 0; bb < 4; bb++)
#pragma unroll
            for (int c = 0; c < 4; c++) acc[a][bb][c] = 0.f;

    int arow = wm + (lane & 15);
    int akh16 = ((lane >> 4) & 1) * 16;
    int brow = wn + ((lane >> 4) & 1) * 8 + (lane & 7);
    int bkh16 = ((lane >> 3) & 1) * 16;

    const int NC = KD / 64;   // 8
    load_chunk(0);
    load_chunk(1);

    for (int kc = 0; kc < NC; kc++) {
        if (kc < NC - 1) cp_wait<1>();
        else cp_wait<0>();
        __syncthreads();

        uint32_t sAh = smb + (kc % LNSTAGE) * LSTAGE;
        uint32_t sAl = sAh + LTILE;
        uint32_t sB = sAh + 2 * LTILE;

#pragma unroll
        for (int kk = 0; kk < 4; kk++) {
            uint32_t ah[4][4], al[4][4], bh[2][4];
#pragma unroll
            for (int mt = 0; mt < 4; mt++) {
                uint32_t o = (uint32_t)((arow + mt * 16) * 128 + kk * 32 + akh16);
                uint32_t sw = SMEM_SWIZZLE_128B(o);
                ldmx4(ah[mt], sAh + sw);
                ldmx4(al[mt], sAl + sw);
            }
#pragma unroll
            for (int np = 0; np < 2; np++) {
                uint32_t o = (uint32_t)((brow + np * 16) * 128 + kk * 32 + bkh16);
                uint32_t sw = SMEM_SWIZZLE_128B(o);
                ldmx4(bh[np], sB + sw);
            }
#pragma unroll
            for (int mt = 0; mt < 4; mt++)
#pragma unroll
                for (int nt = 0; nt < 4; nt++) {
                    uint32_t* bf = &bh[nt >> 1][(nt & 1) * 2];
                    mma16816h(acc[mt][nt], ah[mt], bf);  // hi * B
                    mma16816h(acc[mt][nt], al[mt], bf);  // lo * B
                }
        }
        if (kc + 2 < NC) load_chunk(kc + 2);
    }

    // ---- epilogue: fp32 + bias ----
#pragma unroll
    for (int mt = 0; mt < 4; mt++) {
#pragma unroll
        for (int half = 0; half < 2; half++) {
            int grow = i0 + wm + mt * 16 + (lane >> 2) + half * 8;
#pragma unroll
            for (int nt = 0; nt < 4; nt++) {
                int gcol = j0 + wn + nt * 8 + (lane & 3) * 2;
                float v0 = acc[mt][nt][half * 2 + 0] + bias[gcol];
                float v1 = acc[mt][nt][half * 2 + 1] + bias[gcol + 1];
                *(float2*)&C0[(size_t)grow * KVP + gcol] = make_float2(v0, v1);
            }
        }
    }
}

// ---------------------------------------------------------------------------
// reduce symmetric-G partials (10 tile-pairs x G_NSPLIT) -> full G hi/lo bf16
// ---------------------------------------------------------------------------
__global__ void reduce_G_k() {
    size_t idx = ((size_t)blockIdx.x * 256 + threadIdx.x) * 2;  // KB*KD*KD elems
    const size_t per = (size_t)KD * KD;
    int b = (int)(idx / per);
    size_t rem = idx % per;
    int i = (int)(rem / KD), j = (int)(rem % KD);
    int ti = i >> 7, tj = j >> 7;
    float s0 = 0.f, s1 = 0.f;
    if (ti <= tj) {
        int p = c_PT[ti * 4 + tj];
        size_t off = (size_t)((i & 127) * 128 + (j & 127));
        for (int sp = 0; sp < G_NSPLIT; sp++) {
            const float* base = g_Gp + ((size_t)(b * G_NSPLIT + sp) * 10 + p) * (128 * 128);
            s0 += base[off];
            s1 += base[off + 1];
        }
    } else {
        int p = c_PT[tj * 4 + ti];
        size_t off = (size_t)((j & 127) * 128 + (i & 127));
        for (int sp = 0; sp < G_NSPLIT; sp++) {
            const float* base = g_Gp + ((size_t)(b * G_NSPLIT + sp) * 10 + p) * (128 * 128);
            s0 += base[off];
            s1 += base[off + 128];   // G[i][j+1] = mirrored tile, next row
        }
    }
    __nv_bfloat162 h2, l2;
    split_f32(s0, h2.x, l2.x);
    split_f32(s1, h2.y, l2.y);
    *(__nv_bfloat162*)&g_G_hi[idx] = h2;
    *(__nv_bfloat162*)&g_G_lo[idx] = l2;
}

// ---------------------------------------------------------------------------
// reduce M K-split partials + rank-1 Wb[i]*s[b][j] -> hi/lo bf16
// ---------------------------------------------------------------------------
__global__ void reduce_M_k(const float* __restrict__ Wb) {
    size_t idx = ((size_t)blockIdx.x * 256 + threadIdx.x) * 2;
    const size_t per = (size_t)KD * KD;
    int b = (int)(idx / per);
    size_t rem = idx % per;
    int i = (int)(rem / KD), j = (int)(rem % KD);
    float s0 = 0.f, s1 = 0.f;
    for (int sp = 0; sp < M_NSPLIT; sp++) {
        const float* p = g_Mp + ((size_t)(b * M_NSPLIT + sp)) * per + rem;
        s0 += p[0];
        s1 += p[1];
    }
    float u = Wb[i];
    s0 += u * g_s[b * KD + j];
    s1 += u * g_s[b * KD + j + 1];
    __nv_bfloat162 h2, l2;
    split_f32(s0, h2.x, l2.x);
    split_f32(s1, h2.y, l2.y);
    *(__nv_bfloat162*)&g_M_hi[idx] = h2;
    *(__nv_bfloat162*)&g_M_lo[idx] = l2;
}

// ---------------------------------------------------------------------------
// log_softmax over V + permute (B,L,V)->(L,B,V)
// ---------------------------------------------------------------------------
__global__ void logsoftmax_k(float* __restrict__ out) {
    int l = blockIdx.x, b = blockIdx.y;
    const float* row = g_logits + (size_t)(b * KL + l) * KVP;
    float* orow = out + (size_t)(l * KB + b) * KV;
    __shared__ float sred[8];
    int t = threadIdx.x;
    int wid = t >> 5, lane = t & 31;
    bool act = t < (KV / 4);
    float4 v = act ? *(const float4*)&row[t * 4]
                   : make_float4(-3.4e38f, -3.4e38f, -3.4e38f, -3.4e38f);
    float m = fmaxf(fmaxf(v.x, v.y), fmaxf(v.z, v.w));
#pragma unroll
    for (int s = 16; s >= 1; s >>= 1) m = fmaxf(m, __shfl_xor_sync(0xffffffffu, m, s));
    if (lane == 0) sred[wid] = m;
    __syncthreads();
    float m8 = (lane < 8) ? sred[lane] : -3.4e38f;
#pragma unroll
    for (int s = 4; s >= 1; s >>= 1) m8 = fmaxf(m8, __shfl_xor_sync(0xffffffffu, m8, s));
    float vmax = __shfl_sync(0xffffffffu, m8, 0);

    float e = act ? (__expf(v.x - vmax) + __expf(v.y - vmax) +
                     __expf(v.z - vmax) + __expf(v.w - vmax))
                  : 0.f;
#pragma unroll
    for (int s = 16; s >= 1; s >>= 1) e += __shfl_xor_sync(0xffffffffu, e, s);
    __syncthreads();
    if (lane == 0) sred[wid] = e;
    __syncthreads();
    float e8 = (lane < 8) ? sred[lane] : 0.f;
#pragma unroll
    for (int s = 4; s >= 1; s >>= 1) e8 += __shfl_xor_sync(0xffffffffu, e8, s);
    float denom = vmax + logf(__shfl_sync(0xffffffffu, e8, 0));

    if (act) {
        float4 o;
        o.x = v.x - denom; o.y = v.y - denom;
        o.z = v.z - denom; o.w = v.w - denom;
        *(float4*)&orow[t * 4] = o;
    }
}

// ---------------------------------------------------------------------------
extern "C" void kernel_launch(void* const* d_in, const int* in_sizes, int n_in,
                              void* d_out, int out_size) {
    (void)in_sizes; (void)n_in; (void)out_size;
    const float* x  = (const float*)d_in[0];
    const float* Ww = (const float*)d_in[1];
    const float* Wb = (const float*)d_in[2];
    const float* Lw = (const float*)d_in[3];
    const float* Lb = (const float*)d_in[4];
    float* out = (float*)d_out;

    static bool attr_set = false;
    if (!attr_set) {
        cudaFuncSetAttribute(mma_gemm_k, cudaFuncAttributeMaxDynamicSharedMemorySize, DYN_SMEM);
        cudaFuncSetAttribute(logits_f16_k, cudaFuncAttributeMaxDynamicSharedMemorySize, LDYN);
        attr_set = true;
    }

    __half *Xb_hi, *Xb_lo, *P16;
    __nv_bfloat16 *Xt_hi, *Xt_lo, *Wwh, *Wwl, *Lwh, *Lwl;
    __nv_bfloat16 *Gh, *Gl, *Mh, *Ml;
    float *Lbp, *logits, *Gp, *Mp;
    cudaGetSymbolAddress((void**)&Xb_hi, g_Xb_hi);
    cudaGetSymbolAddress((void**)&Xb_lo, g_Xb_lo);
    cudaGetSymbolAddress((void**)&Xt_hi, g_Xt_hi);
    cudaGetSymbolAddress((void**)&Xt_lo, g_Xt_lo);
    cudaGetSymbolAddress((void**)&Wwh, g_Ww_hi);
    cudaGetSymbolAddress((void**)&Wwl, g_Ww_lo);
    cudaGetSymbolAddress((void**)&Lwh, g_Lw_hi);
    cudaGetSymbolAddress((void**)&Lwl, g_Lw_lo);
    cudaGetSymbolAddress((void**)&Gh, g_G_hi);
    cudaGetSymbolAddress((void**)&Gl, g_G_lo);
    cudaGetSymbolAddress((void**)&Mh, g_M_hi);
    cudaGetSymbolAddress((void**)&Ml, g_M_lo);
    cudaGetSymbolAddress((void**)&P16, g_P16);
    cudaGetSymbolAddress((void**)&Lbp, g_Lbp);
    cudaGetSymbolAddress((void**)&logits, g_logits);
    cudaGetSymbolAddress((void**)&Gp, g_Gp);
    cudaGetSymbolAddress((void**)&Mp, g_Mp);

    prep_x_k<<<dim3(KL / 64, KD / 64, KB), 256>>>(x);
    colsum_final_k<<<(KB * KD) / 256, 256>>>();
    prep_w_k<<<(KVP * KD) / 256, 256>>>(Ww, Lw, Lb);

    // G[b] = Xt*Xt^T (symmetric): 10 upper tile-pairs, K-split x3 -> 120 CTAs
    mma_gemm_k<<<dim3(10, 1, KB * G_NSPLIT), 256, DYN_SMEM>>>(
        Xt_hi, Xt_lo, (size_t)KD * KL, Xt_hi, Xt_lo, (size_t)KD * KL,
        KL, KL / 64, G_NSPLIT, nullptr, nullptr, Gp, 0, 128, nullptr, 4);
    reduce_G_k<<<(KB * KD * KD / 2) / 256, 256>>>();

    // M[b] = Ww*G[b]^T (512x512, K=512); K-split x2; rank-1 in reduce
    mma_gemm_k<<<dim3(4, 4, KB * M_NSPLIT), 256, DYN_SMEM>>>(
        Wwh, Wwl, 0, Gh, Gl, (size_t)KD * KD,
        KD, KD / 64, M_NSPLIT, nullptr, nullptr, Mp, (size_t)KD * KD, KD, nullptr, 3);
    reduce_M_k<<<(KB * KD * KD / 2) / 256, 256>>>(Wb);

    // P[b][v][k] = sum_n Lw[v][n] * M[b][k][n] -> single fp16 (mode 5)
    mma_gemm_k<<<dim3(KVP / 128, KD / 128, KB), 256, DYN_SMEM>>>(
        Lwh, Lwl, 0, Mh, Ml, (size_t)KD * KD,
        KD, KD / 64, 1, (__nv_bfloat16*)P16, nullptr, nullptr,
        (size_t)KVP * KD, KD, nullptr, 5);

    // logits[b] = Xb * P^T + Lb  (fp16 2-product, 4096x1024, K=512)
    logits_f16_k<<<dim3(KL / 128, KVP / 128, KB), 256, LDYN>>>(
        Xb_hi, Xb_lo, P16, Lbp, logits);

    logsoftmax_k<<<dim3(KL, KB), 256>>>(out);
}

// round 13
// speedup vs baseline: 1.2701x; 1.0465x over previous
#include <cuda_runtime.h>
#include <cuda_bf16.h>
#include <cuda_fp16.h>
#include <cstdint>

#define KL 4096
#define KB 4
#define KD 512
#define KV 1000
#define KVP 1024   // padded vocab

// ---------------------------------------------------------------------------
// PTX helpers (sm_80-compatible only: ldmatrix / mma.sync / cp.async)
// ---------------------------------------------------------------------------
__device__ __forceinline__ uint32_t smem_to_u32(const void* p) {
    uint32_t a;
    asm("{ .reg .u64 t; cvta.to.shared.u64 t, %1; cvt.u32.u64 %0, t; }" : "=r"(a) : "l"(p));
    return a;
}
__device__ __forceinline__ void cpasync16(uint32_t s, const void* g) {
    asm volatile("cp.async.cg.shared.global [%0], [%1], 16;" :: "r"(s), "l"(g));
}
__device__ __forceinline__ void cp_commit() {
    asm volatile("cp.async.commit_group;" ::: "memory");
}
template <int N>
__device__ __forceinline__ void cp_wait() {
    asm volatile("cp.async.wait_group %0;" :: "n"(N) : "memory");
}
__device__ __forceinline__ void ldmx4(uint32_t* r, uint32_t a) {
    asm volatile("ldmatrix.sync.aligned.m8n8.x4.shared.b16 {%0,%1,%2,%3}, [%4];"
                 : "=r"(r[0]), "=r"(r[1]), "=r"(r[2]), "=r"(r[3]) : "r"(a));
}
__device__ __forceinline__ void mma16816(float* d, const uint32_t* a, const uint32_t* b) {
    asm volatile(
        "mma.sync.aligned.m16n8k16.row.col.f32.bf16.bf16.f32 "
        "{%0,%1,%2,%3}, {%4,%5,%6,%7}, {%8,%9}, {%0,%1,%2,%3};"
        : "+f"(d[0]), "+f"(d[1]), "+f"(d[2]), "+f"(d[3])
        : "r"(a[0]), "r"(a[1]), "r"(a[2]), "r"(a[3]), "r"(b[0]), "r"(b[1]));
}
__device__ __forceinline__ void mma16816h(float* d, const uint32_t* a, const uint32_t* b) {
    asm volatile(
        "mma.sync.aligned.m16n8k16.row.col.f32.f16.f16.f32 "
        "{%0,%1,%2,%3}, {%4,%5,%6,%7}, {%8,%9}, {%0,%1,%2,%3};"
        : "+f"(d[0]), "+f"(d[1]), "+f"(d[2]), "+f"(d[3])
        : "r"(a[0]), "r"(a[1]), "r"(a[2]), "r"(a[3]), "r"(b[0]), "r"(b[1]));
}
#define SMEM_SWIZZLE_128B(o) ((o) ^ (((o) >> 3) & 0x70))

// symmetric-G tile pair tables (upper triangle of 4x4)
__constant__ int c_pi[10] = {0, 0, 0, 0, 1, 1, 1, 2, 2, 3};
__constant__ int c_pj[10] = {0, 1, 2, 3, 1, 2, 3, 2, 3, 3};
__constant__ int c_PT[16] = {0, 1, 2, 3,  0, 4, 5, 6,  0, 0, 7, 8,  0, 0, 0, 9};

// ---------------------------------------------------------------------------
// scratch (static device globals; no allocations)
// ---------------------------------------------------------------------------
#define G_NSPLIT 3   // 10 pairs * KB * 3 = 120 CTAs -> single wave on 148 SMs
#define M_NSPLIT 2
__device__ __align__(128) float g_part2[KB * KD * 64];   // colsum partials
__device__ __align__(128) float g_s[KB * KD];
__device__ __align__(128) __half g_Xb_hi[(size_t)KB * KL * KD], g_Xb_lo[(size_t)KB * KL * KD];
__device__ __align__(128) __half g_Xt_hi[(size_t)KB * KD * KL], g_Xt_lo[(size_t)KB * KD * KL]; // fp16 now
__device__ __align__(128) __nv_bfloat16 g_Ww_hi[KD * KD], g_Ww_lo[KD * KD];
__device__ __align__(128) __nv_bfloat16 g_Lw_hi[KVP * KD], g_Lw_lo[KVP * KD];
__device__ __align__(128) float g_Lbp[KVP];
__device__ __align__(128) float g_Gp[(size_t)KB * G_NSPLIT * 10 * 128 * 128]; // 7.9 MB
__device__ __align__(128) float g_Mp[(size_t)M_NSPLIT * KB * KD * KD];        // 8 MB
__device__ __align__(128) __nv_bfloat16 g_G_hi[KB * KD * KD], g_G_lo[KB * KD * KD];
__device__ __align__(128) __nv_bfloat16 g_M_hi[KB * KD * KD], g_M_lo[KB * KD * KD];
__device__ __align__(128) __half g_P16[(size_t)KB * KVP * KD];                // fp16 single
__device__ __align__(128) float g_logits[(size_t)KB * KL * KVP];

__device__ __forceinline__ void split_f32(float v, __nv_bfloat16& h, __nv_bfloat16& l) {
    h = __float2bfloat16(v);
    l = __float2bfloat16(v - __bfloat162float(h));
}
__device__ __forceinline__ void split_f16(float v, __half& h, __half& l) {
    h = __float2half(v);
    l = __float2half(v - __half2float(h));
}

// ---------------------------------------------------------------------------
// prep_x: x -> Xb fp16 hi/lo (logits A), Xt fp16 hi/lo (G operands), colsums
// ---------------------------------------------------------------------------
__global__ __launch_bounds__(256) void prep_x_k(const float* __restrict__ x) {
    __shared__ __half shi[64][65], slo[64][65];
    __shared__ float ssum[4][64];
    int b = blockIdx.z;
    int lblk = blockIdx.x;
    int l0 = lblk * 64, d0 = blockIdx.y * 64;
    int t = threadIdx.x;
    int c = t & 63, r4 = t >> 6;
    float ps = 0.f;
#pragma unroll 4
    for (int rr = 0; rr < 16; rr++) {
        int r = r4 * 16 + rr;
        float v = x[(size_t)(l0 + r) * (KB * KD) + b * KD + d0 + c];
        ps += v;
        size_t o = ((size_t)b * KL + (l0 + r)) * KD + d0 + c;
        __half fh, fl;
        split_f16(v, fh, fl);
        g_Xb_hi[o] = fh; g_Xb_lo[o] = fl;
        shi[r][c] = fh; slo[r][c] = fl;
    }
    ssum[r4][c] = ps;
    __syncthreads();
#pragma unroll 4
    for (int rr = 0; rr < 16; rr++) {
        int r = r4 * 16 + rr;   // d index
        size_t o = ((size_t)b * KD + (d0 + r)) * KL + l0 + c;
        g_Xt_hi[o] = shi[c][r];
        g_Xt_lo[o] = slo[c][r];
    }
    if (t < 64) {
        float s = ssum[0][t] + ssum[1][t] + ssum[2][t] + ssum[3][t];
        g_part2[((size_t)b * KD + d0 + t) * 64 + lblk] = s;
    }
}

__global__ void colsum_final_k() {
    int idx = blockIdx.x * 256 + threadIdx.x;  // KB*KD
    float s = 0.f;
    const float* p = &g_part2[(size_t)idx * 64];
#pragma unroll
    for (int k = 0; k < 64; k++) s += p[k];
    g_s[idx] = s;
}

// ---------------------------------------------------------------------------
// prep_w (flat): split Ww; split Lw padded to 1024 rows; pad Lb
// ---------------------------------------------------------------------------
__global__ void prep_w_k(const float* __restrict__ Ww, const float* __restrict__ Lw,
                         const float* __restrict__ Lb) {
    int idx = blockIdx.x * 256 + threadIdx.x;   // over KVP*KD
    int row = idx / KD;
    float v2 = (row < KV) ? Lw[idx] : 0.f;
    __nv_bfloat16 h2, l2;
    split_f32(v2, h2, l2);
    g_Lw_hi[idx] = h2; g_Lw_lo[idx] = l2;
    if (idx < KD * KD) {
        __nv_bfloat16 h, l;
        split_f32(Ww[idx], h, l);
        g_Ww_hi[idx] = h; g_Ww_lo[idx] = l;
    }
    if (idx < KVP) g_Lbp[idx] = (idx < KV) ? Lb[idx] : 0.f;
}

// ---------------------------------------------------------------------------
// mma.sync bf16 split GEMM (R7-proven): C[m][n] = sum_k A[m][k]*B[n][k]
//   mode 0: write Chi/Clo bf16    mode 3: fp32 K-split partial
//   mode 5: write single fp16 (Chi cast)
// ---------------------------------------------------------------------------
#define TILE_BYTES 16384               // 128 rows x 128B (64 bf16)
#define STAGE_BYTES (4 * TILE_BYTES)   // Ah, Al, Bh, Bl
#define NSTAGE 3
#define DYN_SMEM (NSTAGE * STAGE_BYTES)  // 192 KB

__global__ __launch_bounds__(256, 1) void mma_gemm_k(
    const __nv_bfloat16* __restrict__ Ahi, const __nv_bfloat16* __restrict__ Alo, size_t sA,
    const __nv_bfloat16* __restrict__ Bhi, const __nv_bfloat16* __restrict__ Blo, size_t sB,
    int ldk, int NCtot, int nsplit,
    __nv_bfloat16* __restrict__ Chi, __nv_bfloat16* __restrict__ Clo,
    float* __restrict__ Cf, size_t sC, int ldc,
    const float* __restrict__ bias, int mode) {
    extern __shared__ __align__(1024) char smem[];
    uint32_t smb = smem_to_u32(smem);
    int tid = threadIdx.x;
    int wid = tid >> 5, lane = tid & 31;
    int b = blockIdx.z / nsplit, sp = blockIdx.z % nsplit;
    int basec = NCtot / nsplit, remc = NCtot % nsplit;
    int NC = basec + (sp < remc ? 1 : 0);
    int startc = sp * basec + (sp < remc ? sp : remc);
    int koff0 = startc << 6;
    int i0 = blockIdx.x * 128, j0 = blockIdx.y * 128;
    int wm = (wid >> 2) * 64, wn = (wid & 3) * 32;

    const __nv_bfloat16* tiles[4] = {Ahi + sA * b, Alo + sA * b, Bhi + sB * b, Blo + sB * b};
    const int row0[4] = {i0, i0, j0, j0};

    int lr[4], lu[4];
#pragma unroll
    for (int it = 0; it < 4; it++) {
        int q = tid + it * 256;
        lr[it] = q >> 3;
        lu[it] = q & 7;
    }

    auto load_chunk = [&](int chunk) {
        uint32_t sbase = smb + (chunk % NSTAGE) * STAGE_BYTES;
        int koff = koff0 + (chunk << 6);
#pragma unroll
        for (int tile = 0; tile < 4; tile++) {
            const __nv_bfloat16* src = tiles[tile];
#pragma unroll
            for (int it = 0; it < 4; it++) {
                uint32_t boff = (uint32_t)(lr[it] * 128 + lu[it] * 16);
                uint32_t sw = SMEM_SWIZZLE_128B(boff);
                const void* g = src + (size_t)(row0[tile] + lr[it]) * ldk + koff + lu[it] * 8;
                cpasync16(sbase + tile * TILE_BYTES + sw, g);
            }
        }
        cp_commit();
    };

    float acc[4][4][4];
#pragma unroll
    for (int a = 0; a < 4; a++)
#pragma unroll
        for (int bb = 0; bb < 4; bb++)
#pragma unroll
            for (int c = 0; c < 4; c++) acc[a][bb][c] = 0.f;

    int arow = wm + (lane & 15);
    int akh16 = ((lane >> 4) & 1) * 16;
    int brow = wn + ((lane >> 4) & 1) * 8 + (lane & 7);
    int bkh16 = ((lane >> 3) & 1) * 16;

    load_chunk(0);
    if (NC > 1) load_chunk(1);

    for (int kc = 0; kc < NC; kc++) {
        if (kc < NC - 1) cp_wait<1>();
        else cp_wait<0>();
        __syncthreads();

        uint32_t sAh = smb + (kc % NSTAGE) * STAGE_BYTES;
        uint32_t sAl = sAh + TILE_BYTES;
        uint32_t sBh = sAh + 2 * TILE_BYTES;
        uint32_t sBl = sAh + 3 * TILE_BYTES;

#pragma unroll
        for (int kk = 0; kk < 4; kk++) {
            uint32_t ah[4][4], al[4][4], bh[2][4], bl[2][4];
#pragma unroll
            for (int mt = 0; mt < 4; mt++) {
                uint32_t o = (uint32_t)((arow + mt * 16) * 128 + kk * 32 + akh16);
                uint32_t sw = SMEM_SWIZZLE_128B(o);
                ldmx4(ah[mt], sAh + sw);
                ldmx4(al[mt], sAl + sw);
            }
#pragma unroll
            for (int np = 0; np < 2; np++) {
                uint32_t o = (uint32_t)((brow + np * 16) * 128 + kk * 32 + bkh16);
                uint32_t sw = SMEM_SWIZZLE_128B(o);
                ldmx4(bh[np], sBh + sw);
                ldmx4(bl[np], sBl + sw);
            }
#pragma unroll
            for (int mt = 0; mt < 4; mt++)
#pragma unroll
                for (int nt = 0; nt < 4; nt++) {
                    uint32_t* bfh = &bh[nt >> 1][(nt & 1) * 2];
                    uint32_t* bfl = &bl[nt >> 1][(nt & 1) * 2];
                    mma16816(acc[mt][nt], ah[mt], bfh);  // hi*hi
                    mma16816(acc[mt][nt], ah[mt], bfl);  // hi*lo
                    mma16816(acc[mt][nt], al[mt], bfh);  // lo*hi
                }
        }
        if (kc + 2 < NC) load_chunk(kc + 2);
    }

    // ---- epilogue ----
#pragma unroll
    for (int mt = 0; mt < 4; mt++) {
#pragma unroll
        for (int half = 0; half < 2; half++) {
            int lrow = wm + mt * 16 + (lane >> 2) + half * 8;
            int grow = i0 + lrow;
#pragma unroll
            for (int nt = 0; nt < 4; nt++) {
                int lcol = wn + nt * 8 + (lane & 3) * 2;
                int gcol = j0 + lcol;
                float v0 = acc[mt][nt][half * 2 + 0];
                float v1 = acc[mt][nt][half * 2 + 1];
                if (mode == 3) {
                    *(float2*)&Cf[sC * blockIdx.z + (size_t)grow * ldc + gcol] = make_float2(v0, v1);
                } else if (mode == 5) {
                    __half2 hh;
                    hh.x = __float2half(v0);
                    hh.y = __float2half(v1);
                    *(__half2*)&((__half*)Chi)[sC * b + (size_t)grow * ldc + gcol] = hh;
                } else {
                    __nv_bfloat162 h2, l2;
                    split_f32(v0, h2.x, l2.x);
                    split_f32(v1, h2.y, l2.y);
                    *(__nv_bfloat162*)&Chi[sC * b + (size_t)grow * ldc + gcol] = h2;
                    *(__nv_bfloat162*)&Clo[sC * b + (size_t)grow * ldc + gcol] = l2;
                }
            }
        }
    }
}

// ---------------------------------------------------------------------------
// f16 2-product GEMM: C[m][n] = sum_k (Ah+Al)[m][k] * B16[n][k]
//   3 tiles/chunk (Ah, Al, B16), 3-stage cp.async, R7 pipeline skeleton.
//   mode 2: fp32 + bias out at batch b (logits)
//   mode 4: symmetric pairs (c_pi/c_pj), K-split, fp32 local 128x128 tile (G)
// ---------------------------------------------------------------------------
#define LTILE 16384
#define LSTAGE (3 * LTILE)
#define LNSTAGE 3
#define LDYN (LNSTAGE * LSTAGE)   // 147456

__global__ __launch_bounds__(256, 1) void f16_gemm_k(
    const __half* __restrict__ Ahi, const __half* __restrict__ Alo, size_t sA,
    const __half* __restrict__ B16, size_t sB,
    int ldk, int NCtot, int nsplit,
    float* __restrict__ Cf, size_t sC, int ldc,
    const float* __restrict__ bias, int mode) {
    extern __shared__ __align__(1024) char smem[];
    uint32_t smb = smem_to_u32(smem);
    int tid = threadIdx.x;
    int wid = tid >> 5, lane = tid & 31;
    int b = blockIdx.z / nsplit, sp = blockIdx.z % nsplit;
    int basec = NCtot / nsplit, remc = NCtot % nsplit;
    int NC = basec + (sp < remc ? 1 : 0);
    int startc = sp * basec + (sp < remc ? sp : remc);
    int koff0 = startc << 6;
    int i0, j0;
    if (mode == 4) {
        i0 = c_pi[blockIdx.x] * 128;
        j0 = c_pj[blockIdx.x] * 128;
    } else {
        i0 = blockIdx.x * 128;
        j0 = blockIdx.y * 128;
    }
    int wm = (wid >> 2) * 64, wn = (wid & 3) * 32;

    const __half* tiles[3] = {Ahi + sA * b, Alo + sA * b, B16 + sB * b};
    const int row0[3] = {i0, i0, j0};

    int lr[4], lu[4];
#pragma unroll
    for (int it = 0; it < 4; it++) {
        int q = tid + it * 256;
        lr[it] = q >> 3;
        lu[it] = q & 7;
    }

    auto load_chunk = [&](int chunk) {
        uint32_t sbase = smb + (chunk % LNSTAGE) * LSTAGE;
        int koff = koff0 + (chunk << 6);
#pragma unroll
        for (int tile = 0; tile < 3; tile++) {
            const __half* src = tiles[tile];
#pragma unroll
            for (int it = 0; it < 4; it++) {
                uint32_t boff = (uint32_t)(lr[it] * 128 + lu[it] * 16);
                uint32_t sw = SMEM_SWIZZLE_128B(boff);
                cpasync16(sbase + tile * LTILE + sw,
                          src + (size_t)(row0[tile] + lr[it]) * ldk + koff + lu[it] * 8);
            }
        }
        cp_commit();
    };

    float acc[4][4][4];
#pragma unroll
    for (int a = 0; a < 4; a++)
#pragma unroll
        for (int bb = 0; bb < 4; bb++)
#pragma unroll
            for (int c = 0; c < 4; c++) acc[a][bb][c] = 0.f;

    int arow = wm + (lane & 15);
    int akh16 = ((lane >> 4) & 1) * 16;
    int brow = wn + ((lane >> 4) & 1) * 8 + (lane & 7);
    int bkh16 = ((lane >> 3) & 1) * 16;

    load_chunk(0);
    if (NC > 1) load_chunk(1);

    for (int kc = 0; kc < NC; kc++) {
        if (kc < NC - 1) cp_wait<1>();
        else cp_wait<0>();
        __syncthreads();

        uint32_t sAh = smb + (kc % LNSTAGE) * LSTAGE;
        uint32_t sAl = sAh + LTILE;
        uint32_t sB_ = sAh + 2 * LTILE;

#pragma unroll
        for (int kk = 0; kk < 4; kk++) {
            uint32_t ah[4][4], al[4][4], bh[2][4];
#pragma unroll
            for (int mt = 0; mt < 4; mt++) {
                uint32_t o = (uint32_t)((arow + mt * 16) * 128 + kk * 32 + akh16);
                uint32_t sw = SMEM_SWIZZLE_128B(o);
                ldmx4(ah[mt], sAh + sw);
                ldmx4(al[mt], sAl + sw);
            }
#pragma unroll
            for (int np = 0; np < 2; np++) {
                uint32_t o = (uint32_t)((brow + np * 16) * 128 + kk * 32 + bkh16);
                uint32_t sw = SMEM_SWIZZLE_128B(o);
                ldmx4(bh[np], sB_ + sw);
            }
#pragma unroll
            for (int mt = 0; mt < 4; mt++)
#pragma unroll
                for (int nt = 0; nt < 4; nt++) {
                    uint32_t* bf = &bh[nt >> 1][(nt & 1) * 2];
                    mma16816h(acc[mt][nt], ah[mt], bf);  // hi * B
                    mma16816h(acc[mt][nt], al[mt], bf);  // lo * B
                }
        }
        if (kc + 2 < NC) load_chunk(kc + 2);
    }

    // ---- epilogue ----
    float* loc = (mode == 4)
        ? Cf + ((size_t)blockIdx.z * gridDim.x + blockIdx.x) * (128 * 128)
        : nullptr;
#pragma unroll
    for (int mt = 0; mt < 4; mt++) {
#pragma unroll
        for (int half = 0; half < 2; half++) {
            int lrow = wm + mt * 16 + (lane >> 2) + half * 8;
            int grow = i0 + lrow;
#pragma unroll
            for (int nt = 0; nt < 4; nt++) {
                int lcol = wn + nt * 8 + (lane & 3) * 2;
                int gcol = j0 + lcol;
                float v0 = acc[mt][nt][half * 2 + 0];
                float v1 = acc[mt][nt][half * 2 + 1];
                if (mode == 4) {
                    *(float2*)&loc[lrow * 128 + lcol] = make_float2(v0, v1);
                } else {
                    float2 f2 = make_float2(v0 + bias[gcol], v1 + bias[gcol + 1]);
                    *(float2*)&Cf[sC * b + (size_t)grow * ldc + gcol] = f2;
                }
            }
        }
    }
}

// ---------------------------------------------------------------------------
// reduce symmetric-G partials (10 tile-pairs x G_NSPLIT) -> full G hi/lo bf16
// ---------------------------------------------------------------------------
__global__ void reduce_G_k() {
    size_t idx = ((size_t)blockIdx.x * 256 + threadIdx.x) * 2;  // KB*KD*KD elems
    const size_t per = (size_t)KD * KD;
    int b = (int)(idx / per);
    size_t rem = idx % per;
    int i = (int)(rem / KD), j = (int)(rem % KD);
    int ti = i >> 7, tj = j >> 7;
    float s0 = 0.f, s1 = 0.f;
    if (ti <= tj) {
        int p = c_PT[ti * 4 + tj];
        size_t off = (size_t)((i & 127) * 128 + (j & 127));
        for (int sp = 0; sp < G_NSPLIT; sp++) {
            const float* base = g_Gp + ((size_t)(b * G_NSPLIT + sp) * 10 + p) * (128 * 128);
            s0 += base[off];
            s1 += base[off + 1];
        }
    } else {
        int p = c_PT[tj * 4 + ti];
        size_t off = (size_t)((j & 127) * 128 + (i & 127));
        for (int sp = 0; sp < G_NSPLIT; sp++) {
            const float* base = g_Gp + ((size_t)(b * G_NSPLIT + sp) * 10 + p) * (128 * 128);
            s0 += base[off];
            s1 += base[off + 128];   // G[i][j+1] = mirrored tile, next row
        }
    }
    __nv_bfloat162 h2, l2;
    split_f32(s0, h2.x, l2.x);
    split_f32(s1, h2.y, l2.y);
    *(__nv_bfloat162*)&g_G_hi[idx] = h2;
    *(__nv_bfloat162*)&g_G_lo[idx] = l2;
}

// ---------------------------------------------------------------------------
// reduce M K-split partials + rank-1 Wb[i]*s[b][j] -> hi/lo bf16
// ---------------------------------------------------------------------------
__global__ void reduce_M_k(const float* __restrict__ Wb) {
    size_t idx = ((size_t)blockIdx.x * 256 + threadIdx.x) * 2;
    const size_t per = (size_t)KD * KD;
    int b = (int)(idx / per);
    size_t rem = idx % per;
    int i = (int)(rem / KD), j = (int)(rem % KD);
    float s0 = 0.f, s1 = 0.f;
    for (int sp = 0; sp < M_NSPLIT; sp++) {
        const float* p = g_Mp + ((size_t)(b * M_NSPLIT + sp)) * per + rem;
        s0 += p[0];
        s1 += p[1];
    }
    float u = Wb[i];
    s0 += u * g_s[b * KD + j];
    s1 += u * g_s[b * KD + j + 1];
    __nv_bfloat162 h2, l2;
    split_f32(s0, h2.x, l2.x);
    split_f32(s1, h2.y, l2.y);
    *(__nv_bfloat162*)&g_M_hi[idx] = h2;
    *(__nv_bfloat162*)&g_M_lo[idx] = l2;
}

// ---------------------------------------------------------------------------
// log_softmax over V + permute (B,L,V)->(L,B,V)
// ---------------------------------------------------------------------------
__global__ void logsoftmax_k(float* __restrict__ out) {
    int l = blockIdx.x, b = blockIdx.y;
    const float* row = g_logits + (size_t)(b * KL + l) * KVP;
    float* orow = out + (size_t)(l * KB + b) * KV;
    __shared__ float sred[8];
    int t = threadIdx.x;
    int wid = t >> 5, lane = t & 31;
    bool act = t < (KV / 4);
    float4 v = act ? *(const float4*)&row[t * 4]
                   : make_float4(-3.4e38f, -3.4e38f, -3.4e38f, -3.4e38f);
    float m = fmaxf(fmaxf(v.x, v.y), fmaxf(v.z, v.w));
#pragma unroll
    for (int s = 16; s >= 1; s >>= 1) m = fmaxf(m, __shfl_xor_sync(0xffffffffu, m, s));
    if (lane == 0) sred[wid] = m;
    __syncthreads();
    float m8 = (lane < 8) ? sred[lane] : -3.4e38f;
#pragma unroll
    for (int s = 4; s >= 1; s >>= 1) m8 = fmaxf(m8, __shfl_xor_sync(0xffffffffu, m8, s));
    float vmax = __shfl_sync(0xffffffffu, m8, 0);

    float e = act ? (__expf(v.x - vmax) + __expf(v.y - vmax) +
                     __expf(v.z - vmax) + __expf(v.w - vmax))
                  : 0.f;
#pragma unroll
    for (int s = 16; s >= 1; s >>= 1) e += __shfl_xor_sync(0xffffffffu, e, s);
    __syncthreads();
    if (lane == 0) sred[wid] = e;
    __syncthreads();
    float e8 = (lane < 8) ? sred[lane] : 0.f;
#pragma unroll
    for (int s = 4; s >= 1; s >>= 1) e8 += __shfl_xor_sync(0xffffffffu, e8, s);
    float denom = vmax + logf(__shfl_sync(0xffffffffu, e8, 0));

    if (act) {
        float4 o;
        o.x = v.x - denom; o.y = v.y - denom;
        o.z = v.z - denom; o.w = v.w - denom;
        *(float4*)&orow[t * 4] = o;
    }
}

// ---------------------------------------------------------------------------
extern "C" void kernel_launch(void* const* d_in, const int* in_sizes, int n_in,
                              void* d_out, int out_size) {
    (void)in_sizes; (void)n_in; (void)out_size;
    const float* x  = (const float*)d_in[0];
    const float* Ww = (const float*)d_in[1];
    const float* Wb = (const float*)d_in[2];
    const float* Lw = (const float*)d_in[3];
    const float* Lb = (const float*)d_in[4];
    float* out = (float*)d_out;

    static bool attr_set = false;
    if (!attr_set) {
        cudaFuncSetAttribute(mma_gemm_k, cudaFuncAttributeMaxDynamicSharedMemorySize, DYN_SMEM);
        cudaFuncSetAttribute(f16_gemm_k, cudaFuncAttributeMaxDynamicSharedMemorySize, LDYN);
        attr_set = true;
    }

    __half *Xb_hi, *Xb_lo, *Xt_hi, *Xt_lo, *P16;
    __nv_bfloat16 *Wwh, *Wwl, *Lwh, *Lwl;
    __nv_bfloat16 *Gh, *Gl, *Mh, *Ml;
    float *Lbp, *logits, *Gp, *Mp;
    cudaGetSymbolAddress((void**)&Xb_hi, g_Xb_hi);
    cudaGetSymbolAddress((void**)&Xb_lo, g_Xb_lo);
    cudaGetSymbolAddress((void**)&Xt_hi, g_Xt_hi);
    cudaGetSymbolAddress((void**)&Xt_lo, g_Xt_lo);
    cudaGetSymbolAddress((void**)&Wwh, g_Ww_hi);
    cudaGetSymbolAddress((void**)&Wwl, g_Ww_lo);
    cudaGetSymbolAddress((void**)&Lwh, g_Lw_hi);
    cudaGetSymbolAddress((void**)&Lwl, g_Lw_lo);
    cudaGetSymbolAddress((void**)&Gh, g_G_hi);
    cudaGetSymbolAddress((void**)&Gl, g_G_lo);
    cudaGetSymbolAddress((void**)&Mh, g_M_hi);
    cudaGetSymbolAddress((void**)&Ml, g_M_lo);
    cudaGetSymbolAddress((void**)&P16, g_P16);
    cudaGetSymbolAddress((void**)&Lbp, g_Lbp);
    cudaGetSymbolAddress((void**)&logits, g_logits);
    cudaGetSymbolAddress((void**)&Gp, g_Gp);
    cudaGetSymbolAddress((void**)&Mp, g_Mp);

    prep_x_k<<<dim3(KL / 64, KD / 64, KB), 256>>>(x);
    colsum_final_k<<<(KB * KD) / 256, 256>>>();
    prep_w_k<<<(KVP * KD) / 256, 256>>>(Ww, Lw, Lb);

    // G[b] = (Xt_hi+Xt_lo) * Xt_hi^T  (fp16 2-product, symmetric 10 pairs,
    // K-split x3 -> 120 CTAs single wave); B operand IS the hi tensor.
    f16_gemm_k<<<dim3(10, 1, KB * G_NSPLIT), 256, LDYN>>>(
        Xt_hi, Xt_lo, (size_t)KD * KL, Xt_hi, (size_t)KD * KL,
        KL, KL / 64, G_NSPLIT, Gp, 0, 128, nullptr, 4);
    reduce_G_k<<<(KB * KD * KD / 2) / 256, 256>>>();

    // M[b] = Ww*G[b]^T (bf16 3-product, K-split x2; rank-1 in reduce)
    mma_gemm_k<<<dim3(4, 4, KB * M_NSPLIT), 256, DYN_SMEM>>>(
        Wwh, Wwl, 0, Gh, Gl, (size_t)KD * KD,
        KD, KD / 64, M_NSPLIT, nullptr, nullptr, Mp, (size_t)KD * KD, KD, nullptr, 3);
    reduce_M_k<<<(KB * KD * KD / 2) / 256, 256>>>(Wb);

    // P[b][v][k] = sum_n Lw[v][n] * M[b][k][n] -> single fp16 (mode 5)
    mma_gemm_k<<<dim3(KVP / 128, KD / 128, KB), 256, DYN_SMEM>>>(
        Lwh, Lwl, 0, Mh, Ml, (size_t)KD * KD,
        KD, KD / 64, 1, (__nv_bfloat16*)P16, nullptr, nullptr,
        (size_t)KVP * KD, KD, nullptr, 5);

    // logits[b] = Xb * P^T + Lb  (fp16 2-product)
    f16_gemm_k<<<dim3(KL / 128, KVP / 128, KB), 256, LDYN>>>(
        Xb_hi, Xb_lo, (size_t)KL * KD, P16, (size_t)KVP * KD,
        KD, KD / 64, 1, logits, (size_t)KL * KVP, KVP, Lbp, 2);

    logsoftmax_k<<<dim3(KL, KB), 256>>>(out);
}

// round 15
// speedup vs baseline: 1.3189x; 1.0384x over previous
#include <cuda_runtime.h>
#include <cuda_bf16.h>
#include <cuda_fp16.h>
#include <cstdint>

#define KL 4096
#define KB 4
#define KD 512
#define KV 1000
#define KVP 1024   // padded vocab

// ---------------------------------------------------------------------------
// PTX helpers (sm_80-compatible only: ldmatrix / mma.sync / cp.async)
// ---------------------------------------------------------------------------
__device__ __forceinline__ uint32_t smem_to_u32(const void* p) {
    uint32_t a;
    asm("{ .reg .u64 t; cvta.to.shared.u64 t, %1; cvt.u32.u64 %0, t; }" : "=r"(a) : "l"(p));
    return a;
}
__device__ __forceinline__ void cpasync16(uint32_t s, const void* g) {
    asm volatile("cp.async.cg.shared.global [%0], [%1], 16;" :: "r"(s), "l"(g));
}
__device__ __forceinline__ void cp_commit() {
    asm volatile("cp.async.commit_group;" ::: "memory");
}
template <int N>
__device__ __forceinline__ void cp_wait() {
    asm volatile("cp.async.wait_group %0;" :: "n"(N) : "memory");
}
__device__ __forceinline__ void ldmx4(uint32_t* r, uint32_t a) {
    asm volatile("ldmatrix.sync.aligned.m8n8.x4.shared.b16 {%0,%1,%2,%3}, [%4];"
                 : "=r"(r[0]), "=r"(r[1]), "=r"(r[2]), "=r"(r[3]) : "r"(a));
}
__device__ __forceinline__ void mma16816(float* d, const uint32_t* a, const uint32_t* b) {
    asm volatile(
        "mma.sync.aligned.m16n8k16.row.col.f32.bf16.bf16.f32 "
        "{%0,%1,%2,%3}, {%4,%5,%6,%7}, {%8,%9}, {%0,%1,%2,%3};"
        : "+f"(d[0]), "+f"(d[1]), "+f"(d[2]), "+f"(d[3])
        : "r"(a[0]), "r"(a[1]), "r"(a[2]), "r"(a[3]), "r"(b[0]), "r"(b[1]));
}
__device__ __forceinline__ void mma16816h(float* d, const uint32_t* a, const uint32_t* b) {
    asm volatile(
        "mma.sync.aligned.m16n8k16.row.col.f32.f16.f16.f32 "
        "{%0,%1,%2,%3}, {%4,%5,%6,%7}, {%8,%9}, {%0,%1,%2,%3};"
        : "+f"(d[0]), "+f"(d[1]), "+f"(d[2]), "+f"(d[3])
        : "r"(a[0]), "r"(a[1]), "r"(a[2]), "r"(a[3]), "r"(b[0]), "r"(b[1]));
}
#define SMEM_SWIZZLE_128B(o) ((o) ^ (((o) >> 3) & 0x70))

// symmetric-G tile pair tables (upper triangle of 4x4)
__constant__ int c_pi[10] = {0, 0, 0, 0, 1, 1, 1, 2, 2, 3};
__constant__ int c_pj[10] = {0, 1, 2, 3, 1, 2, 3, 2, 3, 3};
__constant__ int c_PT[16] = {0, 1, 2, 3,  0, 4, 5, 6,  0, 0, 7, 8,  0, 0, 0, 9};

// ---------------------------------------------------------------------------
// scratch (static device globals; no allocations)
// ---------------------------------------------------------------------------
#define G_NSPLIT 3   // 10 pairs * KB * 3 = 120 CTAs -> single wave on 148 SMs
#define M_NSPLIT 2
__device__ __align__(128) float g_part2[KB * KD * 64];   // colsum partials
__device__ __align__(128) float g_s[KB * KD];
__device__ __align__(128) __half g_Xb_hi[(size_t)KB * KL * KD], g_Xb_lo[(size_t)KB * KL * KD];
__device__ __align__(128) __half g_Xt_hi[(size_t)KB * KD * KL], g_Xt_lo[(size_t)KB * KD * KL];
__device__ __align__(128) __nv_bfloat16 g_Ww_hi[KD * KD], g_Ww_lo[KD * KD];
__device__ __align__(128) __nv_bfloat16 g_Lw_hi[KVP * KD], g_Lw_lo[KVP * KD];
__device__ __align__(128) float g_Lbp[KVP];
__device__ __align__(128) float g_Gp[(size_t)KB * G_NSPLIT * 10 * 128 * 128]; // 7.9 MB
__device__ __align__(128) float g_Mp[(size_t)M_NSPLIT * KB * KD * KD];        // 8 MB
__device__ __align__(128) __nv_bfloat16 g_G_hi[KB * KD * KD], g_G_lo[KB * KD * KD];
__device__ __align__(128) __nv_bfloat16 g_M_hi[KB * KD * KD], g_M_lo[KB * KD * KD];
__device__ __align__(128) __half g_P16[(size_t)KB * KVP * KD];                // fp16 single
__device__ __align__(128) float g_logits[(size_t)KB * KL * KVP];

__device__ __forceinline__ void split_f32(float v, __nv_bfloat16& h, __nv_bfloat16& l) {
    h = __float2bfloat16(v);
    l = __float2bfloat16(v - __bfloat162float(h));
}
__device__ __forceinline__ void split_f16(float v, __half& h, __half& l) {
    h = __float2half(v);
    l = __float2half(v - __half2float(h));
}

// ---------------------------------------------------------------------------
// prep_x: x -> Xb fp16 hi/lo (logits A), Xt fp16 hi/lo (G operands), colsums
// ---------------------------------------------------------------------------
__global__ __launch_bounds__(256) void prep_x_k(const float* __restrict__ x) {
    __shared__ __half shi[64][65], slo[64][65];
    __shared__ float ssum[4][64];
    int b = blockIdx.z;
    int lblk = blockIdx.x;
    int l0 = lblk * 64, d0 = blockIdx.y * 64;
    int t = threadIdx.x;
    int c = t & 63, r4 = t >> 6;
    float ps = 0.f;
#pragma unroll 4
    for (int rr = 0; rr < 16; rr++) {
        int r = r4 * 16 + rr;
        float v = x[(size_t)(l0 + r) * (KB * KD) + b * KD + d0 + c];
        ps += v;
        size_t o = ((size_t)b * KL + (l0 + r)) * KD + d0 + c;
        __half fh, fl;
        split_f16(v, fh, fl);
        g_Xb_hi[o] = fh; g_Xb_lo[o] = fl;
        shi[r][c] = fh; slo[r][c] = fl;
    }
    ssum[r4][c] = ps;
    __syncthreads();
#pragma unroll 4
    for (int rr = 0; rr < 16; rr++) {
        int r = r4 * 16 + rr;   // d index
        size_t o = ((size_t)b * KD + (d0 + r)) * KL + l0 + c;
        g_Xt_hi[o] = shi[c][r];
        g_Xt_lo[o] = slo[c][r];
    }
    if (t < 64) {
        float s = ssum[0][t] + ssum[1][t] + ssum[2][t] + ssum[3][t];
        g_part2[((size_t)b * KD + d0 + t) * 64 + lblk] = s;
    }
}

__global__ void colsum_final_k() {
    int idx = blockIdx.x * 256 + threadIdx.x;  // KB*KD
    float s = 0.f;
    const float* p = &g_part2[(size_t)idx * 64];
#pragma unroll
    for (int k = 0; k < 64; k++) s += p[k];
    g_s[idx] = s;
}

// ---------------------------------------------------------------------------
// prep_w (flat): split Ww; split Lw padded to 1024 rows; pad Lb
// ---------------------------------------------------------------------------
__global__ void prep_w_k(const float* __restrict__ Ww, const float* __restrict__ Lw,
                         const float* __restrict__ Lb) {
    int idx = blockIdx.x * 256 + threadIdx.x;   // over KVP*KD
    int row = idx / KD;
    float v2 = (row < KV) ? Lw[idx] : 0.f;
    __nv_bfloat16 h2, l2;
    split_f32(v2, h2, l2);
    g_Lw_hi[idx] = h2; g_Lw_lo[idx] = l2;
    if (idx < KD * KD) {
        __nv_bfloat16 h, l;
        split_f32(Ww[idx], h, l);
        g_Ww_hi[idx] = h; g_Ww_lo[idx] = l;
    }
    if (idx < KVP) g_Lbp[idx] = (idx < KV) ? Lb[idx] : 0.f;
}

// ---------------------------------------------------------------------------
// mma.sync bf16 split GEMM (R7-proven): C[m][n] = sum_k A[m][k]*B[n][k]
//   mode 0: write Chi/Clo bf16    mode 3: fp32 K-split partial
//   mode 5: write single fp16 (Chi cast)
// ---------------------------------------------------------------------------
#define TILE_BYTES 16384               // 128 rows x 128B (64 bf16)
#define STAGE_BYTES (4 * TILE_BYTES)   // Ah, Al, Bh, Bl
#define NSTAGE 3
#define DYN_SMEM (NSTAGE * STAGE_BYTES)  // 192 KB

__global__ __launch_bounds__(256, 1) void mma_gemm_k(
    const __nv_bfloat16* __restrict__ Ahi, const __nv_bfloat16* __restrict__ Alo, size_t sA,
    const __nv_bfloat16* __restrict__ Bhi, const __nv_bfloat16* __restrict__ Blo, size_t sB,
    int ldk, int NCtot, int nsplit,
    __nv_bfloat16* __restrict__ Chi, __nv_bfloat16* __restrict__ Clo,
    float* __restrict__ Cf, size_t sC, int ldc,
    const float* __restrict__ bias, int mode) {
    extern __shared__ __align__(1024) char smem[];
    uint32_t smb = smem_to_u32(smem);
    int tid = threadIdx.x;
    int wid = tid >> 5, lane = tid & 31;
    int b = blockIdx.z / nsplit, sp = blockIdx.z % nsplit;
    int basec = NCtot / nsplit, remc = NCtot % nsplit;
    int NC = basec + (sp < remc ? 1 : 0);
    int startc = sp * basec + (sp < remc ? sp : remc);
    int koff0 = startc << 6;
    int i0 = blockIdx.x * 128, j0 = blockIdx.y * 128;
    int wm = (wid >> 2) * 64, wn = (wid & 3) * 32;

    const __nv_bfloat16* tiles[4] = {Ahi + sA * b, Alo + sA * b, Bhi + sB * b, Blo + sB * b};
    const int row0[4] = {i0, i0, j0, j0};

    int lr[4], lu[4];
#pragma unroll
    for (int it = 0; it < 4; it++) {
        int q = tid + it * 256;
        lr[it] = q >> 3;
        lu[it] = q & 7;
    }

    auto load_chunk = [&](int chunk) {
        uint32_t sbase = smb + (chunk % NSTAGE) * STAGE_BYTES;
        int koff = koff0 + (chunk << 6);
#pragma unroll
        for (int tile = 0; tile < 4; tile++) {
            const __nv_bfloat16* src = tiles[tile];
#pragma unroll
            for (int it = 0; it < 4; it++) {
                uint32_t boff = (uint32_t)(lr[it] * 128 + lu[it] * 16);
                uint32_t sw = SMEM_SWIZZLE_128B(boff);
                const void* g = src + (size_t)(row0[tile] + lr[it]) * ldk + koff + lu[it] * 8;
                cpasync16(sbase + tile * TILE_BYTES + sw, g);
            }
        }
        cp_commit();
    };

    float acc[4][4][4];
#pragma unroll
    for (int a = 0; a < 4; a++)
#pragma unroll
        for (int bb = 0; bb < 4; bb++)
#pragma unroll
            for (int c = 0; c < 4; c++) acc[a][bb][c] = 0.f;

    int arow = wm + (lane & 15);
    int akh16 = ((lane >> 4) & 1) * 16;
    int brow = wn + ((lane >> 4) & 1) * 8 + (lane & 7);
    int bkh16 = ((lane >> 3) & 1) * 16;

    load_chunk(0);
    if (NC > 1) load_chunk(1);

    for (int kc = 0; kc < NC; kc++) {
        if (kc < NC - 1) cp_wait<1>();
        else cp_wait<0>();
        __syncthreads();

        uint32_t sAh = smb + (kc % NSTAGE) * STAGE_BYTES;
        uint32_t sAl = sAh + TILE_BYTES;
        uint32_t sBh = sAh + 2 * TILE_BYTES;
        uint32_t sBl = sAh + 3 * TILE_BYTES;

#pragma unroll
        for (int kk = 0; kk < 4; kk++) {
            uint32_t ah[4][4], al[4][4], bh[2][4], bl[2][4];
#pragma unroll
            for (int mt = 0; mt < 4; mt++) {
                uint32_t o = (uint32_t)((arow + mt * 16) * 128 + kk * 32 + akh16);
                uint32_t sw = SMEM_SWIZZLE_128B(o);
                ldmx4(ah[mt], sAh + sw);
                ldmx4(al[mt], sAl + sw);
            }
#pragma unroll
            for (int np = 0; np < 2; np++) {
                uint32_t o = (uint32_t)((brow + np * 16) * 128 + kk * 32 + bkh16);
                uint32_t sw = SMEM_SWIZZLE_128B(o);
                ldmx4(bh[np], sBh + sw);
                ldmx4(bl[np], sBl + sw);
            }
#pragma unroll
            for (int mt = 0; mt < 4; mt++)
#pragma unroll
                for (int nt = 0; nt < 4; nt++) {
                    uint32_t* bfh = &bh[nt >> 1][(nt & 1) * 2];
                    uint32_t* bfl = &bl[nt >> 1][(nt & 1) * 2];
                    mma16816(acc[mt][nt], ah[mt], bfh);  // hi*hi
                    mma16816(acc[mt][nt], ah[mt], bfl);  // hi*lo
                    mma16816(acc[mt][nt], al[mt], bfh);  // lo*hi
                }
        }
        if (kc + 2 < NC) load_chunk(kc + 2);
    }

    // ---- epilogue ----
#pragma unroll
    for (int mt = 0; mt < 4; mt++) {
#pragma unroll
        for (int half = 0; half < 2; half++) {
            int lrow = wm + mt * 16 + (lane >> 2) + half * 8;
            int grow = i0 + lrow;
#pragma unroll
            for (int nt = 0; nt < 4; nt++) {
                int lcol = wn + nt * 8 + (lane & 3) * 2;
                int gcol = j0 + lcol;
                float v0 = acc[mt][nt][half * 2 + 0];
                float v1 = acc[mt][nt][half * 2 + 1];
                if (mode == 3) {
                    *(float2*)&Cf[sC * blockIdx.z + (size_t)grow * ldc + gcol] = make_float2(v0, v1);
                } else if (mode == 5) {
                    __half2 hh;
                    hh.x = __float2half(v0);
                    hh.y = __float2half(v1);
                    *(__half2*)&((__half*)Chi)[sC * b + (size_t)grow * ldc + gcol] = hh;
                } else {
                    __nv_bfloat162 h2, l2;
                    split_f32(v0, h2.x, l2.x);
                    split_f32(v1, h2.y, l2.y);
                    *(__nv_bfloat162*)&Chi[sC * b + (size_t)grow * ldc + gcol] = h2;
                    *(__nv_bfloat162*)&Clo[sC * b + (size_t)grow * ldc + gcol] = l2;
                }
            }
        }
    }
}

// ---------------------------------------------------------------------------
// f16 2-product GEMM, templated on pipeline depth / CTAs-per-SM:
//   C[m][n] = sum_k (Ah+Al)[m][k] * B16[n][k]
//   NST=3, MINB=1: depth-2 prefetch (G).   NST=2, MINB=2: 2 CTAs/SM (logits).
//   A fragments streamed per-mt to fit the 128-reg cap at MINB=2.
//   mode 2: fp32 + bias out at batch b    mode 4: symmetric-pair K-split tile
// ---------------------------------------------------------------------------
#define LTILE 16384
#define LSTAGE (3 * LTILE)

template <int NST, int MINB>
__global__ __launch_bounds__(256, MINB) void f16_gemm_t(
    const __half* __restrict__ Ahi, const __half* __restrict__ Alo, size_t sA,
    const __half* __restrict__ B16, size_t sB,
    int ldk, int NCtot, int nsplit,
    float* __restrict__ Cf, size_t sC, int ldc,
    const float* __restrict__ bias, int mode) {
    extern __shared__ __align__(1024) char smem[];
    uint32_t smb = smem_to_u32(smem);
    int tid = threadIdx.x;
    int wid = tid >> 5, lane = tid & 31;
    int b = blockIdx.z / nsplit, sp = blockIdx.z % nsplit;
    int basec = NCtot / nsplit, remc = NCtot % nsplit;
    int NC = basec + (sp < remc ? 1 : 0);
    int startc = sp * basec + (sp < remc ? sp : remc);
    int koff0 = startc << 6;
    int i0, j0;
    if (mode == 4) {
        i0 = c_pi[blockIdx.x] * 128;
        j0 = c_pj[blockIdx.x] * 128;
    } else {
        i0 = blockIdx.x * 128;
        j0 = blockIdx.y * 128;
    }
    int wm = (wid >> 2) * 64, wn = (wid & 3) * 32;

    const __half* tiles[3] = {Ahi + sA * b, Alo + sA * b, B16 + sB * b};
    const int row0[3] = {i0, i0, j0};

    int lr[4], lu[4];
#pragma unroll
    for (int it = 0; it < 4; it++) {
        int q = tid + it * 256;
        lr[it] = q >> 3;
        lu[it] = q & 7;
    }

    auto load_chunk = [&](int chunk) {
        uint32_t sbase = smb + (chunk % NST) * LSTAGE;
        int koff = koff0 + (chunk << 6);
#pragma unroll
        for (int tile = 0; tile < 3; tile++) {
            const __half* src = tiles[tile];
#pragma unroll
            for (int it = 0; it < 4; it++) {
                uint32_t boff = (uint32_t)(lr[it] * 128 + lu[it] * 16);
                uint32_t sw = SMEM_SWIZZLE_128B(boff);
                cpasync16(sbase + tile * LTILE + sw,
                          src + (size_t)(row0[tile] + lr[it]) * ldk + koff + lu[it] * 8);
            }
        }
        cp_commit();
    };

    float acc[4][4][4];
#pragma unroll
    for (int a = 0; a < 4; a++)
#pragma unroll
        for (int bb = 0; bb < 4; bb++)
#pragma unroll
            for (int c = 0; c < 4; c++) acc[a][bb][c] = 0.f;

    int arow = wm + (lane & 15);
    int akh16 = ((lane >> 4) & 1) * 16;
    int brow = wn + ((lane >> 4) & 1) * 8 + (lane & 7);
    int bkh16 = ((lane >> 3) & 1) * 16;

    load_chunk(0);
    if (NST == 3 && NC > 1) load_chunk(1);

    for (int kc = 0; kc < NC; kc++) {
        if (NST == 3) {
            if (kc < NC - 1) cp_wait<1>();
            else cp_wait<0>();
        } else {
            cp_wait<0>();
        }
        __syncthreads();
        if (NST == 2 && kc + 1 < NC) load_chunk(kc + 1);

        uint32_t sAh = smb + (kc % NST) * LSTAGE;
        uint32_t sAl = sAh + LTILE;
        uint32_t sB_ = sAh + 2 * LTILE;

#pragma unroll
        for (int kk = 0; kk < 4; kk++) {
            uint32_t bh[2][4];
#pragma unroll
            for (int np = 0; np < 2; np++) {
                uint32_t o = (uint32_t)((brow + np * 16) * 128 + kk * 32 + bkh16);
                uint32_t sw = SMEM_SWIZZLE_128B(o);
                ldmx4(bh[np], sB_ + sw);
            }
#pragma unroll
            for (int mt = 0; mt < 4; mt++) {
                uint32_t ah[4], al[4];
                uint32_t o = (uint32_t)((arow + mt * 16) * 128 + kk * 32 + akh16);
                uint32_t sw = SMEM_SWIZZLE_128B(o);
                ldmx4(ah, sAh + sw);
                ldmx4(al, sAl + sw);
#pragma unroll
                for (int nt = 0; nt < 4; nt++) {
                    uint32_t* bf = &bh[nt >> 1][(nt & 1) * 2];
                    mma16816h(acc[mt][nt], ah, bf);  // hi * B
                    mma16816h(acc[mt][nt], al, bf);  // lo * B
                }
            }
        }
        if (NST == 3 && kc + 2 < NC) load_chunk(kc + 2);
    }

    // ---- epilogue ----
    float* loc = (mode == 4)
        ? Cf + ((size_t)blockIdx.z * gridDim.x + blockIdx.x) * (128 * 128)
        : nullptr;
#pragma unroll
    for (int mt = 0; mt < 4; mt++) {
#pragma unroll
        for (int half = 0; half < 2; half++) {
            int lrow = wm + mt * 16 + (lane >> 2) + half * 8;
            int grow = i0 + lrow;
#pragma unroll
            for (int nt = 0; nt < 4; nt++) {
                int lcol = wn + nt * 8 + (lane & 3) * 2;
                int gcol = j0 + lcol;
                float v0 = acc[mt][nt][half * 2 + 0];
                float v1 = acc[mt][nt][half * 2 + 1];
                if (mode == 4) {
                    *(float2*)&loc[lrow * 128 + lcol] = make_float2(v0, v1);
                } else {
                    float2 f2 = make_float2(v0 + bias[gcol], v1 + bias[gcol + 1]);
                    *(float2*)&Cf[sC * b + (size_t)grow * ldc + gcol] = f2;
                }
            }
        }
    }
}

// ---------------------------------------------------------------------------
// reduce symmetric-G partials (10 tile-pairs x G_NSPLIT) -> full G hi/lo bf16
// ---------------------------------------------------------------------------
__global__ void reduce_G_k() {
    size_t idx = ((size_t)blockIdx.x * 256 + threadIdx.x) * 2;  // KB*KD*KD elems
    const size_t per = (size_t)KD * KD;
    int b = (int)(idx / per);
    size_t rem = idx % per;
    int i = (int)(rem / KD), j = (int)(rem % KD);
    int ti = i >> 7, tj = j >> 7;
    float s0 = 0.f, s1 = 0.f;
    if (ti <= tj) {
        int p = c_PT[ti * 4 + tj];
        size_t off = (size_t)((i & 127) * 128 + (j & 127));
        for (int sp = 0; sp < G_NSPLIT; sp++) {
            const float* base = g_Gp + ((size_t)(b * G_NSPLIT + sp) * 10 + p) * (128 * 128);
            s0 += base[off];
            s1 += base[off + 1];
        }
    } else {
        int p = c_PT[tj * 4 + ti];
        size_t off = (size_t)((j & 127) * 128 + (i & 127));
        for (int sp = 0; sp < G_NSPLIT; sp++) {
            const float* base = g_Gp + ((size_t)(b * G_NSPLIT + sp) * 10 + p) * (128 * 128);
            s0 += base[off];
            s1 += base[off + 128];   // G[i][j+1] = mirrored tile, next row
        }
    }
    __nv_bfloat162 h2, l2;
    split_f32(s0, h2.x, l2.x);
    split_f32(s1, h2.y, l2.y);
    *(__nv_bfloat162*)&g_G_hi[idx] = h2;
    *(__nv_bfloat162*)&g_G_lo[idx] = l2;
}

// ---------------------------------------------------------------------------
// reduce M K-split partials + rank-1 Wb[i]*s[b][j] -> hi/lo bf16
// ---------------------------------------------------------------------------
__global__ void reduce_M_k(const float* __restrict__ Wb) {
    size_t idx = ((size_t)blockIdx.x * 256 + threadIdx.x) * 2;
    const size_t per = (size_t)KD * KD;
    int b = (int)(idx / per);
    size_t rem = idx % per;
    int i = (int)(rem / KD), j = (int)(rem % KD);
    float s0 = 0.f, s1 = 0.f;
    for (int sp = 0; sp < M_NSPLIT; sp++) {
        const float* p = g_Mp + ((size_t)(b * M_NSPLIT + sp)) * per + rem;
        s0 += p[0];
        s1 += p[1];
    }
    float u = Wb[i];
    s0 += u * g_s[b * KD + j];
    s1 += u * g_s[b * KD + j + 1];
    __nv_bfloat162 h2, l2;
    split_f32(s0, h2.x, l2.x);
    split_f32(s1, h2.y, l2.y);
    *(__nv_bfloat162*)&g_M_hi[idx] = h2;
    *(__nv_bfloat162*)&g_M_lo[idx] = l2;
}

// ---------------------------------------------------------------------------
// log_softmax over V + permute (B,L,V)->(L,B,V)
// ---------------------------------------------------------------------------
__global__ void logsoftmax_k(float* __restrict__ out) {
    int l = blockIdx.x, b = blockIdx.y;
    const float* row = g_logits + (size_t)(b * KL + l) * KVP;
    float* orow = out + (size_t)(l * KB + b) * KV;
    __shared__ float sred[8];
    int t = threadIdx.x;
    int wid = t >> 5, lane = t & 31;
    bool act = t < (KV / 4);
    float4 v = act ? *(const float4*)&row[t * 4]
                   : make_float4(-3.4e38f, -3.4e38f, -3.4e38f, -3.4e38f);
    float m = fmaxf(fmaxf(v.x, v.y), fmaxf(v.z, v.w));
#pragma unroll
    for (int s = 16; s >= 1; s >>= 1) m = fmaxf(m, __shfl_xor_sync(0xffffffffu, m, s));
    if (lane == 0) sred[wid] = m;
    __syncthreads();
    float m8 = (lane < 8) ? sred[lane] : -3.4e38f;
#pragma unroll
    for (int s = 4; s >= 1; s >>= 1) m8 = fmaxf(m8, __shfl_xor_sync(0xffffffffu, m8, s));
    float vmax = __shfl_sync(0xffffffffu, m8, 0);

    float e = act ? (__expf(v.x - vmax) + __expf(v.y - vmax) +
                     __expf(v.z - vmax) + __expf(v.w - vmax))
                  : 0.f;
#pragma unroll
    for (int s = 16; s >= 1; s >>= 1) e += __shfl_xor_sync(0xffffffffu, e, s);
    __syncthreads();
    if (lane == 0) sred[wid] = e;
    __syncthreads();
    float e8 = (lane < 8) ? sred[lane] : 0.f;
#pragma unroll
    for (int s = 4; s >= 1; s >>= 1) e8 += __shfl_xor_sync(0xffffffffu, e8, s);
    float denom = vmax + logf(__shfl_sync(0xffffffffu, e8, 0));

    if (act) {
        float4 o;
        o.x = v.x - denom; o.y = v.y - denom;
        o.z = v.z - denom; o.w = v.w - denom;
        *(float4*)&orow[t * 4] = o;
    }
}

// ---------------------------------------------------------------------------
extern "C" void kernel_launch(void* const* d_in, const int* in_sizes, int n_in,
                              void* d_out, int out_size) {
    (void)in_sizes; (void)n_in; (void)out_size;
    const float* x  = (const float*)d_in[0];
    const float* Ww = (const float*)d_in[1];
    const float* Wb = (const float*)d_in[2];
    const float* Lw = (const float*)d_in[3];
    const float* Lb = (const float*)d_in[4];
    float* out = (float*)d_out;

    static bool attr_set = false;
    if (!attr_set) {
        cudaFuncSetAttribute(mma_gemm_k, cudaFuncAttributeMaxDynamicSharedMemorySize, DYN_SMEM);
        cudaFuncSetAttribute(f16_gemm_t<3, 1>, cudaFuncAttributeMaxDynamicSharedMemorySize,
                             3 * LSTAGE);
        cudaFuncSetAttribute(f16_gemm_t<2, 2>, cudaFuncAttributeMaxDynamicSharedMemorySize,
                             2 * LSTAGE);
        attr_set = true;
    }

    __half *Xb_hi, *Xb_lo, *Xt_hi, *Xt_lo, *P16;
    __nv_bfloat16 *Wwh, *Wwl, *Lwh, *Lwl;
    __nv_bfloat16 *Gh, *Gl, *Mh, *Ml;
    float *Lbp, *logits, *Gp, *Mp;
    cudaGetSymbolAddress((void**)&Xb_hi, g_Xb_hi);
    cudaGetSymbolAddress((void**)&Xb_lo, g_Xb_lo);
    cudaGetSymbolAddress((void**)&Xt_hi, g_Xt_hi);
    cudaGetSymbolAddress((void**)&Xt_lo, g_Xt_lo);
    cudaGetSymbolAddress((void**)&Wwh, g_Ww_hi);
    cudaGetSymbolAddress((void**)&Wwl, g_Ww_lo);
    cudaGetSymbolAddress((void**)&Lwh, g_Lw_hi);
    cudaGetSymbolAddress((void**)&Lwl, g_Lw_lo);
    cudaGetSymbolAddress((void**)&Gh, g_G_hi);
    cudaGetSymbolAddress((void**)&Gl, g_G_lo);
    cudaGetSymbolAddress((void**)&Mh, g_M_hi);
    cudaGetSymbolAddress((void**)&Ml, g_M_lo);
    cudaGetSymbolAddress((void**)&P16, g_P16);
    cudaGetSymbolAddress((void**)&Lbp, g_Lbp);
    cudaGetSymbolAddress((void**)&logits, g_logits);
    cudaGetSymbolAddress((void**)&Gp, g_Gp);
    cudaGetSymbolAddress((void**)&Mp, g_Mp);

    prep_x_k<<<dim3(KL / 64, KD / 64, KB), 256>>>(x);
    colsum_final_k<<<(KB * KD) / 256, 256>>>();
    prep_w_k<<<(KVP * KD) / 256, 256>>>(Ww, Lw, Lb);

    // G[b] = (Xt_hi+Xt_lo) * Xt_hi^T  (fp16 2-product, symmetric 10 pairs,
    // K-split x3 -> 120 CTAs single wave, 3-stage depth-2 prefetch)
    f16_gemm_t<3, 1><<<dim3(10, 1, KB * G_NSPLIT), 256, 3 * LSTAGE>>>(
        Xt_hi, Xt_lo, (size_t)KD * KL, Xt_hi, (size_t)KD * KL,
        KL, KL / 64, G_NSPLIT, Gp, 0, 128, nullptr, 4);
    reduce_G_k<<<(KB * KD * KD / 2) / 256, 256>>>();

    // M[b] = Ww*G[b]^T (bf16 3-product, K-split x2; rank-1 in reduce)
    mma_gemm_k<<<dim3(4, 4, KB * M_NSPLIT), 256, DYN_SMEM>>>(
        Wwh, Wwl, 0, Gh, Gl, (size_t)KD * KD,
        KD, KD / 64, M_NSPLIT, nullptr, nullptr, Mp, (size_t)KD * KD, KD, nullptr, 3);
    reduce_M_k<<<(KB * KD * KD / 2) / 256, 256>>>(Wb);

    // P[b][v][k] = sum_n Lw[v][n] * M[b][k][n] -> single fp16 (mode 5)
    mma_gemm_k<<<dim3(KVP / 128, KD / 128, KB), 256, DYN_SMEM>>>(
        Lwh, Lwl, 0, Mh, Ml, (size_t)KD * KD,
        KD, KD / 64, 1, (__nv_bfloat16*)P16, nullptr, nullptr,
        (size_t)KVP * KD, KD, nullptr, 5);

    // logits[b] = Xb * P^T + Lb  (fp16 2-product, 2-stage, 2 CTAs/SM)
    f16_gemm_t<2, 2><<<dim3(KL / 128, KVP / 128, KB), 256, 2 * LSTAGE>>>(
        Xb_hi, Xb_lo, (size_t)KL * KD, P16, (size_t)KVP * KD,
        KD, KD / 64, 1, logits, (size_t)KL * KVP, KVP, Lbp, 2);

    logsoftmax_k<<<dim3(KL, KB), 256>>>(out);
}

// round 16
// speedup vs baseline: 1.7013x; 1.2899x over previous
#include <cuda_runtime.h>
#include <cuda_bf16.h>
#include <cuda_fp16.h>
#include <cstdint>

#define KL 4096
#define KB 4
#define KD 512
#define KV 1000
#define KVP 1024   // padded vocab

// ---------------------------------------------------------------------------
// PTX helpers (sm_80-compatible only: ldmatrix / mma.sync / cp.async)
// ---------------------------------------------------------------------------
__device__ __forceinline__ uint32_t smem_to_u32(const void* p) {
    uint32_t a;
    asm("{ .reg .u64 t; cvta.to.shared.u64 t, %1; cvt.u32.u64 %0, t; }" : "=r"(a) : "l"(p));
    return a;
}
__device__ __forceinline__ void cpasync16(uint32_t s, const void* g) {
    asm volatile("cp.async.cg.shared.global [%0], [%1], 16;" :: "r"(s), "l"(g));
}
__device__ __forceinline__ void cp_commit() {
    asm volatile("cp.async.commit_group;" ::: "memory");
}
template <int N>
__device__ __forceinline__ void cp_wait() {
    asm volatile("cp.async.wait_group %0;" :: "n"(N) : "memory");
}
__device__ __forceinline__ void ldmx4(uint32_t* r, uint32_t a) {
    asm volatile("ldmatrix.sync.aligned.m8n8.x4.shared.b16 {%0,%1,%2,%3}, [%4];"
                 : "=r"(r[0]), "=r"(r[1]), "=r"(r[2]), "=r"(r[3]) : "r"(a));
}
__device__ __forceinline__ void mma16816(float* d, const uint32_t* a, const uint32_t* b) {
    asm volatile(
        "mma.sync.aligned.m16n8k16.row.col.f32.bf16.bf16.f32 "
        "{%0,%1,%2,%3}, {%4,%5,%6,%7}, {%8,%9}, {%0,%1,%2,%3};"
        : "+f"(d[0]), "+f"(d[1]), "+f"(d[2]), "+f"(d[3])
        : "r"(a[0]), "r"(a[1]), "r"(a[2]), "r"(a[3]), "r"(b[0]), "r"(b[1]));
}
__device__ __forceinline__ void mma16816h(float* d, const uint32_t* a, const uint32_t* b) {
    asm volatile(
        "mma.sync.aligned.m16n8k16.row.col.f32.f16.f16.f32 "
        "{%0,%1,%2,%3}, {%4,%5,%6,%7}, {%8,%9}, {%0,%1,%2,%3};"
        : "+f"(d[0]), "+f"(d[1]), "+f"(d[2]), "+f"(d[3])
        : "r"(a[0]), "r"(a[1]), "r"(a[2]), "r"(a[3]), "r"(b[0]), "r"(b[1]));
}
#define SMEM_SWIZZLE_128B(o) ((o) ^ (((o) >> 3) & 0x70))

// symmetric-G tile pair tables (upper triangle of 4x4)
__constant__ int c_pi[10] = {0, 0, 0, 0, 1, 1, 1, 2, 2, 3};
__constant__ int c_pj[10] = {0, 1, 2, 3, 1, 2, 3, 2, 3, 3};
__constant__ int c_PT[16] = {0, 1, 2, 3,  0, 4, 5, 6,  0, 0, 7, 8,  0, 0, 0, 9};

// ---------------------------------------------------------------------------
// scratch (static device globals; no allocations)
// ---------------------------------------------------------------------------
#define G_NSPLIT 3   // 10 pairs * KB * 3 = 120 CTAs -> single wave on 148 SMs
#define M_NSPLIT 2
__device__ __align__(128) float g_part2[KB * KD * 64];   // colsum partials
__device__ __align__(128) float g_s[KB * KD];
__device__ __align__(128) __half g_Xb16[(size_t)KB * KL * KD];   // fp16 single
__device__ __align__(128) __half g_Xt16[(size_t)KB * KD * KL];   // fp16 single
__device__ __align__(128) __nv_bfloat16 g_Ww_hi[KD * KD], g_Ww_lo[KD * KD];
__device__ __align__(128) __nv_bfloat16 g_Lw_hi[KVP * KD], g_Lw_lo[KVP * KD];
__device__ __align__(128) float g_Lbp[KVP];
__device__ __align__(128) float g_Gp[(size_t)KB * G_NSPLIT * 10 * 128 * 128]; // 7.9 MB
__device__ __align__(128) float g_Mp[(size_t)M_NSPLIT * KB * KD * KD];        // 8 MB
__device__ __align__(128) __nv_bfloat16 g_G_hi[KB * KD * KD], g_G_lo[KB * KD * KD];
__device__ __align__(128) __nv_bfloat16 g_M_hi[KB * KD * KD], g_M_lo[KB * KD * KD];
__device__ __align__(128) __half g_P16[(size_t)KB * KVP * KD];                // fp16 single
__device__ __align__(128) float g_logits[(size_t)KB * KL * KVP];

__device__ __forceinline__ void split_f32(float v, __nv_bfloat16& h, __nv_bfloat16& l) {
    h = __float2bfloat16(v);
    l = __float2bfloat16(v - __bfloat162float(h));
}

// ---------------------------------------------------------------------------
// prep_x: x -> Xb16 (logits A), Xt16 (G operands), colsum partials
// ---------------------------------------------------------------------------
__global__ __launch_bounds__(256) void prep_x_k(const float* __restrict__ x) {
    __shared__ __half sh[64][65];
    __shared__ float ssum[4][64];
    int b = blockIdx.z;
    int lblk = blockIdx.x;
    int l0 = lblk * 64, d0 = blockIdx.y * 64;
    int t = threadIdx.x;
    int c = t & 63, r4 = t >> 6;
    float ps = 0.f;
#pragma unroll 4
    for (int rr = 0; rr < 16; rr++) {
        int r = r4 * 16 + rr;
        float v = x[(size_t)(l0 + r) * (KB * KD) + b * KD + d0 + c];
        ps += v;
        __half fh = __float2half(v);
        g_Xb16[((size_t)b * KL + (l0 + r)) * KD + d0 + c] = fh;
        sh[r][c] = fh;
    }
    ssum[r4][c] = ps;
    __syncthreads();
#pragma unroll 4
    for (int rr = 0; rr < 16; rr++) {
        int r = r4 * 16 + rr;   // d index
        g_Xt16[((size_t)b * KD + (d0 + r)) * KL + l0 + c] = sh[c][r];
    }
    if (t < 64) {
        float s = ssum[0][t] + ssum[1][t] + ssum[2][t] + ssum[3][t];
        g_part2[((size_t)b * KD + d0 + t) * 64 + lblk] = s;
    }
}

__global__ void colsum_final_k() {
    int idx = blockIdx.x * 256 + threadIdx.x;  // KB*KD
    float s = 0.f;
    const float* p = &g_part2[(size_t)idx * 64];
#pragma unroll
    for (int k = 0; k < 64; k++) s += p[k];
    g_s[idx] = s;
}

// ---------------------------------------------------------------------------
// prep_w (flat): split Ww; split Lw padded to 1024 rows; pad Lb
// ---------------------------------------------------------------------------
__global__ void prep_w_k(const float* __restrict__ Ww, const float* __restrict__ Lw,
                         const float* __restrict__ Lb) {
    int idx = blockIdx.x * 256 + threadIdx.x;   // over KVP*KD
    int row = idx / KD;
    float v2 = (row < KV) ? Lw[idx] : 0.f;
    __nv_bfloat16 h2, l2;
    split_f32(v2, h2, l2);
    g_Lw_hi[idx] = h2; g_Lw_lo[idx] = l2;
    if (idx < KD * KD) {
        __nv_bfloat16 h, l;
        split_f32(Ww[idx], h, l);
        g_Ww_hi[idx] = h; g_Ww_lo[idx] = l;
    }
    if (idx < KVP) g_Lbp[idx] = (idx < KV) ? Lb[idx] : 0.f;
}

// ---------------------------------------------------------------------------
// mma.sync bf16 split GEMM (R7-proven): C[m][n] = sum_k A[m][k]*B[n][k]
//   mode 3: fp32 K-split partial    mode 5: write single fp16 (Chi cast)
// ---------------------------------------------------------------------------
#define TILE_BYTES 16384               // 128 rows x 128B (64 bf16)
#define STAGE_BYTES (4 * TILE_BYTES)   // Ah, Al, Bh, Bl
#define NSTAGE 3
#define DYN_SMEM (NSTAGE * STAGE_BYTES)  // 192 KB

__global__ __launch_bounds__(256, 1) void mma_gemm_k(
    const __nv_bfloat16* __restrict__ Ahi, const __nv_bfloat16* __restrict__ Alo, size_t sA,
    const __nv_bfloat16* __restrict__ Bhi, const __nv_bfloat16* __restrict__ Blo, size_t sB,
    int ldk, int NCtot, int nsplit,
    __nv_bfloat16* __restrict__ Chi, __nv_bfloat16* __restrict__ Clo,
    float* __restrict__ Cf, size_t sC, int ldc,
    const float* __restrict__ bias, int mode) {
    extern __shared__ __align__(1024) char smem[];
    uint32_t smb = smem_to_u32(smem);
    int tid = threadIdx.x;
    int wid = tid >> 5, lane = tid & 31;
    int b = blockIdx.z / nsplit, sp = blockIdx.z % nsplit;
    int basec = NCtot / nsplit, remc = NCtot % nsplit;
    int NC = basec + (sp < remc ? 1 : 0);
    int startc = sp * basec + (sp < remc ? sp : remc);
    int koff0 = startc << 6;
    int i0 = blockIdx.x * 128, j0 = blockIdx.y * 128;
    int wm = (wid >> 2) * 64, wn = (wid & 3) * 32;

    const __nv_bfloat16* tiles[4] = {Ahi + sA * b, Alo + sA * b, Bhi + sB * b, Blo + sB * b};
    const int row0[4] = {i0, i0, j0, j0};

    int lr[4], lu[4];
#pragma unroll
    for (int it = 0; it < 4; it++) {
        int q = tid + it * 256;
        lr[it] = q >> 3;
        lu[it] = q & 7;
    }

    auto load_chunk = [&](int chunk) {
        uint32_t sbase = smb + (chunk % NSTAGE) * STAGE_BYTES;
        int koff = koff0 + (chunk << 6);
#pragma unroll
        for (int tile = 0; tile < 4; tile++) {
            const __nv_bfloat16* src = tiles[tile];
#pragma unroll
            for (int it = 0; it < 4; it++) {
                uint32_t boff = (uint32_t)(lr[it] * 128 + lu[it] * 16);
                uint32_t sw = SMEM_SWIZZLE_128B(boff);
                const void* g = src + (size_t)(row0[tile] + lr[it]) * ldk + koff + lu[it] * 8;
                cpasync16(sbase + tile * TILE_BYTES + sw, g);
            }
        }
        cp_commit();
    };

    float acc[4][4][4];
#pragma unroll
    for (int a = 0; a < 4; a++)
#pragma unroll
        for (int bb = 0; bb < 4; bb++)
#pragma unroll
            for (int c = 0; c < 4; c++) acc[a][bb][c] = 0.f;

    int arow = wm + (lane & 15);
    int akh16 = ((lane >> 4) & 1) * 16;
    int brow = wn + ((lane >> 4) & 1) * 8 + (lane & 7);
    int bkh16 = ((lane >> 3) & 1) * 16;

    load_chunk(0);
    if (NC > 1) load_chunk(1);

    for (int kc = 0; kc < NC; kc++) {
        if (kc < NC - 1) cp_wait<1>();
        else cp_wait<0>();
        __syncthreads();

        uint32_t sAh = smb + (kc % NSTAGE) * STAGE_BYTES;
        uint32_t sAl = sAh + TILE_BYTES;
        uint32_t sBh = sAh + 2 * TILE_BYTES;
        uint32_t sBl = sAh + 3 * TILE_BYTES;

#pragma unroll
        for (int kk = 0; kk < 4; kk++) {
            uint32_t ah[4][4], al[4][4], bh[2][4], bl[2][4];
#pragma unroll
            for (int mt = 0; mt < 4; mt++) {
                uint32_t o = (uint32_t)((arow + mt * 16) * 128 + kk * 32 + akh16);
                uint32_t sw = SMEM_SWIZZLE_128B(o);
                ldmx4(ah[mt], sAh + sw);
                ldmx4(al[mt], sAl + sw);
            }
#pragma unroll
            for (int np = 0; np < 2; np++) {
                uint32_t o = (uint32_t)((brow + np * 16) * 128 + kk * 32 + bkh16);
                uint32_t sw = SMEM_SWIZZLE_128B(o);
                ldmx4(bh[np], sBh + sw);
                ldmx4(bl[np], sBl + sw);
            }
#pragma unroll
            for (int mt = 0; mt < 4; mt++)
#pragma unroll
                for (int nt = 0; nt < 4; nt++) {
                    uint32_t* bfh = &bh[nt >> 1][(nt & 1) * 2];
                    uint32_t* bfl = &bl[nt >> 1][(nt & 1) * 2];
                    mma16816(acc[mt][nt], ah[mt], bfh);  // hi*hi
                    mma16816(acc[mt][nt], ah[mt], bfl);  // hi*lo
                    mma16816(acc[mt][nt], al[mt], bfh);  // lo*hi
                }
        }
        if (kc + 2 < NC) load_chunk(kc + 2);
    }

    // ---- epilogue ----
#pragma unroll
    for (int mt = 0; mt < 4; mt++) {
#pragma unroll
        for (int half = 0; half < 2; half++) {
            int lrow = wm + mt * 16 + (lane >> 2) + half * 8;
            int grow = i0 + lrow;
#pragma unroll
            for (int nt = 0; nt < 4; nt++) {
                int lcol = wn + nt * 8 + (lane & 3) * 2;
                int gcol = j0 + lcol;
                float v0 = acc[mt][nt][half * 2 + 0];
                float v1 = acc[mt][nt][half * 2 + 1];
                if (mode == 3) {
                    *(float2*)&Cf[sC * blockIdx.z + (size_t)grow * ldc + gcol] = make_float2(v0, v1);
                } else if (mode == 5) {
                    __half2 hh;
                    hh.x = __float2half(v0);
                    hh.y = __float2half(v1);
                    *(__half2*)&((__half*)Chi)[sC * b + (size_t)grow * ldc + gcol] = hh;
                } else {
                    __nv_bfloat162 h2, l2;
                    split_f32(v0, h2.x, l2.x);
                    split_f32(v1, h2.y, l2.y);
                    *(__nv_bfloat162*)&Chi[sC * b + (size_t)grow * ldc + gcol] = h2;
                    *(__nv_bfloat162*)&Clo[sC * b + (size_t)grow * ldc + gcol] = l2;
                }
            }
        }
    }
}

// ---------------------------------------------------------------------------
// single-product fp16 GEMM: C[m][n] = sum_k A16[m][k] * B16[n][k]
//   2 tiles/chunk (A, B). NST stages; MINB CTAs/SM.
//   mode 2: fp32 + bias out at batch b (logits)
//   mode 4: symmetric pairs (c_pi/c_pj), K-split, fp32 local 128x128 tile (G)
// ---------------------------------------------------------------------------
#define STILE 16384
#define SSTAGE (2 * STILE)

template <int NST, int MINB>
__global__ __launch_bounds__(256, MINB) void f16s_gemm_t(
    const __half* __restrict__ A16, size_t sA,
    const __half* __restrict__ B16, size_t sB,
    int ldk, int NCtot, int nsplit,
    float* __restrict__ Cf, size_t sC, int ldc,
    const float* __restrict__ bias, int mode) {
    extern __shared__ __align__(1024) char smem[];
    uint32_t smb = smem_to_u32(smem);
    int tid = threadIdx.x;
    int wid = tid >> 5, lane = tid & 31;
    int b = blockIdx.z / nsplit, sp = blockIdx.z % nsplit;
    int basec = NCtot / nsplit, remc = NCtot % nsplit;
    int NC = basec + (sp < remc ? 1 : 0);
    int startc = sp * basec + (sp < remc ? sp : remc);
    int koff0 = startc << 6;
    int i0, j0;
    if (mode == 4) {
        i0 = c_pi[blockIdx.x] * 128;
        j0 = c_pj[blockIdx.x] * 128;
    } else {
        i0 = blockIdx.x * 128;
        j0 = blockIdx.y * 128;
    }
    int wm = (wid >> 2) * 64, wn = (wid & 3) * 32;

    const __half* tiles[2] = {A16 + sA * b, B16 + sB * b};
    const int row0[2] = {i0, j0};

    int lr[4], lu[4];
#pragma unroll
    for (int it = 0; it < 4; it++) {
        int q = tid + it * 256;
        lr[it] = q >> 3;
        lu[it] = q & 7;
    }

    auto load_chunk = [&](int chunk) {
        uint32_t sbase = smb + (chunk % NST) * SSTAGE;
        int koff = koff0 + (chunk << 6);
#pragma unroll
        for (int tile = 0; tile < 2; tile++) {
            const __half* src = tiles[tile];
#pragma unroll
            for (int it = 0; it < 4; it++) {
                uint32_t boff = (uint32_t)(lr[it] * 128 + lu[it] * 16);
                uint32_t sw = SMEM_SWIZZLE_128B(boff);
                cpasync16(sbase + tile * STILE + sw,
                          src + (size_t)(row0[tile] + lr[it]) * ldk + koff + lu[it] * 8);
            }
        }
        cp_commit();
    };

    float acc[4][4][4];
#pragma unroll
    for (int a = 0; a < 4; a++)
#pragma unroll
        for (int bb = 0; bb < 4; bb++)
#pragma unroll
            for (int c = 0; c < 4; c++) acc[a][bb][c] = 0.f;

    int arow = wm + (lane & 15);
    int akh16 = ((lane >> 4) & 1) * 16;
    int brow = wn + ((lane >> 4) & 1) * 8 + (lane & 7);
    int bkh16 = ((lane >> 3) & 1) * 16;

    load_chunk(0);
    if (NST == 3 && NC > 1) load_chunk(1);

    for (int kc = 0; kc < NC; kc++) {
        if (NST == 3) {
            if (kc < NC - 1) cp_wait<1>();
            else cp_wait<0>();
        } else {
            cp_wait<0>();
        }
        __syncthreads();
        if (NST == 2 && kc + 1 < NC) load_chunk(kc + 1);

        uint32_t sA_ = smb + (kc % NST) * SSTAGE;
        uint32_t sB_ = sA_ + STILE;

#pragma unroll
        for (int kk = 0; kk < 4; kk++) {
            uint32_t bh[2][4];
#pragma unroll
            for (int np = 0; np < 2; np++) {
                uint32_t o = (uint32_t)((brow + np * 16) * 128 + kk * 32 + bkh16);
                uint32_t sw = SMEM_SWIZZLE_128B(o);
                ldmx4(bh[np], sB_ + sw);
            }
#pragma unroll
            for (int mt = 0; mt < 4; mt++) {
                uint32_t ah[4];
                uint32_t o = (uint32_t)((arow + mt * 16) * 128 + kk * 32 + akh16);
                uint32_t sw = SMEM_SWIZZLE_128B(o);
                ldmx4(ah, sA_ + sw);
#pragma unroll
                for (int nt = 0; nt < 4; nt++)
                    mma16816h(acc[mt][nt], ah, &bh[nt >> 1][(nt & 1) * 2]);
            }
        }
        if (NST == 3 && kc + 2 < NC) load_chunk(kc + 2);
    }

    // ---- epilogue ----
    float* loc = (mode == 4)
        ? Cf + ((size_t)blockIdx.z * gridDim.x + blockIdx.x) * (128 * 128)
        : nullptr;
#pragma unroll
    for (int mt = 0; mt < 4; mt++) {
#pragma unroll
        for (int half = 0; half < 2; half++) {
            int lrow = wm + mt * 16 + (lane >> 2) + half * 8;
            int grow = i0 + lrow;
#pragma unroll
            for (int nt = 0; nt < 4; nt++) {
                int lcol = wn + nt * 8 + (lane & 3) * 2;
                int gcol = j0 + lcol;
                float v0 = acc[mt][nt][half * 2 + 0];
                float v1 = acc[mt][nt][half * 2 + 1];
                if (mode == 4) {
                    *(float2*)&loc[lrow * 128 + lcol] = make_float2(v0, v1);
                } else {
                    float2 f2 = make_float2(v0 + bias[gcol], v1 + bias[gcol + 1]);
                    *(float2*)&Cf[sC * b + (size_t)grow * ldc + gcol] = f2;
                }
            }
        }
    }
}

// ---------------------------------------------------------------------------
// reduce symmetric-G partials (10 tile-pairs x G_NSPLIT) -> full G hi/lo bf16
// ---------------------------------------------------------------------------
__global__ void reduce_G_k() {
    size_t idx = ((size_t)blockIdx.x * 256 + threadIdx.x) * 2;  // KB*KD*KD elems
    const size_t per = (size_t)KD * KD;
    int b = (int)(idx / per);
    size_t rem = idx % per;
    int i = (int)(rem / KD), j = (int)(rem % KD);
    int ti = i >> 7, tj = j >> 7;
    float s0 = 0.f, s1 = 0.f;
    if (ti <= tj) {
        int p = c_PT[ti * 4 + tj];
        size_t off = (size_t)((i & 127) * 128 + (j & 127));
        for (int sp = 0; sp < G_NSPLIT; sp++) {
            const float* base = g_Gp + ((size_t)(b * G_NSPLIT + sp) * 10 + p) * (128 * 128);
            s0 += base[off];
            s1 += base[off + 1];
        }
    } else {
        int p = c_PT[tj * 4 + ti];
        size_t off = (size_t)((j & 127) * 128 + (i & 127));
        for (int sp = 0; sp < G_NSPLIT; sp++) {
            const float* base = g_Gp + ((size_t)(b * G_NSPLIT + sp) * 10 + p) * (128 * 128);
            s0 += base[off];
            s1 += base[off + 128];   // G[i][j+1] = mirrored tile, next row
        }
    }
    __nv_bfloat162 h2, l2;
    split_f32(s0, h2.x, l2.x);
    split_f32(s1, h2.y, l2.y);
    *(__nv_bfloat162*)&g_G_hi[idx] = h2;
    *(__nv_bfloat162*)&g_G_lo[idx] = l2;
}

// ---------------------------------------------------------------------------
// reduce M K-split partials + rank-1 Wb[i]*s[b][j] -> hi/lo bf16
// ---------------------------------------------------------------------------
__global__ void reduce_M_k(const float* __restrict__ Wb) {
    size_t idx = ((size_t)blockIdx.x * 256 + threadIdx.x) * 2;
    const size_t per = (size_t)KD * KD;
    int b = (int)(idx / per);
    size_t rem = idx % per;
    int i = (int)(rem / KD), j = (int)(rem % KD);
    float s0 = 0.f, s1 = 0.f;
    for (int sp = 0; sp < M_NSPLIT; sp++) {
        const float* p = g_Mp + ((size_t)(b * M_NSPLIT + sp)) * per + rem;
        s0 += p[0];
        s1 += p[1];
    }
    float u = Wb[i];
    s0 += u * g_s[b * KD + j];
    s1 += u * g_s[b * KD + j + 1];
    __nv_bfloat162 h2, l2;
    split_f32(s0, h2.x, l2.x);
    split_f32(s1, h2.y, l2.y);
    *(__nv_bfloat162*)&g_M_hi[idx] = h2;
    *(__nv_bfloat162*)&g_M_lo[idx] = l2;
}

// ---------------------------------------------------------------------------
// log_softmax over V + permute (B,L,V)->(L,B,V)
// ---------------------------------------------------------------------------
__global__ void logsoftmax_k(float* __restrict__ out) {
    int l = blockIdx.x, b = blockIdx.y;
    const float* row = g_logits + (size_t)(b * KL + l) * KVP;
    float* orow = out + (size_t)(l * KB + b) * KV;
    __shared__ float sred[8];
    int t = threadIdx.x;
    int wid = t >> 5, lane = t & 31;
    bool act = t < (KV / 4);
    float4 v = act ? *(const float4*)&row[t * 4]
                   : make_float4(-3.4e38f, -3.4e38f, -3.4e38f, -3.4e38f);
    float m = fmaxf(fmaxf(v.x, v.y), fmaxf(v.z, v.w));
#pragma unroll
    for (int s = 16; s >= 1; s >>= 1) m = fmaxf(m, __shfl_xor_sync(0xffffffffu, m, s));
    if (lane == 0) sred[wid] = m;
    __syncthreads();
    float m8 = (lane < 8) ? sred[lane] : -3.4e38f;
#pragma unroll
    for (int s = 4; s >= 1; s >>= 1) m8 = fmaxf(m8, __shfl_xor_sync(0xffffffffu, m8, s));
    float vmax = __shfl_sync(0xffffffffu, m8, 0);

    float e = act ? (__expf(v.x - vmax) + __expf(v.y - vmax) +
                     __expf(v.z - vmax) + __expf(v.w - vmax))
                  : 0.f;
#pragma unroll
    for (int s = 16; s >= 1; s >>= 1) e += __shfl_xor_sync(0xffffffffu, e, s);
    __syncthreads();
    if (lane == 0) sred[wid] = e;
    __syncthreads();
    float e8 = (lane < 8) ? sred[lane] : 0.f;
#pragma unroll
    for (int s = 4; s >= 1; s >>= 1) e8 += __shfl_xor_sync(0xffffffffu, e8, s);
    float denom = vmax + logf(__shfl_sync(0xffffffffu, e8, 0));

    if (act) {
        float4 o;
        o.x = v.x - denom; o.y = v.y - denom;
        o.z = v.z - denom; o.w = v.w - denom;
        *(float4*)&orow[t * 4] = o;
    }
}

// ---------------------------------------------------------------------------
extern "C" void kernel_launch(void* const* d_in, const int* in_sizes, int n_in,
                              void* d_out, int out_size) {
    (void)in_sizes; (void)n_in; (void)out_size;
    const float* x  = (const float*)d_in[0];
    const float* Ww = (const float*)d_in[1];
    const float* Wb = (const float*)d_in[2];
    const float* Lw = (const float*)d_in[3];
    const float* Lb = (const float*)d_in[4];
    float* out = (float*)d_out;

    static bool attr_set = false;
    if (!attr_set) {
        cudaFuncSetAttribute(mma_gemm_k, cudaFuncAttributeMaxDynamicSharedMemorySize, DYN_SMEM);
        cudaFuncSetAttribute(f16s_gemm_t<3, 1>, cudaFuncAttributeMaxDynamicSharedMemorySize,
                             3 * SSTAGE);
        cudaFuncSetAttribute(f16s_gemm_t<2, 2>, cudaFuncAttributeMaxDynamicSharedMemorySize,
                             2 * SSTAGE);
        attr_set = true;
    }

    __half *Xb16, *Xt16, *P16;
    __nv_bfloat16 *Wwh, *Wwl, *Lwh, *Lwl;
    __nv_bfloat16 *Gh, *Gl, *Mh, *Ml;
    float *Lbp, *logits, *Gp, *Mp;
    cudaGetSymbolAddress((void**)&Xb16, g_Xb16);
    cudaGetSymbolAddress((void**)&Xt16, g_Xt16);
    cudaGetSymbolAddress((void**)&Wwh, g_Ww_hi);
    cudaGetSymbolAddress((void**)&Wwl, g_Ww_lo);
    cudaGetSymbolAddress((void**)&Lwh, g_Lw_hi);
    cudaGetSymbolAddress((void**)&Lwl, g_Lw_lo);
    cudaGetSymbolAddress((void**)&Gh, g_G_hi);
    cudaGetSymbolAddress((void**)&Gl, g_G_lo);
    cudaGetSymbolAddress((void**)&Mh, g_M_hi);
    cudaGetSymbolAddress((void**)&Ml, g_M_lo);
    cudaGetSymbolAddress((void**)&P16, g_P16);
    cudaGetSymbolAddress((void**)&Lbp, g_Lbp);
    cudaGetSymbolAddress((void**)&logits, g_logits);
    cudaGetSymbolAddress((void**)&Gp, g_Gp);
    cudaGetSymbolAddress((void**)&Mp, g_Mp);

    prep_x_k<<<dim3(KL / 64, KD / 64, KB), 256>>>(x);
    colsum_final_k<<<(KB * KD) / 256, 256>>>();
    prep_w_k<<<(KVP * KD) / 256, 256>>>(Ww, Lw, Lb);

    // G[b] = Xt16 * Xt16^T  (single fp16 product, symmetric 10 pairs,
    // K-split x3 -> 120 CTAs single wave, 3-stage depth-2 prefetch)
    f16s_gemm_t<3, 1><<<dim3(10, 1, KB * G_NSPLIT), 256, 3 * SSTAGE>>>(
        Xt16, (size_t)KD * KL, Xt16, (size_t)KD * KL,
        KL, KL / 64, G_NSPLIT, Gp, 0, 128, nullptr, 4);
    reduce_G_k<<<(KB * KD * KD / 2) / 256, 256>>>();

    // M[b] = Ww*G[b]^T (bf16 3-product exact, K-split x2; rank-1 in reduce)
    mma_gemm_k<<<dim3(4, 4, KB * M_NSPLIT), 256, DYN_SMEM>>>(
        Wwh, Wwl, 0, Gh, Gl, (size_t)KD * KD,
        KD, KD / 64, M_NSPLIT, nullptr, nullptr, Mp, (size_t)KD * KD, KD, nullptr, 3);
    reduce_M_k<<<(KB * KD * KD / 2) / 256, 256>>>(Wb);

    // P[b][v][k] = sum_n Lw[v][n] * M[b][k][n] -> single fp16 (mode 5)
    mma_gemm_k<<<dim3(KVP / 128, KD / 128, KB), 256, DYN_SMEM>>>(
        Lwh, Lwl, 0, Mh, Ml, (size_t)KD * KD,
        KD, KD / 64, 1, (__nv_bfloat16*)P16, nullptr, nullptr,
        (size_t)KVP * KD, KD, nullptr, 5);

    // logits[b] = Xb16 * P16^T + Lb  (single fp16 product, 2-stage, 2 CTAs/SM)
    f16s_gemm_t<2, 2><<<dim3(KL / 128, KVP / 128, KB), 256, 2 * SSTAGE>>>(
        Xb16, (size_t)KL * KD, P16, (size_t)KVP * KD,
        KD, KD / 64, 1, logits, (size_t)KL * KVP, KVP, Lbp, 2);

    logsoftmax_k<<<dim3(KL, KB), 256>>>(out);
}

// round 17
// speedup vs baseline: 1.8396x; 1.0813x over previous
#include <cuda_runtime.h>
#include <cuda_fp16.h>
#include <cstdint>

#define KL 4096
#define KB 4
#define KD 512
#define KV 1000
#define KVP 1024   // padded vocab

// ---------------------------------------------------------------------------
// PTX helpers (sm_80-compatible only: ldmatrix / mma.sync / cp.async)
// ---------------------------------------------------------------------------
__device__ __forceinline__ uint32_t smem_to_u32(const void* p) {
    uint32_t a;
    asm("{ .reg .u64 t; cvta.to.shared.u64 t, %1; cvt.u32.u64 %0, t; }" : "=r"(a) : "l"(p));
    return a;
}
__device__ __forceinline__ void cpasync16(uint32_t s, const void* g) {
    asm volatile("cp.async.cg.shared.global [%0], [%1], 16;" :: "r"(s), "l"(g));
}
__device__ __forceinline__ void cp_commit() {
    asm volatile("cp.async.commit_group;" ::: "memory");
}
template <int N>
__device__ __forceinline__ void cp_wait() {
    asm volatile("cp.async.wait_group %0;" :: "n"(N) : "memory");
}
__device__ __forceinline__ void ldmx4(uint32_t* r, uint32_t a) {
    asm volatile("ldmatrix.sync.aligned.m8n8.x4.shared.b16 {%0,%1,%2,%3}, [%4];"
                 : "=r"(r[0]), "=r"(r[1]), "=r"(r[2]), "=r"(r[3]) : "r"(a));
}
__device__ __forceinline__ void mma16816h(float* d, const uint32_t* a, const uint32_t* b) {
    asm volatile(
        "mma.sync.aligned.m16n8k16.row.col.f32.f16.f16.f32 "
        "{%0,%1,%2,%3}, {%4,%5,%6,%7}, {%8,%9}, {%0,%1,%2,%3};"
        : "+f"(d[0]), "+f"(d[1]), "+f"(d[2]), "+f"(d[3])
        : "r"(a[0]), "r"(a[1]), "r"(a[2]), "r"(a[3]), "r"(b[0]), "r"(b[1]));
}
#define SMEM_SWIZZLE_128B(o) ((o) ^ (((o) >> 3) & 0x70))

// symmetric-G tile pair tables (upper triangle of 4x4)
__constant__ int c_pi[10] = {0, 0, 0, 0, 1, 1, 1, 2, 2, 3};
__constant__ int c_pj[10] = {0, 1, 2, 3, 1, 2, 3, 2, 3, 3};
__constant__ int c_PT[16] = {0, 1, 2, 3,  0, 4, 5, 6,  0, 0, 7, 8,  0, 0, 0, 9};

// ---------------------------------------------------------------------------
// scratch (static device globals; no allocations)
// ---------------------------------------------------------------------------
#define G_NSPLIT 3   // 10 pairs * KB * 3 = 120 CTAs -> single wave on 148 SMs
#define M_NSPLIT 2
__device__ __align__(128) float g_part2[KB * KD * 64];   // colsum partials
__device__ __align__(128) float g_s[KB * KD];
__device__ __align__(128) __half g_Xb16[(size_t)KB * KL * KD];
__device__ __align__(128) __half g_Xt16[(size_t)KB * KD * KL];
__device__ __align__(128) __half g_Ww16[KD * KD];
__device__ __align__(128) __half g_Lw16[KVP * KD];
__device__ __align__(128) float g_Lbp[KVP];
__device__ __align__(128) float g_Gp[(size_t)KB * G_NSPLIT * 10 * 128 * 128]; // 7.9 MB
__device__ __align__(128) float g_Mp[(size_t)M_NSPLIT * KB * KD * KD];        // 8 MB
__device__ __align__(128) __half g_G16[KB * KD * KD];
__device__ __align__(128) __half g_M16[KB * KD * KD];
__device__ __align__(128) __half g_P16[(size_t)KB * KVP * KD];
__device__ __align__(128) float g_logits[(size_t)KB * KL * KVP];

// ---------------------------------------------------------------------------
// prep_x: x -> Xb16 (logits A), Xt16 (G operands), colsum partials
// ---------------------------------------------------------------------------
__global__ __launch_bounds__(256) void prep_x_k(const float* __restrict__ x) {
    __shared__ __half sh[64][65];
    __shared__ float ssum[4][64];
    int b = blockIdx.z;
    int lblk = blockIdx.x;
    int l0 = lblk * 64, d0 = blockIdx.y * 64;
    int t = threadIdx.x;
    int c = t & 63, r4 = t >> 6;
    float ps = 0.f;
#pragma unroll 4
    for (int rr = 0; rr < 16; rr++) {
        int r = r4 * 16 + rr;
        float v = x[(size_t)(l0 + r) * (KB * KD) + b * KD + d0 + c];
        ps += v;
        __half fh = __float2half(v);
        g_Xb16[((size_t)b * KL + (l0 + r)) * KD + d0 + c] = fh;
        sh[r][c] = fh;
    }
    ssum[r4][c] = ps;
    __syncthreads();
#pragma unroll 4
    for (int rr = 0; rr < 16; rr++) {
        int r = r4 * 16 + rr;   // d index
        g_Xt16[((size_t)b * KD + (d0 + r)) * KL + l0 + c] = sh[c][r];
    }
    if (t < 64) {
        float s = ssum[0][t] + ssum[1][t] + ssum[2][t] + ssum[3][t];
        g_part2[((size_t)b * KD + d0 + t) * 64 + lblk] = s;
    }
}

__global__ void colsum_final_k() {
    int idx = blockIdx.x * 256 + threadIdx.x;  // KB*KD
    float s = 0.f;
    const float* p = &g_part2[(size_t)idx * 64];
#pragma unroll
    for (int k = 0; k < 64; k++) s += p[k];
    g_s[idx] = s;
}

// ---------------------------------------------------------------------------
// prep_w (flat): Ww -> fp16; Lw -> fp16 padded to 1024 rows; pad Lb
// ---------------------------------------------------------------------------
__global__ void prep_w_k(const float* __restrict__ Ww, const float* __restrict__ Lw,
                         const float* __restrict__ Lb) {
    int idx = blockIdx.x * 256 + threadIdx.x;   // over KVP*KD
    int row = idx / KD;
    g_Lw16[idx] = __float2half((row < KV) ? Lw[idx] : 0.f);
    if (idx < KD * KD) g_Ww16[idx] = __float2half(Ww[idx]);
    if (idx < KVP) g_Lbp[idx] = (idx < KV) ? Lb[idx] : 0.f;
}

// ---------------------------------------------------------------------------
// single-product fp16 GEMM: C[m][n] = sum_k A16[m][k] * B16[n][k]
//   2 tiles/chunk (A, B). NST stages; MINB CTAs/SM.
//   mode 2: fp32 + bias out at batch b (logits)
//   mode 3: fp32 K-split partial at slot blockIdx.z (M)
//   mode 4: symmetric pairs (c_pi/c_pj), K-split, fp32 local 128x128 tile (G)
//   mode 5: fp16 single out at batch b (P; Cf reinterpreted as __half*)
// ---------------------------------------------------------------------------
#define STILE 16384
#define SSTAGE (2 * STILE)

template <int NST, int MINB>
__global__ __launch_bounds__(256, MINB) void f16s_gemm_t(
    const __half* __restrict__ A16, size_t sA,
    const __half* __restrict__ B16, size_t sB,
    int ldk, int NCtot, int nsplit,
    float* __restrict__ Cf, size_t sC, int ldc,
    const float* __restrict__ bias, int mode) {
    extern __shared__ __align__(1024) char smem[];
    uint32_t smb = smem_to_u32(smem);
    int tid = threadIdx.x;
    int wid = tid >> 5, lane = tid & 31;
    int b = blockIdx.z / nsplit, sp = blockIdx.z % nsplit;
    int basec = NCtot / nsplit, remc = NCtot % nsplit;
    int NC = basec + (sp < remc ? 1 : 0);
    int startc = sp * basec + (sp < remc ? sp : remc);
    int koff0 = startc << 6;
    int i0, j0;
    if (mode == 4) {
        i0 = c_pi[blockIdx.x] * 128;
        j0 = c_pj[blockIdx.x] * 128;
    } else {
        i0 = blockIdx.x * 128;
        j0 = blockIdx.y * 128;
    }
    int wm = (wid >> 2) * 64, wn = (wid & 3) * 32;

    const __half* tiles[2] = {A16 + sA * b, B16 + sB * b};
    const int row0[2] = {i0, j0};

    int lr[4], lu[4];
#pragma unroll
    for (int it = 0; it < 4; it++) {
        int q = tid + it * 256;
        lr[it] = q >> 3;
        lu[it] = q & 7;
    }

    auto load_chunk = [&](int chunk) {
        uint32_t sbase = smb + (chunk % NST) * SSTAGE;
        int koff = koff0 + (chunk << 6);
#pragma unroll
        for (int tile = 0; tile < 2; tile++) {
            const __half* src = tiles[tile];
#pragma unroll
            for (int it = 0; it < 4; it++) {
                uint32_t boff = (uint32_t)(lr[it] * 128 + lu[it] * 16);
                uint32_t sw = SMEM_SWIZZLE_128B(boff);
                cpasync16(sbase + tile * STILE + sw,
                          src + (size_t)(row0[tile] + lr[it]) * ldk + koff + lu[it] * 8);
            }
        }
        cp_commit();
    };

    float acc[4][4][4];
#pragma unroll
    for (int a = 0; a < 4; a++)
#pragma unroll
        for (int bb = 0; bb < 4; bb++)
#pragma unroll
            for (int c = 0; c < 4; c++) acc[a][bb][c] = 0.f;

    int arow = wm + (lane & 15);
    int akh16 = ((lane >> 4) & 1) * 16;
    int brow = wn + ((lane >> 4) & 1) * 8 + (lane & 7);
    int bkh16 = ((lane >> 3) & 1) * 16;

    load_chunk(0);
    if (NST == 3 && NC > 1) load_chunk(1);

    for (int kc = 0; kc < NC; kc++) {
        if (NST == 3) {
            if (kc < NC - 1) cp_wait<1>();
            else cp_wait<0>();
        } else {
            cp_wait<0>();
        }
        __syncthreads();
        if (NST == 2 && kc + 1 < NC) load_chunk(kc + 1);

        uint32_t sA_ = smb + (kc % NST) * SSTAGE;
        uint32_t sB_ = sA_ + STILE;

#pragma unroll
        for (int kk = 0; kk < 4; kk++) {
            uint32_t bh[2][4];
#pragma unroll
            for (int np = 0; np < 2; np++) {
                uint32_t o = (uint32_t)((brow + np * 16) * 128 + kk * 32 + bkh16);
                uint32_t sw = SMEM_SWIZZLE_128B(o);
                ldmx4(bh[np], sB_ + sw);
            }
#pragma unroll
            for (int mt = 0; mt < 4; mt++) {
                uint32_t ah[4];
                uint32_t o = (uint32_t)((arow + mt * 16) * 128 + kk * 32 + akh16);
                uint32_t sw = SMEM_SWIZZLE_128B(o);
                ldmx4(ah, sA_ + sw);
#pragma unroll
                for (int nt = 0; nt < 4; nt++)
                    mma16816h(acc[mt][nt], ah, &bh[nt >> 1][(nt & 1) * 2]);
            }
        }
        if (NST == 3 && kc + 2 < NC) load_chunk(kc + 2);
    }

    // ---- epilogue ----
    float* loc = (mode == 4)
        ? Cf + ((size_t)blockIdx.z * gridDim.x + blockIdx.x) * (128 * 128)
        : nullptr;
#pragma unroll
    for (int mt = 0; mt < 4; mt++) {
#pragma unroll
        for (int half = 0; half < 2; half++) {
            int lrow = wm + mt * 16 + (lane >> 2) + half * 8;
            int grow = i0 + lrow;
#pragma unroll
            for (int nt = 0; nt < 4; nt++) {
                int lcol = wn + nt * 8 + (lane & 3) * 2;
                int gcol = j0 + lcol;
                float v0 = acc[mt][nt][half * 2 + 0];
                float v1 = acc[mt][nt][half * 2 + 1];
                if (mode == 4) {
                    *(float2*)&loc[lrow * 128 + lcol] = make_float2(v0, v1);
                } else if (mode == 3) {
                    *(float2*)&Cf[sC * blockIdx.z + (size_t)grow * ldc + gcol] =
                        make_float2(v0, v1);
                } else if (mode == 5) {
                    __half2 hh;
                    hh.x = __float2half(v0);
                    hh.y = __float2half(v1);
                    *(__half2*)&((__half*)Cf)[sC * b + (size_t)grow * ldc + gcol] = hh;
                } else {
                    float2 f2 = make_float2(v0 + bias[gcol], v1 + bias[gcol + 1]);
                    *(float2*)&Cf[sC * b + (size_t)grow * ldc + gcol] = f2;
                }
            }
        }
    }
}

// ---------------------------------------------------------------------------
// reduce symmetric-G partials (10 tile-pairs x G_NSPLIT) -> full G fp16
// ---------------------------------------------------------------------------
__global__ void reduce_G_k() {
    size_t idx = ((size_t)blockIdx.x * 256 + threadIdx.x) * 2;  // KB*KD*KD elems
    const size_t per = (size_t)KD * KD;
    int b = (int)(idx / per);
    size_t rem = idx % per;
    int i = (int)(rem / KD), j = (int)(rem % KD);
    int ti = i >> 7, tj = j >> 7;
    float s0 = 0.f, s1 = 0.f;
    if (ti <= tj) {
        int p = c_PT[ti * 4 + tj];
        size_t off = (size_t)((i & 127) * 128 + (j & 127));
        for (int sp = 0; sp < G_NSPLIT; sp++) {
            const float* base = g_Gp + ((size_t)(b * G_NSPLIT + sp) * 10 + p) * (128 * 128);
            s0 += base[off];
            s1 += base[off + 1];
        }
    } else {
        int p = c_PT[tj * 4 + ti];
        size_t off = (size_t)((j & 127) * 128 + (i & 127));
        for (int sp = 0; sp < G_NSPLIT; sp++) {
            const float* base = g_Gp + ((size_t)(b * G_NSPLIT + sp) * 10 + p) * (128 * 128);
            s0 += base[off];
            s1 += base[off + 128];   // G[i][j+1] = mirrored tile, next row
        }
    }
    __half2 hh;
    hh.x = __float2half(s0);
    hh.y = __float2half(s1);
    *(__half2*)&g_G16[idx] = hh;
}

// ---------------------------------------------------------------------------
// reduce M K-split partials + rank-1 Wb[i]*s[b][j] -> fp16
// ---------------------------------------------------------------------------
__global__ void reduce_M_k(const float* __restrict__ Wb) {
    size_t idx = ((size_t)blockIdx.x * 256 + threadIdx.x) * 2;
    const size_t per = (size_t)KD * KD;
    int b = (int)(idx / per);
    size_t rem = idx % per;
    int i = (int)(rem / KD), j = (int)(rem % KD);
    float s0 = 0.f, s1 = 0.f;
    for (int sp = 0; sp < M_NSPLIT; sp++) {
        const float* p = g_Mp + ((size_t)(b * M_NSPLIT + sp)) * per + rem;
        s0 += p[0];
        s1 += p[1];
    }
    float u = Wb[i];
    s0 += u * g_s[b * KD + j];
    s1 += u * g_s[b * KD + j + 1];
    __half2 hh;
    hh.x = __float2half(s0);
    hh.y = __float2half(s1);
    *(__half2*)&g_M16[idx] = hh;
}

// ---------------------------------------------------------------------------
// log_softmax over V + permute (B,L,V)->(L,B,V)
// ---------------------------------------------------------------------------
__global__ void logsoftmax_k(float* __restrict__ out) {
    int l = blockIdx.x, b = blockIdx.y;
    const float* row = g_logits + (size_t)(b * KL + l) * KVP;
    float* orow = out + (size_t)(l * KB + b) * KV;
    __shared__ float sred[8];
    int t = threadIdx.x;
    int wid = t >> 5, lane = t & 31;
    bool act = t < (KV / 4);
    float4 v = act ? *(const float4*)&row[t * 4]
                   : make_float4(-3.4e38f, -3.4e38f, -3.4e38f, -3.4e38f);
    float m = fmaxf(fmaxf(v.x, v.y), fmaxf(v.z, v.w));
#pragma unroll
    for (int s = 16; s >= 1; s >>= 1) m = fmaxf(m, __shfl_xor_sync(0xffffffffu, m, s));
    if (lane == 0) sred[wid] = m;
    __syncthreads();
    float m8 = (lane < 8) ? sred[lane] : -3.4e38f;
#pragma unroll
    for (int s = 4; s >= 1; s >>= 1) m8 = fmaxf(m8, __shfl_xor_sync(0xffffffffu, m8, s));
    float vmax = __shfl_sync(0xffffffffu, m8, 0);

    float e = act ? (__expf(v.x - vmax) + __expf(v.y - vmax) +
                     __expf(v.z - vmax) + __expf(v.w - vmax))
                  : 0.f;
#pragma unroll
    for (int s = 16; s >= 1; s >>= 1) e += __shfl_xor_sync(0xffffffffu, e, s);
    __syncthreads();
    if (lane == 0) sred[wid] = e;
    __syncthreads();
    float e8 = (lane < 8) ? sred[lane] : 0.f;
#pragma unroll
    for (int s = 4; s >= 1; s >>= 1) e8 += __shfl_xor_sync(0xffffffffu, e8, s);
    float denom = vmax + logf(__shfl_sync(0xffffffffu, e8, 0));

    if (act) {
        float4 o;
        o.x = v.x - denom; o.y = v.y - denom;
        o.z = v.z - denom; o.w = v.w - denom;
        *(float4*)&orow[t * 4] = o;
    }
}

// ---------------------------------------------------------------------------
extern "C" void kernel_launch(void* const* d_in, const int* in_sizes, int n_in,
                              void* d_out, int out_size) {
    (void)in_sizes; (void)n_in; (void)out_size;
    const float* x  = (const float*)d_in[0];
    const float* Ww = (const float*)d_in[1];
    const float* Wb = (const float*)d_in[2];
    const float* Lw = (const float*)d_in[3];
    const float* Lb = (const float*)d_in[4];
    float* out = (float*)d_out;

    static bool attr_set = false;
    if (!attr_set) {
        cudaFuncSetAttribute(f16s_gemm_t<3, 1>, cudaFuncAttributeMaxDynamicSharedMemorySize,
                             3 * SSTAGE);
        cudaFuncSetAttribute(f16s_gemm_t<2, 2>, cudaFuncAttributeMaxDynamicSharedMemorySize,
                             2 * SSTAGE);
        attr_set = true;
    }

    __half *Xb16, *Xt16, *Ww16, *Lw16, *G16, *M16, *P16;
    float *Lbp, *logits, *Gp, *Mp;
    cudaGetSymbolAddress((void**)&Xb16, g_Xb16);
    cudaGetSymbolAddress((void**)&Xt16, g_Xt16);
    cudaGetSymbolAddress((void**)&Ww16, g_Ww16);
    cudaGetSymbolAddress((void**)&Lw16, g_Lw16);
    cudaGetSymbolAddress((void**)&G16, g_G16);
    cudaGetSymbolAddress((void**)&M16, g_M16);
    cudaGetSymbolAddress((void**)&P16, g_P16);
    cudaGetSymbolAddress((void**)&Lbp, g_Lbp);
    cudaGetSymbolAddress((void**)&logits, g_logits);
    cudaGetSymbolAddress((void**)&Gp, g_Gp);
    cudaGetSymbolAddress((void**)&Mp, g_Mp);

    prep_x_k<<<dim3(KL / 64, KD / 64, KB), 256>>>(x);
    colsum_final_k<<<(KB * KD) / 256, 256>>>();
    prep_w_k<<<(KVP * KD) / 256, 256>>>(Ww, Lw, Lb);

    // G[b] = Xt16 * Xt16^T  (symmetric 10 pairs, K-split x3 -> 120 CTAs)
    f16s_gemm_t<3, 1><<<dim3(10, 1, KB * G_NSPLIT), 256, 3 * SSTAGE>>>(
        Xt16, (size_t)KD * KL, Xt16, (size_t)KD * KL,
        KL, KL / 64, G_NSPLIT, Gp, 0, 128, nullptr, 4);
    reduce_G_k<<<(KB * KD * KD / 2) / 256, 256>>>();

    // M[b] = Ww16 * G16[b]^T  (K-split x2 -> 128 CTAs; rank-1 in reduce)
    f16s_gemm_t<3, 1><<<dim3(4, 4, KB * M_NSPLIT), 256, 3 * SSTAGE>>>(
        Ww16, 0, G16, (size_t)KD * KD,
        KD, KD / 64, M_NSPLIT, Mp, (size_t)KD * KD, KD, nullptr, 3);
    reduce_M_k<<<(KB * KD * KD / 2) / 256, 256>>>(Wb);

    // P[b][v][k] = sum_n Lw16[v][n] * M16[b][k][n] -> fp16 (128 CTAs)
    f16s_gemm_t<3, 1><<<dim3(KVP / 128, KD / 128, KB), 256, 3 * SSTAGE>>>(
        Lw16, 0, M16, (size_t)KD * KD,
        KD, KD / 64, 1, (float*)P16, (size_t)KVP * KD, KD, nullptr, 5);

    // logits[b] = Xb16 * P16^T + Lb  (2-stage, 2 CTAs/SM)
    f16s_gemm_t<2, 2><<<dim3(KL / 128, KVP / 128, KB), 256, 2 * SSTAGE>>>(
        Xb16, (size_t)KL * KD, P16, (size_t)KVP * KD,
        KD, KD / 64, 1, logits, (size_t)KL * KVP, KVP, Lbp, 2);

    logsoftmax_k<<<dim3(KL, KB), 256>>>(out);
}